// round 7
// baseline (speedup 1.0000x reference)
#include <cuda_runtime.h>
#include <math.h>

#define NB   4
#define CIN  192
#define HH   128
#define WW   128
#define PP   (HH*WW)       // 16384
#define C1c  48
#define C0c  16
#define CMc  16
#define BATCH 64           // NB * CMc
#define JW   65
#define P65  (128*JW)      // 8320

// ---------------- device scratch (no allocation allowed) ----------------
static __device__ float2 gf_chrp1[255];
static __device__ float2 gf_E[509];
static __device__ float  gf_S[509];
static __device__ float2 gf_fac[128];

static __device__ float2  g_M   [128*128];
static __device__ float2  g_Cm  [128*128];
static __device__ float2  g_Minv[128*128];
static __device__ float2  g_Fh  [128*128];
static __device__ float2  g_Fhi [128*128];
static __device__ float2  g_Fw  [JW*128];
static __device__ float2  g_Bw  [JW*128];

static __device__ float   g_W2[256];      // magw @ magf
static __device__ float   g_b2[16];       // magw @ magf_b + mag_b
static __device__ float   g_Wc[192*16];   // conv2[:, :16] @ conv0_w
static __device__ float   g_bc[192];      // conv2[:, :16] @ conv0_b

static __device__ float   g_x1 [NB*C1c*PP];
static __device__ float2  g_T  [BATCH*128*128];
static __device__ float2  g_F  [BATCH*128*128];
static __device__ float   g_mag[BATCH*PP];
static __device__ float   g_pha[BATCH*PP];
static __device__ float   g_magout[BATCH*PP];
static __device__ float2  g_T65[BATCH*P65];
static __device__ float2  g_F65[BATCH*P65];
static __device__ float   g_fm[BATCH*P65];
static __device__ float   g_fp[BATCH*P65];
static __device__ float   g_cat[NB*C1c*PP];   // ch 16..47 used

// ---------------- table construction ----------------
__global__ void k_tables() {
    int t = threadIdx.x;
    const double PI = 3.14159265358979323846;
    double tana2 = tan(PI / 8.0);
    double sina  = sin(PI / 4.0);
    double coef  = tana2 / 512.0;
    double ec    = 1.0 / (512.0 * sina);
    for (int j = t; j < 255; j += 512) {
        double n = (double)(j - 127);
        double s, c; sincospi(-coef * n * n, &s, &c);
        gf_chrp1[j] = make_float2((float)c, (float)s);
    }
    double amp = sqrt(1.0 / (512.0 * sina));
    double ps, pc; sincospi(-0.125, &ps, &pc);
    for (int r = t; r < 128; r += 512) {
        double n = 2.0 * r - 127.0;
        double s, c; sincospi(-coef * n * n, &s, &c);
        gf_fac[r] = make_float2((float)(amp * (pc * c - ps * s)),
                                (float)(amp * (pc * s + ps * c)));
    }
    for (int i = t; i < 509; i += 512) {
        double d = (double)(i - 254);
        double s, c; sincospi(ec * d * d, &s, &c);
        gf_E[i] = make_float2((float)c, (float)s);
        int m = i - 254;
        double sv;
        if (m == 0) sv = 1.0;
        else if ((m & 1) == 0) sv = 0.0;
        else {
            double x = 0.5 * (double)m;
            sv = sinpi(x) / (PI * x);
        }
        gf_S[i] = (float)sv;
    }
}

__global__ void k_dft() {
    int idx = blockIdx.x * 256 + threadIdx.x;
    if (idx < 128 * 128) {
        int u = idx >> 7, v = idx & 127;
        int e1 = ((u + 64) * (v + 64)) & 127;
        double s, c; sincospi(2.0 * e1 / 128.0, &s, &c);
        double inv = 1.0 / sqrt(128.0);
        g_Cm[idx] = make_float2((float)(c * inv), (float)(s * inv));
        int e2 = (u * v) & 127;
        double s2, c2; sincospi(-2.0 * e2 / 128.0, &s2, &c2);
        g_Fh[idx] = make_float2((float)c2, (float)s2);
        double s3, c3; sincospi(2.0 * e2 / 128.0, &s3, &c3);
        g_Fhi[idx] = make_float2((float)(c3 / 128.0), (float)(s3 / 128.0));
    }
    if (idx < JW * 128) {
        int k = idx / 128, w = idx & 127;
        int e = (k * w) & 127;
        double s, c; sincospi(-2.0 * e / 128.0, &s, &c);
        g_Fw[idx] = make_float2((float)c, (float)s);
        float2 bw;
        if (k == 0)       bw = make_float2(1.0f / 128.0f, 0.f);
        else if (k == 64) bw = make_float2(((w & 1) ? -1.0f : 1.0f) / 128.0f, 0.f);
        else {
            double s4, c4; sincospi(2.0 * e / 128.0, &s4, &c4);
            bw = make_float2((float)(c4 * 2.0 / 128.0), (float)(s4 * 2.0 / 128.0));
        }
        g_Bw[idx] = bw;
    }
}

__global__ void k_buildM() {
    int idx = blockIdx.x * 256 + threadIdx.x;
    if (idx >= 128 * 128) return;
    int r = idx >> 7, k = idx & 127;
    float ax = 0.f, ay = 0.f;
    {
        int j = 2 * k;
        float2 c1 = gf_chrp1[j];
        float2 e  = gf_E[2 * r - j + 254];
        ax += c1.x * e.x - c1.y * e.y;
        ay += c1.x * e.y + c1.y * e.x;
    }
    for (int j = 1; j < 255; j += 2) {
        float s = gf_S[j - 2 * k + 254];
        float2 c1 = gf_chrp1[j];
        float2 e  = gf_E[2 * r - j + 254];
        ax += (c1.x * e.x - c1.y * e.y) * s;
        ay += (c1.x * e.y + c1.y * e.x) * s;
    }
    float2 f = gf_fac[r];
    g_M[idx] = make_float2(f.x * ax - f.y * ay, f.x * ay + f.y * ax);
}

// one block per output row; M row cached in smem; Cm reads coalesced
__global__ void __launch_bounds__(128) k_buildMinv() {
    __shared__ float2 sM[128];
    int r = blockIdx.x, v = threadIdx.x;
    sM[v] = g_M[r * 128 + v];
    __syncthreads();
    float ax = 0.f, ay = 0.f;
#pragma unroll 8
    for (int u = 0; u < 128; u++) {
        float2 a = sM[u];
        float2 b = g_Cm[u * 128 + v];
        ax += a.x * b.x - a.y * b.y;
        ay += a.x * b.y + a.y * b.x;
    }
    g_Minv[r * 128 + v] = make_float2(ax, ay);
}

// W2 = magw @ magf ; b2 = magw @ magf_b + mag_b
__global__ void k_w2(const float* __restrict__ magw, const float* __restrict__ magf,
                     const float* __restrict__ magfb, const float* __restrict__ magb) {
    int t = threadIdx.x;
    int o = t >> 4, c = t & 15;
    float a = 0.f;
#pragma unroll
    for (int m = 0; m < 16; m++) a += magw[o * 16 + m] * magf[m * 16 + c];
    g_W2[t] = a;
    if (t < 16) {
        float b = magb[t];
#pragma unroll
        for (int m = 0; m < 16; m++) b += magw[t * 16 + m] * magfb[m];
        g_b2[t] = b;
    }
}

// Wc = conv2[:, :16] @ conv0_w ; bc = conv2[:, :16] @ conv0_b
__global__ void k_wc(const float* __restrict__ conv2w, const float* __restrict__ conv0w,
                     const float* __restrict__ conv0b) {
    int idx = blockIdx.x * 256 + threadIdx.x;
    if (idx < 192 * 16) {
        int o = idx >> 4, c = idx & 15;
        float a = 0.f;
#pragma unroll
        for (int m = 0; m < 16; m++) a += conv2w[o * 48 + m] * conv0w[m * 16 + c];
        g_Wc[idx] = a;
    }
    if (idx < 192) {
        float b = 0.f;
#pragma unroll
        for (int m = 0; m < 16; m++) b += conv2w[idx * 48 + m] * conv0b[m];
        g_bc[idx] = b;
    }
}

// ---------------- generic 1x1 conv (GEMM) — used for conv1 ----------------
__global__ void __launch_bounds__(128)
k_g1x1(const float* __restrict__ X, const float* __restrict__ Wt,
       const float* __restrict__ Bs, float* __restrict__ Y,
       int Cc, int P, int xStrideN, int yStrideN) {
    __shared__ float sW[16 * 192];
    int n = blockIdx.z, ob = blockIdx.y * 16;
    int tx = threadIdx.x;
    for (int e = tx; e < 16 * Cc; e += 128) sW[e] = Wt[ob * Cc + e];
    __syncthreads();
    const float* Xn = X + (size_t)n * xStrideN;
    int pb = blockIdx.x * 512;
    float acc[16][4];
#pragma unroll
    for (int o = 0; o < 16; o++)
#pragma unroll
        for (int s = 0; s < 4; s++) acc[o][s] = 0.f;
    for (int c = 0; c < Cc; c++) {
        float xv[4];
#pragma unroll
        for (int s = 0; s < 4; s++) {
            int p = pb + s * 128 + tx;
            xv[s] = (p < P) ? Xn[(size_t)c * P + p] : 0.f;
        }
#pragma unroll
        for (int o = 0; o < 16; o++) {
            float w = sW[o * Cc + c];
#pragma unroll
            for (int s = 0; s < 4; s++) acc[o][s] += w * xv[s];
        }
    }
#pragma unroll
    for (int o = 0; o < 16; o++) {
        float b = Bs ? Bs[ob + o] : 0.f;
#pragma unroll
        for (int s = 0; s < 4; s++) {
            int p = pb + s * 128 + tx;
            if (p < P) Y[(size_t)n * yStrideN + (size_t)(ob + o) * P + p] = acc[o][s] + b;
        }
    }
}

// ---------------- conv2 with folded conv_0 branch ----------------
// out[n][o][p] = sum_{c<16} Wc[o][c]*x1[n][c][p] + sum_{16<=c<48} conv2w[o][c]*cat[n][c][p] + bc[o]
__global__ void __launch_bounds__(128)
k_conv2(const float* __restrict__ X1, const float* __restrict__ Cat,
        const float* __restrict__ conv2w, float* __restrict__ Y) {
    __shared__ float sW[16 * 48];
    __shared__ float sB[16];
    int n = blockIdx.z, ob = blockIdx.y * 16;
    int tx = threadIdx.x;
    for (int e = tx; e < 16 * 48; e += 128) {
        int o = e / 48, c = e % 48;
        sW[e] = (c < 16) ? g_Wc[(ob + o) * 16 + c] : conv2w[(ob + o) * 48 + c];
    }
    if (tx < 16) sB[tx] = g_bc[ob + tx];
    __syncthreads();
    const float* Xn = X1 + (size_t)n * 48 * PP;
    const float* Cn = Cat + (size_t)n * 48 * PP;
    int pb = blockIdx.x * 512;
    float acc[16][4];
#pragma unroll
    for (int o = 0; o < 16; o++)
#pragma unroll
        for (int s = 0; s < 4; s++) acc[o][s] = 0.f;
#pragma unroll 4
    for (int c = 0; c < 48; c++) {
        const float* src = (c < 16) ? Xn : Cn;
        float xv[4];
#pragma unroll
        for (int s = 0; s < 4; s++)
            xv[s] = src[(size_t)c * PP + pb + s * 128 + tx];
#pragma unroll
        for (int o = 0; o < 16; o++) {
            float w = sW[o * 48 + c];
#pragma unroll
            for (int s = 0; s < 4; s++) acc[o][s] += w * xv[s];
        }
    }
#pragma unroll
    for (int o = 0; o < 16; o++)
#pragma unroll
        for (int s = 0; s < 4; s++)
            Y[(size_t)n * 192 * PP + (size_t)(ob + o) * PP + pb + s * 128 + tx] = acc[o][s] + sB[o];
}

// ---------------- 64x64-tile complex GEMMs ----------------
__global__ void __launch_bounds__(256)
k_rxMT64(const float* __restrict__ Xb, int cPerN, int cOff,
         const float2* __restrict__ M, float2* __restrict__ Y, int J) {
    __shared__ float  sA[64][17];
    __shared__ float2 sB[16][65];
    int b = blockIdx.z;
    const float* X = Xb + (size_t)((b >> 4) * cPerN + cOff + (b & 15)) * PP;
    int j0 = blockIdx.x * 64, i0 = blockIdx.y * 64;
    int tid = threadIdx.x;
    int tx = tid & 15, ty = tid >> 4;
    float2 acc[4][4];
#pragma unroll
    for (int a = 0; a < 4; a++)
#pragma unroll
        for (int c = 0; c < 4; c++) acc[a][c] = make_float2(0.f, 0.f);
    for (int kt = 0; kt < 128; kt += 16) {
#pragma unroll
        for (int s = 0; s < 4; s++) {
            int e = tid + s * 256; int r = e >> 4, c = e & 15;
            sA[r][c] = X[(i0 + r) * 128 + kt + c];
            float2 v = (j0 + r < J) ? M[(j0 + r) * 128 + kt + c] : make_float2(0.f, 0.f);
            sB[c][r] = v;
        }
        __syncthreads();
#pragma unroll
        for (int kk = 0; kk < 16; kk++) {
            float av[4]; float2 bv[4];
#pragma unroll
            for (int ii = 0; ii < 4; ii++) av[ii] = sA[ty * 4 + ii][kk];
#pragma unroll
            for (int jj = 0; jj < 4; jj++) bv[jj] = sB[kk][tx * 4 + jj];
#pragma unroll
            for (int ii = 0; ii < 4; ii++)
#pragma unroll
                for (int jj = 0; jj < 4; jj++) {
                    acc[ii][jj].x += av[ii] * bv[jj].x;
                    acc[ii][jj].y += av[ii] * bv[jj].y;
                }
        }
        __syncthreads();
    }
#pragma unroll
    for (int ii = 0; ii < 4; ii++)
#pragma unroll
        for (int jj = 0; jj < 4; jj++) {
            int j = j0 + tx * 4 + jj;
            if (j < J)
                Y[((size_t)b * 128 + i0 + ty * 4 + ii) * J + j] = acc[ii][jj];
        }
}

__global__ void __launch_bounds__(256)
k_cMT64(const float2* __restrict__ Xc, const float2* __restrict__ M,
        float2* __restrict__ Y, int J) {
    __shared__ float2 sA[64][17];
    __shared__ float2 sB[16][65];
    int b = blockIdx.z;
    const float2* X = Xc + (size_t)b * 128 * 128;
    int j0 = blockIdx.x * 64, i0 = blockIdx.y * 64;
    int tid = threadIdx.x;
    int tx = tid & 15, ty = tid >> 4;
    float2 acc[4][4];
#pragma unroll
    for (int a = 0; a < 4; a++)
#pragma unroll
        for (int c = 0; c < 4; c++) acc[a][c] = make_float2(0.f, 0.f);
    for (int kt = 0; kt < 128; kt += 16) {
#pragma unroll
        for (int s = 0; s < 4; s++) {
            int e = tid + s * 256; int r = e >> 4, c = e & 15;
            sA[r][c] = X[(i0 + r) * 128 + kt + c];
            float2 v = (j0 + r < J) ? M[(j0 + r) * 128 + kt + c] : make_float2(0.f, 0.f);
            sB[c][r] = v;
        }
        __syncthreads();
#pragma unroll
        for (int kk = 0; kk < 16; kk++) {
            float2 av[4]; float2 bv[4];
#pragma unroll
            for (int ii = 0; ii < 4; ii++) av[ii] = sA[ty * 4 + ii][kk];
#pragma unroll
            for (int jj = 0; jj < 4; jj++) bv[jj] = sB[kk][tx * 4 + jj];
#pragma unroll
            for (int ii = 0; ii < 4; ii++)
#pragma unroll
                for (int jj = 0; jj < 4; jj++) {
                    acc[ii][jj].x += av[ii].x * bv[jj].x - av[ii].y * bv[jj].y;
                    acc[ii][jj].y += av[ii].x * bv[jj].y + av[ii].y * bv[jj].x;
                }
        }
        __syncthreads();
    }
#pragma unroll
    for (int ii = 0; ii < 4; ii++)
#pragma unroll
        for (int jj = 0; jj < 4; jj++) {
            int j = j0 + tx * 4 + jj;
            if (j < J)
                Y[((size_t)b * 128 + i0 + ty * 4 + ii) * J + j] = acc[ii][jj];
        }
}

// MODE 0: complex Y ; MODE 1: o1=mag, o2=pha ; MODE 2: |.| into cat ch16..31
template <int MODE>
__global__ void __launch_bounds__(256)
k_MxX64(const float2* __restrict__ M, const float2* __restrict__ Xc,
        float2* __restrict__ Y, float* __restrict__ o1, float* __restrict__ o2,
        int J) {
    __shared__ float2 sA[64][17];
    __shared__ float2 sB[16][65];
    int b = blockIdx.z;
    const float2* X = Xc + (size_t)b * 128 * J;
    int j0 = blockIdx.x * 64, i0 = blockIdx.y * 64;
    int tid = threadIdx.x;
    int tx = tid & 15, ty = tid >> 4;
    float2 acc[4][4];
#pragma unroll
    for (int a = 0; a < 4; a++)
#pragma unroll
        for (int c = 0; c < 4; c++) acc[a][c] = make_float2(0.f, 0.f);
    for (int kt = 0; kt < 128; kt += 16) {
#pragma unroll
        for (int s = 0; s < 4; s++) {
            int e = tid + s * 256;
            int r = e >> 4, c = e & 15;
            sA[r][c] = M[(i0 + r) * 128 + kt + c];
            int r2 = e >> 6, c2 = e & 63;
            float2 v = (j0 + c2 < J) ? X[(size_t)(kt + r2) * J + j0 + c2]
                                     : make_float2(0.f, 0.f);
            sB[r2][c2] = v;
        }
        __syncthreads();
#pragma unroll
        for (int kk = 0; kk < 16; kk++) {
            float2 av[4]; float2 bv[4];
#pragma unroll
            for (int ii = 0; ii < 4; ii++) av[ii] = sA[ty * 4 + ii][kk];
#pragma unroll
            for (int jj = 0; jj < 4; jj++) bv[jj] = sB[kk][tx * 4 + jj];
#pragma unroll
            for (int ii = 0; ii < 4; ii++)
#pragma unroll
                for (int jj = 0; jj < 4; jj++) {
                    acc[ii][jj].x += av[ii].x * bv[jj].x - av[ii].y * bv[jj].y;
                    acc[ii][jj].y += av[ii].x * bv[jj].y + av[ii].y * bv[jj].x;
                }
        }
        __syncthreads();
    }
#pragma unroll
    for (int ii = 0; ii < 4; ii++)
#pragma unroll
        for (int jj = 0; jj < 4; jj++) {
            int i = i0 + ty * 4 + ii;
            int j = j0 + tx * 4 + jj;
            if (j >= J) continue;
            float2 v = acc[ii][jj];
            if (MODE == 0) {
                Y[((size_t)b * 128 + i) * J + j] = v;
            } else if (MODE == 1) {
                size_t idx = ((size_t)b * 128 + i) * J + j;
                float m = sqrtf(v.x * v.x + v.y * v.y);
                o1[idx] = m;
                o2[idx] = atan2f(v.y, v.x);
            } else {
                int n = b >> 4, c = b & 15;
                o1[(size_t)(n * C1c + 16 + c) * PP + i * 128 + j] =
                    sqrtf(v.x * v.x + v.y * v.y);
            }
        }
}

// x_1o = Re(T3 @ Bw) -> cat ch 32..47
__global__ void k_irfft_w(const float2* __restrict__ T3, float* __restrict__ Ybase) {
    int b = blockIdx.z;
    int tx = threadIdx.x, ty = threadIdx.y;
    int hbase = blockIdx.y * 16;
    float acc[4] = {0.f, 0.f, 0.f, 0.f};
    for (int k = 0; k < JW; k++) {
        float2 bw = g_Bw[k * 128 + tx];
#pragma unroll
        for (int s = 0; s < 4; s++) {
            float2 a = T3[((size_t)b * 128 + hbase + ty * 4 + s) * JW + k];
            acc[s] += a.x * bw.x - a.y * bw.y;
        }
    }
    int n = b >> 4, c = b & 15;
    float* Yp = Ybase + (size_t)(n * C1c + 32 + c) * PP;
#pragma unroll
    for (int s = 0; s < 4; s++)
        Yp[(hbase + ty * 4 + s) * WW + tx] = acc[s];
}

// ---------------- 3x3 masked conv, fused with magw (in-register 16x16) ----
// writes magout = magw @ (conv3(mag*mask1) + mag_s_b) + mag_b for INSIDE pixels
__global__ void __launch_bounds__(256)
k_conv3m(const float* __restrict__ X, const float* __restrict__ Wt,
         const float* __restrict__ Bs, const float* __restrict__ MagW,
         const float* __restrict__ MagB, float* __restrict__ Y) {
    __shared__ float sW[CMc * CMc * 9];
    __shared__ float sMW[256];
    __shared__ float sSB[16];
    __shared__ float sMB[16];
    __shared__ float sT[10][34];
    int tid = threadIdx.y * 32 + threadIdx.x;
    for (int e = tid; e < CMc * CMc * 9; e += 256) sW[e] = Wt[e];
    if (tid < 256) sMW[tid] = MagW[tid];
    if (tid < 16) { sSB[tid] = Bs[tid]; sMB[tid] = MagB[tid]; }
    int n = blockIdx.z;
    int wb = blockIdx.x * 32, hb = 16 + blockIdx.y * 8;
    const float* Xn = X + (size_t)n * CMc * PP;
    float acc[CMc];
#pragma unroll
    for (int o = 0; o < CMc; o++) acc[o] = 0.f;
    for (int c = 0; c < CMc; c++) {
        __syncthreads();
        for (int e = tid; e < 340; e += 256) {
            int ly = e / 34, lx = e % 34;
            int gy = hb - 1 + ly, gx = wb - 1 + lx;
            float v = 0.f;
            if (gy >= 19 && gy < 109 && gx >= 19 && gx < 109)
                v = Xn[(size_t)c * PP + gy * WW + gx];
            sT[ly][lx] = v;
        }
        __syncthreads();
#pragma unroll
        for (int kh = 0; kh < 3; kh++)
#pragma unroll
            for (int kw = 0; kw < 3; kw++) {
                float xv = sT[threadIdx.y + kh][threadIdx.x + kw];
#pragma unroll
                for (int o = 0; o < CMc; o++)
                    acc[o] += sW[(o * CMc + c) * 9 + kh * 3 + kw] * xv;
            }
    }
    int h = hb + threadIdx.y, w = wb + threadIdx.x;
    if (h >= 19 && h < 109 && w >= 19 && w < 109) {
#pragma unroll
        for (int m = 0; m < CMc; m++) acc[m] += sSB[m];
        float* Yn = Y + (size_t)n * CMc * PP;
#pragma unroll
        for (int o = 0; o < CMc; o++) {
            float s = sMB[o];
#pragma unroll
            for (int m = 0; m < CMc; m++) s += sMW[o * 16 + m] * acc[m];
            Yn[(size_t)o * PP + h * WW + w] = s;
        }
    }
}

// ---------------- fused pha-mix + mag-outside + makec ----------------
// phaout = phaw @ pha + phab ; m = inside ? magout : W2 @ mag + b2 ; F = m*e^{i phaout}
__global__ void __launch_bounds__(256)
k_phamc(const float* __restrict__ Pha, const float* __restrict__ Mag,
        const float* __restrict__ MagO, const float* __restrict__ PhaW,
        const float* __restrict__ PhaB, float2* __restrict__ F) {
    __shared__ float sPW[256];
    __shared__ float sW2[256];
    __shared__ float sPB[16];
    __shared__ float sB2[16];
    int t = threadIdx.x;
    if (t < 256) { sPW[t] = PhaW[t]; sW2[t] = g_W2[t]; }
    if (t < 16)  { sPB[t] = PhaB[t]; sB2[t] = g_b2[t]; }
    __syncthreads();
    int n = blockIdx.y;
    int pb = blockIdx.x * 1024;
    size_t base = (size_t)n * 16 * PP;
#pragma unroll
    for (int s = 0; s < 4; s++) {
        int p = pb + s * 256 + t;
        int h = p >> 7, w = p & 127;
        bool inside = (h >= 19 && h < 109 && w >= 19 && w < 109);
        float ph[16], mg[16];
#pragma unroll
        for (int c = 0; c < 16; c++) ph[c] = Pha[base + (size_t)c * PP + p];
        if (!inside) {
#pragma unroll
            for (int c = 0; c < 16; c++) mg[c] = Mag[base + (size_t)c * PP + p];
        }
#pragma unroll
        for (int o = 0; o < 16; o++) {
            float po = sPB[o];
#pragma unroll
            for (int c = 0; c < 16; c++) po += sPW[o * 16 + c] * ph[c];
            float m;
            if (inside) {
                m = MagO[base + (size_t)o * PP + p];
            } else {
                m = sB2[o];
#pragma unroll
                for (int c = 0; c < 16; c++) m += sW2[o * 16 + c] * mg[c];
            }
            float sn, cs;
            sincosf(po, &sn, &cs);
            F[base + (size_t)o * PP + p] = make_float2(m * cs, m * sn);
        }
    }
}

// ---------------- fused rfft mag/pha mix + makec ----------------
__global__ void __launch_bounds__(256)
k_fmfp(const float* __restrict__ Fm, const float* __restrict__ Fp,
       const float* __restrict__ W, const float* __restrict__ B,
       float2* __restrict__ F) {
    __shared__ float sW[256];
    __shared__ float sB[16];
    int t = threadIdx.x;
    if (t < 256) sW[t] = W[t];
    if (t < 16)  sB[t] = B[t];
    __syncthreads();
    int n = blockIdx.y;
    int pb = blockIdx.x * 1024;
    size_t base = (size_t)n * 16 * P65;
#pragma unroll
    for (int s = 0; s < 4; s++) {
        int p = pb + s * 256 + t;
        if (p >= P65) continue;
        float fm[16], fp[16];
#pragma unroll
        for (int c = 0; c < 16; c++) {
            fm[c] = Fm[base + (size_t)c * P65 + p];
            fp[c] = Fp[base + (size_t)c * P65 + p];
        }
#pragma unroll
        for (int o = 0; o < 16; o++) {
            float mo = sB[o], po = sB[o];
#pragma unroll
            for (int c = 0; c < 16; c++) {
                mo += sW[o * 16 + c] * fm[c];
                po += sW[o * 16 + c] * fp[c];
            }
            float sn, cs;
            sincosf(po, &sn, &cs);
            F[base + (size_t)o * P65 + p] = make_float2(mo * cs, mo * sn);
        }
    }
}

// ---------------- launch ----------------
extern "C" void kernel_launch(void* const* d_in, const int* in_sizes, int n_in,
                              void* d_out, int out_size) {
    const float* x        = (const float*)d_in[0];
    const float* conv1_w  = (const float*)d_in[1];
    const float* mag_s_w  = (const float*)d_in[2];
    const float* mag_s_b  = (const float*)d_in[3];
    const float* mag_f_w  = (const float*)d_in[4];
    const float* mag_f_b  = (const float*)d_in[5];
    const float* mag_w    = (const float*)d_in[6];
    const float* mag_b    = (const float*)d_in[7];
    const float* pha_w    = (const float*)d_in[8];
    const float* pha_b    = (const float*)d_in[9];
    const float* conv_0_w = (const float*)d_in[10];
    const float* conv_0_b = (const float*)d_in[11];
    const float* conv_1_w = (const float*)d_in[12];
    const float* conv_1_b = (const float*)d_in[13];
    const float* conv2_w  = (const float*)d_in[14];
    float* out = (float*)d_out;

    float  *px1, *pmag, *ppha, *pmagout, *pfm, *pfp, *pcat;
    float2 *pM, *pMinv, *pFh, *pFhi, *pFw, *pT, *pF, *pT65, *pF65;
    cudaGetSymbolAddress((void**)&px1,    g_x1);
    cudaGetSymbolAddress((void**)&pmag,   g_mag);
    cudaGetSymbolAddress((void**)&ppha,   g_pha);
    cudaGetSymbolAddress((void**)&pmagout,g_magout);
    cudaGetSymbolAddress((void**)&pfm,    g_fm);
    cudaGetSymbolAddress((void**)&pfp,    g_fp);
    cudaGetSymbolAddress((void**)&pcat,   g_cat);
    cudaGetSymbolAddress((void**)&pM,     g_M);
    cudaGetSymbolAddress((void**)&pMinv,  g_Minv);
    cudaGetSymbolAddress((void**)&pFh,    g_Fh);
    cudaGetSymbolAddress((void**)&pFhi,   g_Fhi);
    cudaGetSymbolAddress((void**)&pFw,    g_Fw);
    cudaGetSymbolAddress((void**)&pT,     g_T);
    cudaGetSymbolAddress((void**)&pF,     g_F);
    cudaGetSymbolAddress((void**)&pT65,   g_T65);
    cudaGetSymbolAddress((void**)&pF65,   g_F65);

    // constant matrices + folded weights
    k_tables<<<1, 512>>>();
    k_dft<<<64, 256>>>();
    k_buildM<<<64, 256>>>();
    k_buildMinv<<<128, 128>>>();
    k_w2<<<1, 256>>>(mag_w, mag_f_w, mag_f_b, mag_b);
    k_wc<<<12, 256>>>(conv2_w, conv_0_w, conv_0_b);

    // conv1: 192 -> 48
    k_g1x1<<<dim3(32, 3, NB), 128>>>(x, conv1_w, nullptr, px1, 192, PP, 192 * PP, 48 * PP);

    // ---- FRFT forward: Fre = M @ X @ M^T  (x_05 = channels 16..31) ----
    k_rxMT64<<<dim3(2, 2, BATCH), 256>>>(px1, C1c, 16, pM, pT, 128);
    k_MxX64<1><<<dim3(2, 2, BATCH), 256>>>(pM, pT, nullptr, pmag, ppha, 128);

    // mag path: conv3 + magw fused (inside mask); pha mix + outside mag + makec fused
    k_conv3m<<<dim3(4, 12, NB), dim3(32, 8)>>>(pmag, mag_s_w, mag_s_b, mag_w, mag_b, pmagout);
    k_phamc<<<dim3(16, NB), 256>>>(ppha, pmag, pmagout, pha_w, pha_b, pF);

    // ---- FRFT inverse: |Minv @ FreOut @ Minv^T| -> cat ch16..31 ----
    k_cMT64<<<dim3(2, 2, BATCH), 256>>>(pF, pMinv, pT, 128);
    k_MxX64<2><<<dim3(2, 2, BATCH), 256>>>(pMinv, pT, nullptr, pcat, nullptr, 128);

    // ---- rfft2 branch (x_1 = channels 32..47) ----
    k_rxMT64<<<dim3(2, 2, BATCH), 256>>>(px1, C1c, 32, pFw, pT65, JW);
    k_MxX64<1><<<dim3(2, 2, BATCH), 256>>>(pFh, pT65, nullptr, pfm, pfp, JW);
    k_fmfp<<<dim3(9, NB), 256>>>(pfm, pfp, conv_1_w, conv_1_b, pF65);
    k_MxX64<0><<<dim3(2, 2, BATCH), 256>>>(pFhi, pF65, pT65, nullptr, nullptr, JW);
    k_irfft_w<<<dim3(1, 8, BATCH), dim3(128, 4)>>>(pT65, pcat);

    // ---- conv2 (conv_0 folded in): 48 -> 192 ----
    k_conv2<<<dim3(32, 12, NB), 128>>>(px1, pcat, conv2_w, out);
}

// round 8
// speedup vs baseline: 1.6367x; 1.6367x over previous
#include <cuda_runtime.h>
#include <math.h>

#define NB   4
#define CIN  192
#define HH   128
#define WW   128
#define PP   (HH*WW)       // 16384
#define C1c  48
#define C0c  16
#define CMc  16
#define BATCH 64           // NB * CMc
#define JW   65
#define P65  (128*JW)      // 8320

// ---------------- device scratch (no allocation allowed) ----------------
static __device__ float2 gf_chrp1[255];
static __device__ float2 gf_E[509];
static __device__ float  gf_S[509];
static __device__ float2 gf_fac[128];

static __device__ float2  g_M   [128*128];
static __device__ float2  g_Cm  [128*128];
static __device__ float2  g_Minv[128*128];
static __device__ float2  g_Fh  [128*128];
static __device__ float2  g_Fhi [128*128];
static __device__ float2  g_Fw  [JW*128];
static __device__ float2  g_Bw  [JW*128];

static __device__ float   g_W2[256];      // magw @ magf
static __device__ float   g_b2[16];       // magw @ magf_b + mag_b
static __device__ float   g_Wc[192*16];   // conv2[:, :16] @ conv0_w
static __device__ float   g_bc[192];      // conv2[:, :16] @ conv0_b

static __device__ float   g_x1 [NB*C1c*PP];
static __device__ float2  g_T  [BATCH*128*128];
static __device__ float2  g_F  [BATCH*128*128];
static __device__ float   g_mag[BATCH*PP];
static __device__ float   g_pha[BATCH*PP];
static __device__ float   g_magout[BATCH*PP];
static __device__ float2  g_T65[BATCH*P65];
static __device__ float2  g_F65[BATCH*P65];
static __device__ float   g_fm[BATCH*P65];
static __device__ float   g_fp[BATCH*P65];
static __device__ float   g_cat[NB*C1c*PP];   // ch 16..47 used

// ---------------- table construction ----------------
__global__ void k_tables() {
    int t = threadIdx.x;
    const double PI = 3.14159265358979323846;
    double tana2 = tan(PI / 8.0);
    double sina  = sin(PI / 4.0);
    double coef  = tana2 / 512.0;
    double ec    = 1.0 / (512.0 * sina);
    for (int j = t; j < 255; j += 512) {
        double n = (double)(j - 127);
        double s, c; sincospi(-coef * n * n, &s, &c);
        gf_chrp1[j] = make_float2((float)c, (float)s);
    }
    double amp = sqrt(1.0 / (512.0 * sina));
    double ps, pc; sincospi(-0.125, &ps, &pc);
    for (int r = t; r < 128; r += 512) {
        double n = 2.0 * r - 127.0;
        double s, c; sincospi(-coef * n * n, &s, &c);
        gf_fac[r] = make_float2((float)(amp * (pc * c - ps * s)),
                                (float)(amp * (pc * s + ps * c)));
    }
    for (int i = t; i < 509; i += 512) {
        double d = (double)(i - 254);
        double s, c; sincospi(ec * d * d, &s, &c);
        gf_E[i] = make_float2((float)c, (float)s);
        int m = i - 254;
        double sv;
        if (m == 0) sv = 1.0;
        else if ((m & 1) == 0) sv = 0.0;
        else {
            double x = 0.5 * (double)m;
            sv = sinpi(x) / (PI * x);
        }
        gf_S[i] = (float)sv;
    }
}

__global__ void k_dft() {
    int idx = blockIdx.x * 256 + threadIdx.x;
    if (idx < 128 * 128) {
        int u = idx >> 7, v = idx & 127;
        int e1 = ((u + 64) * (v + 64)) & 127;
        double s, c; sincospi(2.0 * e1 / 128.0, &s, &c);
        double inv = 1.0 / sqrt(128.0);
        g_Cm[idx] = make_float2((float)(c * inv), (float)(s * inv));
        int e2 = (u * v) & 127;
        double s2, c2; sincospi(-2.0 * e2 / 128.0, &s2, &c2);
        g_Fh[idx] = make_float2((float)c2, (float)s2);
        double s3, c3; sincospi(2.0 * e2 / 128.0, &s3, &c3);
        g_Fhi[idx] = make_float2((float)(c3 / 128.0), (float)(s3 / 128.0));
    }
    if (idx < JW * 128) {
        int k = idx / 128, w = idx & 127;
        int e = (k * w) & 127;
        double s, c; sincospi(-2.0 * e / 128.0, &s, &c);
        g_Fw[idx] = make_float2((float)c, (float)s);
        float2 bw;
        if (k == 0)       bw = make_float2(1.0f / 128.0f, 0.f);
        else if (k == 64) bw = make_float2(((w & 1) ? -1.0f : 1.0f) / 128.0f, 0.f);
        else {
            double s4, c4; sincospi(2.0 * e / 128.0, &s4, &c4);
            bw = make_float2((float)(c4 * 2.0 / 128.0), (float)(s4 * 2.0 / 128.0));
        }
        g_Bw[idx] = bw;
    }
}

__global__ void k_buildM() {
    int idx = blockIdx.x * 256 + threadIdx.x;
    if (idx >= 128 * 128) return;
    int r = idx >> 7, k = idx & 127;
    float ax = 0.f, ay = 0.f;
    {
        int j = 2 * k;
        float2 c1 = gf_chrp1[j];
        float2 e  = gf_E[2 * r - j + 254];
        ax += c1.x * e.x - c1.y * e.y;
        ay += c1.x * e.y + c1.y * e.x;
    }
    for (int j = 1; j < 255; j += 2) {
        float s = gf_S[j - 2 * k + 254];
        float2 c1 = gf_chrp1[j];
        float2 e  = gf_E[2 * r - j + 254];
        ax += (c1.x * e.x - c1.y * e.y) * s;
        ay += (c1.x * e.y + c1.y * e.x) * s;
    }
    float2 f = gf_fac[r];
    g_M[idx] = make_float2(f.x * ax - f.y * ay, f.x * ay + f.y * ax);
}

__global__ void __launch_bounds__(128) k_buildMinv() {
    __shared__ float2 sM[128];
    int r = blockIdx.x, v = threadIdx.x;
    sM[v] = g_M[r * 128 + v];
    __syncthreads();
    float ax = 0.f, ay = 0.f;
#pragma unroll 8
    for (int u = 0; u < 128; u++) {
        float2 a = sM[u];
        float2 b = g_Cm[u * 128 + v];
        ax += a.x * b.x - a.y * b.y;
        ay += a.x * b.y + a.y * b.x;
    }
    g_Minv[r * 128 + v] = make_float2(ax, ay);
}

// W2 = magw @ magf ; b2 = magw @ magf_b + mag_b
__global__ void k_w2(const float* __restrict__ magw, const float* __restrict__ magf,
                     const float* __restrict__ magfb, const float* __restrict__ magb) {
    int t = threadIdx.x;
    int o = t >> 4, c = t & 15;
    float a = 0.f;
#pragma unroll
    for (int m = 0; m < 16; m++) a += magw[o * 16 + m] * magf[m * 16 + c];
    g_W2[t] = a;
    if (t < 16) {
        float b = magb[t];
#pragma unroll
        for (int m = 0; m < 16; m++) b += magw[t * 16 + m] * magfb[m];
        g_b2[t] = b;
    }
}

// Wc = conv2[:, :16] @ conv0_w ; bc = conv2[:, :16] @ conv0_b
__global__ void k_wc(const float* __restrict__ conv2w, const float* __restrict__ conv0w,
                     const float* __restrict__ conv0b) {
    int idx = blockIdx.x * 256 + threadIdx.x;
    if (idx < 192 * 16) {
        int o = idx >> 4, c = idx & 15;
        float a = 0.f;
#pragma unroll
        for (int m = 0; m < 16; m++) a += conv2w[o * 48 + m] * conv0w[m * 16 + c];
        g_Wc[idx] = a;
    }
    if (idx < 192) {
        float b = 0.f;
#pragma unroll
        for (int m = 0; m < 16; m++) b += conv2w[idx * 48 + m] * conv0b[m];
        g_bc[idx] = b;
    }
}

// ---------------- generic 1x1 conv (GEMM) — used for conv1 ----------------
__global__ void __launch_bounds__(128)
k_g1x1(const float* __restrict__ X, const float* __restrict__ Wt,
       const float* __restrict__ Bs, float* __restrict__ Y,
       int Cc, int P, int xStrideN, int yStrideN) {
    __shared__ float sW[16 * 192];
    int n = blockIdx.z, ob = blockIdx.y * 16;
    int tx = threadIdx.x;
    for (int e = tx; e < 16 * Cc; e += 128) sW[e] = Wt[ob * Cc + e];
    __syncthreads();
    const float* Xn = X + (size_t)n * xStrideN;
    int pb = blockIdx.x * 512;
    float acc[16][4];
#pragma unroll
    for (int o = 0; o < 16; o++)
#pragma unroll
        for (int s = 0; s < 4; s++) acc[o][s] = 0.f;
    for (int c = 0; c < Cc; c++) {
        float xv[4];
#pragma unroll
        for (int s = 0; s < 4; s++) {
            int p = pb + s * 128 + tx;
            xv[s] = (p < P) ? Xn[(size_t)c * P + p] : 0.f;
        }
#pragma unroll
        for (int o = 0; o < 16; o++) {
            float w = sW[o * Cc + c];
#pragma unroll
            for (int s = 0; s < 4; s++) acc[o][s] += w * xv[s];
        }
    }
#pragma unroll
    for (int o = 0; o < 16; o++) {
        float b = Bs ? Bs[ob + o] : 0.f;
#pragma unroll
        for (int s = 0; s < 4; s++) {
            int p = pb + s * 128 + tx;
            if (p < P) Y[(size_t)n * yStrideN + (size_t)(ob + o) * P + p] = acc[o][s] + b;
        }
    }
}

// ---------------- conv2 with folded conv_0 branch (clean split loops) -----
__global__ void __launch_bounds__(128)
k_conv2(const float* __restrict__ X1, const float* __restrict__ Cat,
        const float* __restrict__ conv2w, float* __restrict__ Y) {
    __shared__ float sWa[16 * 16];   // folded Wc, ch 0..15 (reads x1)
    __shared__ float sWb[16 * 32];   // conv2w, ch 16..47 (reads cat)
    __shared__ float sB[16];
    int n = blockIdx.z, ob = blockIdx.y * 16;
    int tx = threadIdx.x;
    for (int e = tx; e < 256; e += 128)
        sWa[e] = g_Wc[(ob + (e >> 4)) * 16 + (e & 15)];
    for (int e = tx; e < 512; e += 128) {
        int o = e >> 5, c = e & 31;
        sWb[e] = conv2w[(ob + o) * 48 + 16 + c];
    }
    if (tx < 16) sB[tx] = g_bc[ob + tx];
    __syncthreads();
    const float* Xn = X1 + (size_t)n * 48 * PP;
    const float* Cn = Cat + (size_t)n * 48 * PP + (size_t)16 * PP;
    int pb = blockIdx.x * 512;
    float acc[16][4];
#pragma unroll
    for (int o = 0; o < 16; o++)
#pragma unroll
        for (int s = 0; s < 4; s++) acc[o][s] = 0.f;
#pragma unroll 4
    for (int c = 0; c < 16; c++) {
        float xv[4];
#pragma unroll
        for (int s = 0; s < 4; s++)
            xv[s] = Xn[(size_t)c * PP + pb + s * 128 + tx];
#pragma unroll
        for (int o = 0; o < 16; o++) {
            float w = sWa[o * 16 + c];
#pragma unroll
            for (int s = 0; s < 4; s++) acc[o][s] += w * xv[s];
        }
    }
#pragma unroll 4
    for (int c = 0; c < 32; c++) {
        float xv[4];
#pragma unroll
        for (int s = 0; s < 4; s++)
            xv[s] = Cn[(size_t)c * PP + pb + s * 128 + tx];
#pragma unroll
        for (int o = 0; o < 16; o++) {
            float w = sWb[o * 32 + c];
#pragma unroll
            for (int s = 0; s < 4; s++) acc[o][s] += w * xv[s];
        }
    }
#pragma unroll
    for (int o = 0; o < 16; o++)
#pragma unroll
        for (int s = 0; s < 4; s++)
            Y[(size_t)n * 192 * PP + (size_t)(ob + o) * PP + pb + s * 128 + tx] =
                acc[o][s] + sB[o];
}

// ---------------- 64x64-tile complex GEMMs ----------------
__global__ void __launch_bounds__(256)
k_rxMT64(const float* __restrict__ Xb, int cPerN, int cOff,
         const float2* __restrict__ M, float2* __restrict__ Y, int J) {
    __shared__ float  sA[64][17];
    __shared__ float2 sB[16][65];
    int b = blockIdx.z;
    const float* X = Xb + (size_t)((b >> 4) * cPerN + cOff + (b & 15)) * PP;
    int j0 = blockIdx.x * 64, i0 = blockIdx.y * 64;
    int tid = threadIdx.x;
    int tx = tid & 15, ty = tid >> 4;
    float2 acc[4][4];
#pragma unroll
    for (int a = 0; a < 4; a++)
#pragma unroll
        for (int c = 0; c < 4; c++) acc[a][c] = make_float2(0.f, 0.f);
    for (int kt = 0; kt < 128; kt += 16) {
#pragma unroll
        for (int s = 0; s < 4; s++) {
            int e = tid + s * 256; int r = e >> 4, c = e & 15;
            sA[r][c] = X[(i0 + r) * 128 + kt + c];
            float2 v = (j0 + r < J) ? M[(j0 + r) * 128 + kt + c] : make_float2(0.f, 0.f);
            sB[c][r] = v;
        }
        __syncthreads();
#pragma unroll
        for (int kk = 0; kk < 16; kk++) {
            float av[4]; float2 bv[4];
#pragma unroll
            for (int ii = 0; ii < 4; ii++) av[ii] = sA[ty * 4 + ii][kk];
#pragma unroll
            for (int jj = 0; jj < 4; jj++) bv[jj] = sB[kk][tx * 4 + jj];
#pragma unroll
            for (int ii = 0; ii < 4; ii++)
#pragma unroll
                for (int jj = 0; jj < 4; jj++) {
                    acc[ii][jj].x += av[ii] * bv[jj].x;
                    acc[ii][jj].y += av[ii] * bv[jj].y;
                }
        }
        __syncthreads();
    }
#pragma unroll
    for (int ii = 0; ii < 4; ii++)
#pragma unroll
        for (int jj = 0; jj < 4; jj++) {
            int j = j0 + tx * 4 + jj;
            if (j < J)
                Y[((size_t)b * 128 + i0 + ty * 4 + ii) * J + j] = acc[ii][jj];
        }
}

__global__ void __launch_bounds__(256)
k_cMT64(const float2* __restrict__ Xc, const float2* __restrict__ M,
        float2* __restrict__ Y, int J) {
    __shared__ float2 sA[64][17];
    __shared__ float2 sB[16][65];
    int b = blockIdx.z;
    const float2* X = Xc + (size_t)b * 128 * 128;
    int j0 = blockIdx.x * 64, i0 = blockIdx.y * 64;
    int tid = threadIdx.x;
    int tx = tid & 15, ty = tid >> 4;
    float2 acc[4][4];
#pragma unroll
    for (int a = 0; a < 4; a++)
#pragma unroll
        for (int c = 0; c < 4; c++) acc[a][c] = make_float2(0.f, 0.f);
    for (int kt = 0; kt < 128; kt += 16) {
#pragma unroll
        for (int s = 0; s < 4; s++) {
            int e = tid + s * 256; int r = e >> 4, c = e & 15;
            sA[r][c] = X[(i0 + r) * 128 + kt + c];
            float2 v = (j0 + r < J) ? M[(j0 + r) * 128 + kt + c] : make_float2(0.f, 0.f);
            sB[c][r] = v;
        }
        __syncthreads();
#pragma unroll
        for (int kk = 0; kk < 16; kk++) {
            float2 av[4]; float2 bv[4];
#pragma unroll
            for (int ii = 0; ii < 4; ii++) av[ii] = sA[ty * 4 + ii][kk];
#pragma unroll
            for (int jj = 0; jj < 4; jj++) bv[jj] = sB[kk][tx * 4 + jj];
#pragma unroll
            for (int ii = 0; ii < 4; ii++)
#pragma unroll
                for (int jj = 0; jj < 4; jj++) {
                    acc[ii][jj].x += av[ii].x * bv[jj].x - av[ii].y * bv[jj].y;
                    acc[ii][jj].y += av[ii].x * bv[jj].y + av[ii].y * bv[jj].x;
                }
        }
        __syncthreads();
    }
#pragma unroll
    for (int ii = 0; ii < 4; ii++)
#pragma unroll
        for (int jj = 0; jj < 4; jj++) {
            int j = j0 + tx * 4 + jj;
            if (j < J)
                Y[((size_t)b * 128 + i0 + ty * 4 + ii) * J + j] = acc[ii][jj];
        }
}

// MODE 0: complex Y ; MODE 1: o1=mag, o2=pha ; MODE 2: |.| into cat ch16..31
template <int MODE>
__global__ void __launch_bounds__(256)
k_MxX64(const float2* __restrict__ M, const float2* __restrict__ Xc,
        float2* __restrict__ Y, float* __restrict__ o1, float* __restrict__ o2,
        int J) {
    __shared__ float2 sA[64][17];
    __shared__ float2 sB[16][65];
    int b = blockIdx.z;
    const float2* X = Xc + (size_t)b * 128 * J;
    int j0 = blockIdx.x * 64, i0 = blockIdx.y * 64;
    int tid = threadIdx.x;
    int tx = tid & 15, ty = tid >> 4;
    float2 acc[4][4];
#pragma unroll
    for (int a = 0; a < 4; a++)
#pragma unroll
        for (int c = 0; c < 4; c++) acc[a][c] = make_float2(0.f, 0.f);
    for (int kt = 0; kt < 128; kt += 16) {
#pragma unroll
        for (int s = 0; s < 4; s++) {
            int e = tid + s * 256;
            int r = e >> 4, c = e & 15;
            sA[r][c] = M[(i0 + r) * 128 + kt + c];
            int r2 = e >> 6, c2 = e & 63;
            float2 v = (j0 + c2 < J) ? X[(size_t)(kt + r2) * J + j0 + c2]
                                     : make_float2(0.f, 0.f);
            sB[r2][c2] = v;
        }
        __syncthreads();
#pragma unroll
        for (int kk = 0; kk < 16; kk++) {
            float2 av[4]; float2 bv[4];
#pragma unroll
            for (int ii = 0; ii < 4; ii++) av[ii] = sA[ty * 4 + ii][kk];
#pragma unroll
            for (int jj = 0; jj < 4; jj++) bv[jj] = sB[kk][tx * 4 + jj];
#pragma unroll
            for (int ii = 0; ii < 4; ii++)
#pragma unroll
                for (int jj = 0; jj < 4; jj++) {
                    acc[ii][jj].x += av[ii].x * bv[jj].x - av[ii].y * bv[jj].y;
                    acc[ii][jj].y += av[ii].x * bv[jj].y + av[ii].y * bv[jj].x;
                }
        }
        __syncthreads();
    }
#pragma unroll
    for (int ii = 0; ii < 4; ii++)
#pragma unroll
        for (int jj = 0; jj < 4; jj++) {
            int i = i0 + ty * 4 + ii;
            int j = j0 + tx * 4 + jj;
            if (j >= J) continue;
            float2 v = acc[ii][jj];
            if (MODE == 0) {
                Y[((size_t)b * 128 + i) * J + j] = v;
            } else if (MODE == 1) {
                size_t idx = ((size_t)b * 128 + i) * J + j;
                float m = sqrtf(v.x * v.x + v.y * v.y);
                o1[idx] = m;
                o2[idx] = atan2f(v.y, v.x);
            } else {
                int n = b >> 4, c = b & 15;
                o1[(size_t)(n * C1c + 16 + c) * PP + i * 128 + j] =
                    sqrtf(v.x * v.x + v.y * v.y);
            }
        }
}

// x_1o = Re(T3 @ Bw) -> cat ch 32..47
__global__ void k_irfft_w(const float2* __restrict__ T3, float* __restrict__ Ybase) {
    int b = blockIdx.z;
    int tx = threadIdx.x, ty = threadIdx.y;
    int hbase = blockIdx.y * 16;
    float acc[4] = {0.f, 0.f, 0.f, 0.f};
    for (int k = 0; k < JW; k++) {
        float2 bw = g_Bw[k * 128 + tx];
#pragma unroll
        for (int s = 0; s < 4; s++) {
            float2 a = T3[((size_t)b * 128 + hbase + ty * 4 + s) * JW + k];
            acc[s] += a.x * bw.x - a.y * bw.y;
        }
    }
    int n = b >> 4, c = b & 15;
    float* Yp = Ybase + (size_t)(n * C1c + 32 + c) * PP;
#pragma unroll
    for (int s = 0; s < 4; s++)
        Yp[(hbase + ty * 4 + s) * WW + tx] = acc[s];
}

// ---------------- 3x3 masked conv, fused with magw ----------------
__global__ void __launch_bounds__(256)
k_conv3m(const float* __restrict__ X, const float* __restrict__ Wt,
         const float* __restrict__ Bs, const float* __restrict__ MagW,
         const float* __restrict__ MagB, float* __restrict__ Y) {
    __shared__ float sW[CMc * CMc * 9];
    __shared__ float sMW[256];
    __shared__ float sSB[16];
    __shared__ float sMB[16];
    __shared__ float sT[10][34];
    int tid = threadIdx.y * 32 + threadIdx.x;
    for (int e = tid; e < CMc * CMc * 9; e += 256) sW[e] = Wt[e];
    if (tid < 256) sMW[tid] = MagW[tid];
    if (tid < 16) { sSB[tid] = Bs[tid]; sMB[tid] = MagB[tid]; }
    int n = blockIdx.z;
    int wb = blockIdx.x * 32, hb = 16 + blockIdx.y * 8;
    const float* Xn = X + (size_t)n * CMc * PP;
    float acc[CMc];
#pragma unroll
    for (int o = 0; o < CMc; o++) acc[o] = 0.f;
    for (int c = 0; c < CMc; c++) {
        __syncthreads();
        for (int e = tid; e < 340; e += 256) {
            int ly = e / 34, lx = e % 34;
            int gy = hb - 1 + ly, gx = wb - 1 + lx;
            float v = 0.f;
            if (gy >= 19 && gy < 109 && gx >= 19 && gx < 109)
                v = Xn[(size_t)c * PP + gy * WW + gx];
            sT[ly][lx] = v;
        }
        __syncthreads();
#pragma unroll
        for (int kh = 0; kh < 3; kh++)
#pragma unroll
            for (int kw = 0; kw < 3; kw++) {
                float xv = sT[threadIdx.y + kh][threadIdx.x + kw];
#pragma unroll
                for (int o = 0; o < CMc; o++)
                    acc[o] += sW[(o * CMc + c) * 9 + kh * 3 + kw] * xv;
            }
    }
    int h = hb + threadIdx.y, w = wb + threadIdx.x;
    if (h >= 19 && h < 109 && w >= 19 && w < 109) {
#pragma unroll
        for (int m = 0; m < CMc; m++) acc[m] += sSB[m];
        float* Yn = Y + (size_t)n * CMc * PP;
#pragma unroll
        for (int o = 0; o < CMc; o++) {
            float s = sMB[o];
#pragma unroll
            for (int m = 0; m < CMc; m++) s += sMW[o * 16 + m] * acc[m];
            Yn[(size_t)o * PP + h * WW + w] = s;
        }
    }
}

// ---------------- fused pha-mix + mag-outside + makec (1 px/thread) -------
__global__ void __launch_bounds__(128)
k_phamc(const float* __restrict__ Pha, const float* __restrict__ Mag,
        const float* __restrict__ MagO, const float* __restrict__ PhaW,
        const float* __restrict__ PhaB, float2* __restrict__ F) {
    __shared__ float sPW[256];
    __shared__ float sW2[256];
    __shared__ float sPB[16];
    __shared__ float sB2[16];
    int t = threadIdx.x;
    sPW[t] = PhaW[t]; sPW[t + 128] = PhaW[t + 128];
    sW2[t] = g_W2[t]; sW2[t + 128] = g_W2[t + 128];
    if (t < 16)  { sPB[t] = PhaB[t]; sB2[t] = g_b2[t]; }
    __syncthreads();
    int n = blockIdx.y;
    int p = blockIdx.x * 128 + t;
    int h = p >> 7, w = p & 127;
    bool inside = (h >= 19 && h < 109 && w >= 19 && w < 109);
    size_t base = (size_t)n * 16 * PP;
    float ph[16], mg[16];
#pragma unroll
    for (int c = 0; c < 16; c++) ph[c] = Pha[base + (size_t)c * PP + p];
    if (!inside) {
#pragma unroll
        for (int c = 0; c < 16; c++) mg[c] = Mag[base + (size_t)c * PP + p];
    }
#pragma unroll
    for (int o = 0; o < 16; o++) {
        float po = sPB[o];
#pragma unroll
        for (int c = 0; c < 16; c++) po += sPW[o * 16 + c] * ph[c];
        float m;
        if (inside) {
            m = MagO[base + (size_t)o * PP + p];
        } else {
            m = sB2[o];
#pragma unroll
            for (int c = 0; c < 16; c++) m += sW2[o * 16 + c] * mg[c];
        }
        float sn, cs;
        sincosf(po, &sn, &cs);
        F[base + (size_t)o * PP + p] = make_float2(m * cs, m * sn);
    }
}

// ---------------- fused rfft mag/pha mix + makec (1 px/thread) ------------
__global__ void __launch_bounds__(128)
k_fmfp(const float* __restrict__ Fm, const float* __restrict__ Fp,
       const float* __restrict__ W, const float* __restrict__ B,
       float2* __restrict__ F) {
    __shared__ float sW[256];
    __shared__ float sB[16];
    int t = threadIdx.x;
    sW[t] = W[t]; sW[t + 128] = W[t + 128];
    if (t < 16)  sB[t] = B[t];
    __syncthreads();
    int n = blockIdx.y;
    int p = blockIdx.x * 128 + t;
    if (p >= P65) return;
    size_t base = (size_t)n * 16 * P65;
    float fm[16], fp[16];
#pragma unroll
    for (int c = 0; c < 16; c++) {
        fm[c] = Fm[base + (size_t)c * P65 + p];
        fp[c] = Fp[base + (size_t)c * P65 + p];
    }
#pragma unroll
    for (int o = 0; o < 16; o++) {
        float mo = sB[o], po = sB[o];
#pragma unroll
        for (int c = 0; c < 16; c++) {
            mo += sW[o * 16 + c] * fm[c];
            po += sW[o * 16 + c] * fp[c];
        }
        float sn, cs;
        sincosf(po, &sn, &cs);
        F[base + (size_t)o * P65 + p] = make_float2(mo * cs, mo * sn);
    }
}

// ---------------- launch ----------------
extern "C" void kernel_launch(void* const* d_in, const int* in_sizes, int n_in,
                              void* d_out, int out_size) {
    const float* x        = (const float*)d_in[0];
    const float* conv1_w  = (const float*)d_in[1];
    const float* mag_s_w  = (const float*)d_in[2];
    const float* mag_s_b  = (const float*)d_in[3];
    const float* mag_f_w  = (const float*)d_in[4];
    const float* mag_f_b  = (const float*)d_in[5];
    const float* mag_w    = (const float*)d_in[6];
    const float* mag_b    = (const float*)d_in[7];
    const float* pha_w    = (const float*)d_in[8];
    const float* pha_b    = (const float*)d_in[9];
    const float* conv_0_w = (const float*)d_in[10];
    const float* conv_0_b = (const float*)d_in[11];
    const float* conv_1_w = (const float*)d_in[12];
    const float* conv_1_b = (const float*)d_in[13];
    const float* conv2_w  = (const float*)d_in[14];
    float* out = (float*)d_out;

    float  *px1, *pmag, *ppha, *pmagout, *pfm, *pfp, *pcat;
    float2 *pM, *pMinv, *pFh, *pFhi, *pFw, *pT, *pF, *pT65, *pF65;
    cudaGetSymbolAddress((void**)&px1,    g_x1);
    cudaGetSymbolAddress((void**)&pmag,   g_mag);
    cudaGetSymbolAddress((void**)&ppha,   g_pha);
    cudaGetSymbolAddress((void**)&pmagout,g_magout);
    cudaGetSymbolAddress((void**)&pfm,    g_fm);
    cudaGetSymbolAddress((void**)&pfp,    g_fp);
    cudaGetSymbolAddress((void**)&pcat,   g_cat);
    cudaGetSymbolAddress((void**)&pM,     g_M);
    cudaGetSymbolAddress((void**)&pMinv,  g_Minv);
    cudaGetSymbolAddress((void**)&pFh,    g_Fh);
    cudaGetSymbolAddress((void**)&pFhi,   g_Fhi);
    cudaGetSymbolAddress((void**)&pFw,    g_Fw);
    cudaGetSymbolAddress((void**)&pT,     g_T);
    cudaGetSymbolAddress((void**)&pF,     g_F);
    cudaGetSymbolAddress((void**)&pT65,   g_T65);
    cudaGetSymbolAddress((void**)&pF65,   g_F65);

    // constant matrices + folded weights
    k_tables<<<1, 512>>>();
    k_dft<<<64, 256>>>();
    k_buildM<<<64, 256>>>();
    k_buildMinv<<<128, 128>>>();
    k_w2<<<1, 256>>>(mag_w, mag_f_w, mag_f_b, mag_b);
    k_wc<<<12, 256>>>(conv2_w, conv_0_w, conv_0_b);

    // conv1: 192 -> 48
    k_g1x1<<<dim3(32, 3, NB), 128>>>(x, conv1_w, nullptr, px1, 192, PP, 192 * PP, 48 * PP);

    // ---- FRFT forward: Fre = M @ X @ M^T  (x_05 = channels 16..31) ----
    k_rxMT64<<<dim3(2, 2, BATCH), 256>>>(px1, C1c, 16, pM, pT, 128);
    k_MxX64<1><<<dim3(2, 2, BATCH), 256>>>(pM, pT, nullptr, pmag, ppha, 128);

    // mag path: conv3 + magw fused (inside); pha mix + outside mag + makec fused
    k_conv3m<<<dim3(4, 12, NB), dim3(32, 8)>>>(pmag, mag_s_w, mag_s_b, mag_w, mag_b, pmagout);
    k_phamc<<<dim3(128, NB), 128>>>(ppha, pmag, pmagout, pha_w, pha_b, pF);

    // ---- FRFT inverse: |Minv @ FreOut @ Minv^T| -> cat ch16..31 ----
    k_cMT64<<<dim3(2, 2, BATCH), 256>>>(pF, pMinv, pT, 128);
    k_MxX64<2><<<dim3(2, 2, BATCH), 256>>>(pMinv, pT, nullptr, pcat, nullptr, 128);

    // ---- rfft2 branch (x_1 = channels 32..47) ----
    k_rxMT64<<<dim3(2, 2, BATCH), 256>>>(px1, C1c, 32, pFw, pT65, JW);
    k_MxX64<1><<<dim3(2, 2, BATCH), 256>>>(pFh, pT65, nullptr, pfm, pfp, JW);
    k_fmfp<<<dim3(65, NB), 128>>>(pfm, pfp, conv_1_w, conv_1_b, pF65);
    k_MxX64<0><<<dim3(2, 2, BATCH), 256>>>(pFhi, pF65, pT65, nullptr, nullptr, JW);
    k_irfft_w<<<dim3(1, 8, BATCH), dim3(128, 4)>>>(pT65, pcat);

    // ---- conv2 (conv_0 folded in): 48 -> 192 ----
    k_conv2<<<dim3(32, 12, NB), 128>>>(px1, pcat, conv2_w, out);
}

// round 9
// speedup vs baseline: 1.9705x; 1.2040x over previous
#include <cuda_runtime.h>
#include <math.h>

#define NB   4
#define CIN  192
#define HH   128
#define WW   128
#define PP   (HH*WW)       // 16384
#define C1c  48
#define C0c  16
#define CMc  16
#define BATCH 64           // NB * CMc
#define JW   65
#define P65  (128*JW)      // 8320

// ---------------- device scratch (no allocation allowed) ----------------
static __device__ float2 gf_chrp1[255];
static __device__ float2 gf_E[509];
static __device__ float  gf_S[509];
static __device__ float2 gf_fac[128];

static __device__ float2  g_M   [128*128];
static __device__ float2  g_Cm  [128*128];
static __device__ float2  g_Minv[128*128];
static __device__ float2  g_Fh  [128*128];
static __device__ float2  g_Fhi [128*128];
static __device__ float2  g_Fw  [JW*128];
static __device__ float2  g_Bw  [JW*128];

static __device__ float   g_W2[256];      // magw @ magf
static __device__ float   g_b2[16];       // magw @ magf_b + mag_b
static __device__ float   g_Wc[192*16];   // conv2[:, :16] @ conv0_w
static __device__ float   g_bc[192];      // conv2[:, :16] @ conv0_b

static __device__ float   g_x1 [NB*C1c*PP];
static __device__ float2  g_T  [BATCH*128*128];
static __device__ float2  g_F  [BATCH*128*128];
static __device__ float   g_mag[BATCH*PP];
static __device__ float   g_pha[BATCH*PP];
static __device__ float   g_magout[BATCH*PP];
static __device__ float2  g_T65[BATCH*P65];
static __device__ float2  g_F65[BATCH*P65];
static __device__ float   g_fm[BATCH*P65];
static __device__ float   g_fp[BATCH*P65];
static __device__ float   g_cat[NB*C1c*PP];   // ch 16..47 used

// ---------------- merged table + DFT construction ----------------
__global__ void k_setup() {
    int t = threadIdx.x;
    const double PI = 3.14159265358979323846;
    if (blockIdx.x == 0) {
        double tana2 = tan(PI / 8.0);
        double sina  = sin(PI / 4.0);
        double coef  = tana2 / 512.0;
        double ec    = 1.0 / (512.0 * sina);
        for (int j = t; j < 255; j += 256) {
            double n = (double)(j - 127);
            double s, c; sincospi(-coef * n * n, &s, &c);
            gf_chrp1[j] = make_float2((float)c, (float)s);
        }
        double amp = sqrt(1.0 / (512.0 * sina));
        double ps, pc; sincospi(-0.125, &ps, &pc);
        for (int r = t; r < 128; r += 256) {
            double n = 2.0 * r - 127.0;
            double s, c; sincospi(-coef * n * n, &s, &c);
            gf_fac[r] = make_float2((float)(amp * (pc * c - ps * s)),
                                    (float)(amp * (pc * s + ps * c)));
        }
        for (int i = t; i < 509; i += 256) {
            double d = (double)(i - 254);
            double s, c; sincospi(ec * d * d, &s, &c);
            gf_E[i] = make_float2((float)c, (float)s);
            int m = i - 254;
            double sv;
            if (m == 0) sv = 1.0;
            else if ((m & 1) == 0) sv = 0.0;
            else {
                double x = 0.5 * (double)m;
                sv = sinpi(x) / (PI * x);
            }
            gf_S[i] = (float)sv;
        }
    }
    int idx = blockIdx.x * 256 + t;
    if (idx < 128 * 128) {
        int u = idx >> 7, v = idx & 127;
        int e1 = ((u + 64) * (v + 64)) & 127;
        double s, c; sincospi(2.0 * e1 / 128.0, &s, &c);
        double inv = 1.0 / sqrt(128.0);
        g_Cm[idx] = make_float2((float)(c * inv), (float)(s * inv));
        int e2 = (u * v) & 127;
        double s2, c2; sincospi(-2.0 * e2 / 128.0, &s2, &c2);
        g_Fh[idx] = make_float2((float)c2, (float)s2);
        double s3, c3; sincospi(2.0 * e2 / 128.0, &s3, &c3);
        g_Fhi[idx] = make_float2((float)(c3 / 128.0), (float)(s3 / 128.0));
    }
    if (idx < JW * 128) {
        int k = idx / 128, w = idx & 127;
        int e = (k * w) & 127;
        double s, c; sincospi(-2.0 * e / 128.0, &s, &c);
        g_Fw[idx] = make_float2((float)c, (float)s);
        float2 bw;
        if (k == 0)       bw = make_float2(1.0f / 128.0f, 0.f);
        else if (k == 64) bw = make_float2(((w & 1) ? -1.0f : 1.0f) / 128.0f, 0.f);
        else {
            double s4, c4; sincospi(2.0 * e / 128.0, &s4, &c4);
            bw = make_float2((float)(c4 * 2.0 / 128.0), (float)(s4 * 2.0 / 128.0));
        }
        g_Bw[idx] = bw;
    }
}

__global__ void k_buildM() {
    int idx = blockIdx.x * 256 + threadIdx.x;
    if (idx >= 128 * 128) return;
    int r = idx >> 7, k = idx & 127;
    float ax = 0.f, ay = 0.f;
    {
        int j = 2 * k;
        float2 c1 = gf_chrp1[j];
        float2 e  = gf_E[2 * r - j + 254];
        ax += c1.x * e.x - c1.y * e.y;
        ay += c1.x * e.y + c1.y * e.x;
    }
    for (int j = 1; j < 255; j += 2) {
        float s = gf_S[j - 2 * k + 254];
        float2 c1 = gf_chrp1[j];
        float2 e  = gf_E[2 * r - j + 254];
        ax += (c1.x * e.x - c1.y * e.y) * s;
        ay += (c1.x * e.y + c1.y * e.x) * s;
    }
    float2 f = gf_fac[r];
    g_M[idx] = make_float2(f.x * ax - f.y * ay, f.x * ay + f.y * ax);
}

// K-split x4: 128 blocks x 512 threads
__global__ void __launch_bounds__(512) k_buildMinv() {
    __shared__ float2 sM[128];
    __shared__ float2 sP[512];
    int r = blockIdx.x;
    int t = threadIdx.x, v = t & 127, seg = t >> 7;
    if (t < 128) sM[t] = g_M[r * 128 + t];
    __syncthreads();
    float ax = 0.f, ay = 0.f;
    int u0 = seg * 32;
#pragma unroll 8
    for (int u = u0; u < u0 + 32; u++) {
        float2 a = sM[u];
        float2 b = g_Cm[u * 128 + v];
        ax += a.x * b.x - a.y * b.y;
        ay += a.x * b.y + a.y * b.x;
    }
    sP[t] = make_float2(ax, ay);
    __syncthreads();
    if (t < 128) {
        float2 p0 = sP[t], p1 = sP[t + 128], p2 = sP[t + 256], p3 = sP[t + 384];
        g_Minv[r * 128 + v] = make_float2(p0.x + p1.x + p2.x + p3.x,
                                          p0.y + p1.y + p2.y + p3.y);
    }
}

// merged weight folding: blocks 0..11 -> Wc/bc, block 12 -> W2/b2
__global__ void k_fold(const float* __restrict__ conv2w, const float* __restrict__ conv0w,
                       const float* __restrict__ conv0b,
                       const float* __restrict__ magw, const float* __restrict__ magf,
                       const float* __restrict__ magfb, const float* __restrict__ magb) {
    if (blockIdx.x < 12) {
        int idx = blockIdx.x * 256 + threadIdx.x;
        if (idx < 192 * 16) {
            int o = idx >> 4, c = idx & 15;
            float a = 0.f;
#pragma unroll
            for (int m = 0; m < 16; m++) a += conv2w[o * 48 + m] * conv0w[m * 16 + c];
            g_Wc[idx] = a;
        }
        if (idx < 192) {
            float b = 0.f;
#pragma unroll
            for (int m = 0; m < 16; m++) b += conv2w[idx * 48 + m] * conv0b[m];
            g_bc[idx] = b;
        }
    } else {
        int t = threadIdx.x;
        int o = t >> 4, c = t & 15;
        float a = 0.f;
#pragma unroll
        for (int m = 0; m < 16; m++) a += magw[o * 16 + m] * magf[m * 16 + c];
        g_W2[t] = a;
        if (t < 16) {
            float b = magb[t];
#pragma unroll
            for (int m = 0; m < 16; m++) b += magw[t * 16 + m] * magfb[m];
            g_b2[t] = b;
        }
    }
}

// ---------------- generic 1x1 conv (GEMM) — used for conv1 ----------------
__global__ void __launch_bounds__(128)
k_g1x1(const float* __restrict__ X, const float* __restrict__ Wt,
       float* __restrict__ Y, int Cc, int P, int xStrideN, int yStrideN) {
    __shared__ float sW[16 * 192];
    int n = blockIdx.z, ob = blockIdx.y * 16;
    int tx = threadIdx.x;
    for (int e = tx; e < 16 * Cc; e += 128) sW[e] = Wt[ob * Cc + e];
    __syncthreads();
    const float* Xn = X + (size_t)n * xStrideN;
    int pb = blockIdx.x * 512;
    float acc[16][4];
#pragma unroll
    for (int o = 0; o < 16; o++)
#pragma unroll
        for (int s = 0; s < 4; s++) acc[o][s] = 0.f;
#pragma unroll 4
    for (int c = 0; c < Cc; c++) {
        float xv[4];
#pragma unroll
        for (int s = 0; s < 4; s++)
            xv[s] = Xn[(size_t)c * P + pb + s * 128 + tx];
#pragma unroll
        for (int o = 0; o < 16; o++) {
            float w = sW[o * Cc + c];
#pragma unroll
            for (int s = 0; s < 4; s++) acc[o][s] += w * xv[s];
        }
    }
#pragma unroll
    for (int o = 0; o < 16; o++)
#pragma unroll
        for (int s = 0; s < 4; s++)
            Y[(size_t)n * yStrideN + (size_t)(ob + o) * P + pb + s * 128 + tx] = acc[o][s];
}

// ---------------- conv2 with folded conv_0 branch ----------------
__global__ void __launch_bounds__(128)
k_conv2(const float* __restrict__ X1, const float* __restrict__ Cat,
        const float* __restrict__ conv2w, float* __restrict__ Y) {
    __shared__ float sWa[16 * 16];
    __shared__ float sWb[16 * 32];
    __shared__ float sB[16];
    int n = blockIdx.z, ob = blockIdx.y * 16;
    int tx = threadIdx.x;
    for (int e = tx; e < 256; e += 128)
        sWa[e] = g_Wc[(ob + (e >> 4)) * 16 + (e & 15)];
    for (int e = tx; e < 512; e += 128) {
        int o = e >> 5, c = e & 31;
        sWb[e] = conv2w[(ob + o) * 48 + 16 + c];
    }
    if (tx < 16) sB[tx] = g_bc[ob + tx];
    __syncthreads();
    const float* Xn = X1 + (size_t)n * 48 * PP;
    const float* Cn = Cat + (size_t)n * 48 * PP + (size_t)16 * PP;
    int pb = blockIdx.x * 512;
    float acc[16][4];
#pragma unroll
    for (int o = 0; o < 16; o++)
#pragma unroll
        for (int s = 0; s < 4; s++) acc[o][s] = 0.f;
#pragma unroll 4
    for (int c = 0; c < 16; c++) {
        float xv[4];
#pragma unroll
        for (int s = 0; s < 4; s++)
            xv[s] = Xn[(size_t)c * PP + pb + s * 128 + tx];
#pragma unroll
        for (int o = 0; o < 16; o++) {
            float w = sWa[o * 16 + c];
#pragma unroll
            for (int s = 0; s < 4; s++) acc[o][s] += w * xv[s];
        }
    }
#pragma unroll 4
    for (int c = 0; c < 32; c++) {
        float xv[4];
#pragma unroll
        for (int s = 0; s < 4; s++)
            xv[s] = Cn[(size_t)c * PP + pb + s * 128 + tx];
#pragma unroll
        for (int o = 0; o < 16; o++) {
            float w = sWb[o * 32 + c];
#pragma unroll
            for (int s = 0; s < 4; s++) acc[o][s] += w * xv[s];
        }
    }
#pragma unroll
    for (int o = 0; o < 16; o++)
#pragma unroll
        for (int s = 0; s < 4; s++)
            Y[(size_t)n * 192 * PP + (size_t)(ob + o) * PP + pb + s * 128 + tx] =
                acc[o][s] + sB[o];
}

// ---------------- 64x64-tile complex GEMMs (double-buffered) --------------
__global__ void __launch_bounds__(256)
k_rxMT64(const float* __restrict__ Xb, int cPerN, int cOff,
         const float2* __restrict__ M, float2* __restrict__ Y, int J) {
    __shared__ float  sA[2][64][17];
    __shared__ float2 sB[2][16][65];
    int b = blockIdx.z;
    const float* X = Xb + (size_t)((b >> 4) * cPerN + cOff + (b & 15)) * PP;
    int j0 = blockIdx.x * 64, i0 = blockIdx.y * 64;
    int tid = threadIdx.x;
    int tx = tid & 15, ty = tid >> 4;
    float2 acc[4][4];
#pragma unroll
    for (int a = 0; a < 4; a++)
#pragma unroll
        for (int c = 0; c < 4; c++) acc[a][c] = make_float2(0.f, 0.f);
    float  ra[4]; float2 rb[4];
#pragma unroll
    for (int s = 0; s < 4; s++) {
        int e = tid + s * 256; int r = e >> 4, c = e & 15;
        ra[s] = X[(i0 + r) * 128 + c];
        rb[s] = (j0 + r < J) ? M[(j0 + r) * 128 + c] : make_float2(0.f, 0.f);
    }
#pragma unroll
    for (int s = 0; s < 4; s++) {
        int e = tid + s * 256; int r = e >> 4, c = e & 15;
        sA[0][r][c] = ra[s]; sB[0][c][r] = rb[s];
    }
    __syncthreads();
    for (int ch = 0; ch < 8; ch++) {
        if (ch < 7) {
            int kt = (ch + 1) * 16;
#pragma unroll
            for (int s = 0; s < 4; s++) {
                int e = tid + s * 256; int r = e >> 4, c = e & 15;
                ra[s] = X[(i0 + r) * 128 + kt + c];
                rb[s] = (j0 + r < J) ? M[(j0 + r) * 128 + kt + c] : make_float2(0.f, 0.f);
            }
        }
        int pb = ch & 1;
#pragma unroll
        for (int kk = 0; kk < 16; kk++) {
            float av[4]; float2 bv[4];
#pragma unroll
            for (int ii = 0; ii < 4; ii++) av[ii] = sA[pb][ty * 4 + ii][kk];
#pragma unroll
            for (int jj = 0; jj < 4; jj++) bv[jj] = sB[pb][kk][tx * 4 + jj];
#pragma unroll
            for (int ii = 0; ii < 4; ii++)
#pragma unroll
                for (int jj = 0; jj < 4; jj++) {
                    acc[ii][jj].x += av[ii] * bv[jj].x;
                    acc[ii][jj].y += av[ii] * bv[jj].y;
                }
        }
        if (ch < 7) {
            int nb = (ch + 1) & 1;
#pragma unroll
            for (int s = 0; s < 4; s++) {
                int e = tid + s * 256; int r = e >> 4, c = e & 15;
                sA[nb][r][c] = ra[s]; sB[nb][c][r] = rb[s];
            }
            __syncthreads();
        }
    }
#pragma unroll
    for (int ii = 0; ii < 4; ii++)
#pragma unroll
        for (int jj = 0; jj < 4; jj++) {
            int j = j0 + tx * 4 + jj;
            if (j < J)
                Y[((size_t)b * 128 + i0 + ty * 4 + ii) * J + j] = acc[ii][jj];
        }
}

__global__ void __launch_bounds__(256)
k_cMT64(const float2* __restrict__ Xc, const float2* __restrict__ M,
        float2* __restrict__ Y, int J) {
    __shared__ float2 sA[2][64][17];
    __shared__ float2 sB[2][16][65];
    int b = blockIdx.z;
    const float2* X = Xc + (size_t)b * 128 * 128;
    int j0 = blockIdx.x * 64, i0 = blockIdx.y * 64;
    int tid = threadIdx.x;
    int tx = tid & 15, ty = tid >> 4;
    float2 acc[4][4];
#pragma unroll
    for (int a = 0; a < 4; a++)
#pragma unroll
        for (int c = 0; c < 4; c++) acc[a][c] = make_float2(0.f, 0.f);
    float2 ra[4], rb[4];
#pragma unroll
    for (int s = 0; s < 4; s++) {
        int e = tid + s * 256; int r = e >> 4, c = e & 15;
        ra[s] = X[(i0 + r) * 128 + c];
        rb[s] = (j0 + r < J) ? M[(j0 + r) * 128 + c] : make_float2(0.f, 0.f);
    }
#pragma unroll
    for (int s = 0; s < 4; s++) {
        int e = tid + s * 256; int r = e >> 4, c = e & 15;
        sA[0][r][c] = ra[s]; sB[0][c][r] = rb[s];
    }
    __syncthreads();
    for (int ch = 0; ch < 8; ch++) {
        if (ch < 7) {
            int kt = (ch + 1) * 16;
#pragma unroll
            for (int s = 0; s < 4; s++) {
                int e = tid + s * 256; int r = e >> 4, c = e & 15;
                ra[s] = X[(i0 + r) * 128 + kt + c];
                rb[s] = (j0 + r < J) ? M[(j0 + r) * 128 + kt + c] : make_float2(0.f, 0.f);
            }
        }
        int pb = ch & 1;
#pragma unroll
        for (int kk = 0; kk < 16; kk++) {
            float2 av[4]; float2 bv[4];
#pragma unroll
            for (int ii = 0; ii < 4; ii++) av[ii] = sA[pb][ty * 4 + ii][kk];
#pragma unroll
            for (int jj = 0; jj < 4; jj++) bv[jj] = sB[pb][kk][tx * 4 + jj];
#pragma unroll
            for (int ii = 0; ii < 4; ii++)
#pragma unroll
                for (int jj = 0; jj < 4; jj++) {
                    acc[ii][jj].x += av[ii].x * bv[jj].x - av[ii].y * bv[jj].y;
                    acc[ii][jj].y += av[ii].x * bv[jj].y + av[ii].y * bv[jj].x;
                }
        }
        if (ch < 7) {
            int nb = (ch + 1) & 1;
#pragma unroll
            for (int s = 0; s < 4; s++) {
                int e = tid + s * 256; int r = e >> 4, c = e & 15;
                sA[nb][r][c] = ra[s]; sB[nb][c][r] = rb[s];
            }
            __syncthreads();
        }
    }
#pragma unroll
    for (int ii = 0; ii < 4; ii++)
#pragma unroll
        for (int jj = 0; jj < 4; jj++) {
            int j = j0 + tx * 4 + jj;
            if (j < J)
                Y[((size_t)b * 128 + i0 + ty * 4 + ii) * J + j] = acc[ii][jj];
        }
}

// MODE 0: complex Y ; MODE 1: o1=mag, o2=pha ; MODE 2: |.| into cat ch16..31
template <int MODE>
__global__ void __launch_bounds__(256)
k_MxX64(const float2* __restrict__ M, const float2* __restrict__ Xc,
        float2* __restrict__ Y, float* __restrict__ o1, float* __restrict__ o2,
        int J) {
    __shared__ float2 sA[2][64][17];
    __shared__ float2 sB[2][16][65];
    int b = blockIdx.z;
    const float2* X = Xc + (size_t)b * 128 * J;
    int j0 = blockIdx.x * 64, i0 = blockIdx.y * 64;
    int tid = threadIdx.x;
    int tx = tid & 15, ty = tid >> 4;
    float2 acc[4][4];
#pragma unroll
    for (int a = 0; a < 4; a++)
#pragma unroll
        for (int c = 0; c < 4; c++) acc[a][c] = make_float2(0.f, 0.f);
    float2 ra[4], rb[4];
#pragma unroll
    for (int s = 0; s < 4; s++) {
        int e = tid + s * 256;
        int r = e >> 4, c = e & 15;
        ra[s] = M[(i0 + r) * 128 + c];
        int r2 = e >> 6, c2 = e & 63;
        rb[s] = (j0 + c2 < J) ? X[(size_t)r2 * J + j0 + c2] : make_float2(0.f, 0.f);
    }
#pragma unroll
    for (int s = 0; s < 4; s++) {
        int e = tid + s * 256;
        int r = e >> 4, c = e & 15;
        sA[0][r][c] = ra[s];
        int r2 = e >> 6, c2 = e & 63;
        sB[0][r2][c2] = rb[s];
    }
    __syncthreads();
    for (int ch = 0; ch < 8; ch++) {
        if (ch < 7) {
            int kt = (ch + 1) * 16;
#pragma unroll
            for (int s = 0; s < 4; s++) {
                int e = tid + s * 256;
                int r = e >> 4, c = e & 15;
                ra[s] = M[(i0 + r) * 128 + kt + c];
                int r2 = e >> 6, c2 = e & 63;
                rb[s] = (j0 + c2 < J) ? X[(size_t)(kt + r2) * J + j0 + c2]
                                      : make_float2(0.f, 0.f);
            }
        }
        int pb = ch & 1;
#pragma unroll
        for (int kk = 0; kk < 16; kk++) {
            float2 av[4]; float2 bv[4];
#pragma unroll
            for (int ii = 0; ii < 4; ii++) av[ii] = sA[pb][ty * 4 + ii][kk];
#pragma unroll
            for (int jj = 0; jj < 4; jj++) bv[jj] = sB[pb][kk][tx * 4 + jj];
#pragma unroll
            for (int ii = 0; ii < 4; ii++)
#pragma unroll
                for (int jj = 0; jj < 4; jj++) {
                    acc[ii][jj].x += av[ii].x * bv[jj].x - av[ii].y * bv[jj].y;
                    acc[ii][jj].y += av[ii].x * bv[jj].y + av[ii].y * bv[jj].x;
                }
        }
        if (ch < 7) {
            int nb = (ch + 1) & 1;
#pragma unroll
            for (int s = 0; s < 4; s++) {
                int e = tid + s * 256;
                int r = e >> 4, c = e & 15;
                sA[nb][r][c] = ra[s];
                int r2 = e >> 6, c2 = e & 63;
                sB[nb][r2][c2] = rb[s];
            }
            __syncthreads();
        }
    }
#pragma unroll
    for (int ii = 0; ii < 4; ii++)
#pragma unroll
        for (int jj = 0; jj < 4; jj++) {
            int i = i0 + ty * 4 + ii;
            int j = j0 + tx * 4 + jj;
            if (j >= J) continue;
            float2 v = acc[ii][jj];
            if (MODE == 0) {
                Y[((size_t)b * 128 + i) * J + j] = v;
            } else if (MODE == 1) {
                size_t idx = ((size_t)b * 128 + i) * J + j;
                float m = sqrtf(v.x * v.x + v.y * v.y);
                o1[idx] = m;
                o2[idx] = atan2f(v.y, v.x);
            } else {
                int n = b >> 4, c = b & 15;
                o1[(size_t)(n * C1c + 16 + c) * PP + i * 128 + j] =
                    sqrtf(v.x * v.x + v.y * v.y);
            }
        }
}

// x_1o = Re(T3 @ Bw) -> cat ch 32..47
__global__ void k_irfft_w(const float2* __restrict__ T3, float* __restrict__ Ybase) {
    int b = blockIdx.z;
    int tx = threadIdx.x, ty = threadIdx.y;
    int hbase = blockIdx.y * 16;
    float acc[4] = {0.f, 0.f, 0.f, 0.f};
    for (int k = 0; k < JW; k++) {
        float2 bw = g_Bw[k * 128 + tx];
#pragma unroll
        for (int s = 0; s < 4; s++) {
            float2 a = T3[((size_t)b * 128 + hbase + ty * 4 + s) * JW + k];
            acc[s] += a.x * bw.x - a.y * bw.y;
        }
    }
    int n = b >> 4, c = b & 15;
    float* Yp = Ybase + (size_t)(n * C1c + 32 + c) * PP;
#pragma unroll
    for (int s = 0; s < 4; s++)
        Yp[(hbase + ty * 4 + s) * WW + tx] = acc[s];
}

// ---------------- 3x3 masked conv, fused with magw ----------------
__global__ void __launch_bounds__(256)
k_conv3m(const float* __restrict__ X, const float* __restrict__ Wt,
         const float* __restrict__ Bs, const float* __restrict__ MagW,
         const float* __restrict__ MagB, float* __restrict__ Y) {
    __shared__ float sW[CMc * CMc * 9];
    __shared__ float sMW[256];
    __shared__ float sSB[16];
    __shared__ float sMB[16];
    __shared__ float sT[10][34];
    int tid = threadIdx.y * 32 + threadIdx.x;
    for (int e = tid; e < CMc * CMc * 9; e += 256) sW[e] = Wt[e];
    if (tid < 256) sMW[tid] = MagW[tid];
    if (tid < 16) { sSB[tid] = Bs[tid]; sMB[tid] = MagB[tid]; }
    int n = blockIdx.z;
    int wb = blockIdx.x * 32, hb = 16 + blockIdx.y * 8;
    const float* Xn = X + (size_t)n * CMc * PP;
    float acc[CMc];
#pragma unroll
    for (int o = 0; o < CMc; o++) acc[o] = 0.f;
    for (int c = 0; c < CMc; c++) {
        __syncthreads();
        for (int e = tid; e < 340; e += 256) {
            int ly = e / 34, lx = e % 34;
            int gy = hb - 1 + ly, gx = wb - 1 + lx;
            float v = 0.f;
            if (gy >= 19 && gy < 109 && gx >= 19 && gx < 109)
                v = Xn[(size_t)c * PP + gy * WW + gx];
            sT[ly][lx] = v;
        }
        __syncthreads();
#pragma unroll
        for (int kh = 0; kh < 3; kh++)
#pragma unroll
            for (int kw = 0; kw < 3; kw++) {
                float xv = sT[threadIdx.y + kh][threadIdx.x + kw];
#pragma unroll
                for (int o = 0; o < CMc; o++)
                    acc[o] += sW[(o * CMc + c) * 9 + kh * 3 + kw] * xv;
            }
    }
    int h = hb + threadIdx.y, w = wb + threadIdx.x;
    if (h >= 19 && h < 109 && w >= 19 && w < 109) {
#pragma unroll
        for (int m = 0; m < CMc; m++) acc[m] += sSB[m];
        float* Yn = Y + (size_t)n * CMc * PP;
#pragma unroll
        for (int o = 0; o < CMc; o++) {
            float s = sMB[o];
#pragma unroll
            for (int m = 0; m < CMc; m++) s += sMW[o * 16 + m] * acc[m];
            Yn[(size_t)o * PP + h * WW + w] = s;
        }
    }
}

// ---------------- fused pha-mix + mag-outside + makec (1 px/thread) -------
__global__ void __launch_bounds__(128)
k_phamc(const float* __restrict__ Pha, const float* __restrict__ Mag,
        const float* __restrict__ MagO, const float* __restrict__ PhaW,
        const float* __restrict__ PhaB, float2* __restrict__ F) {
    __shared__ float sPW[256];
    __shared__ float sW2[256];
    __shared__ float sPB[16];
    __shared__ float sB2[16];
    int t = threadIdx.x;
    sPW[t] = PhaW[t]; sPW[t + 128] = PhaW[t + 128];
    sW2[t] = g_W2[t]; sW2[t + 128] = g_W2[t + 128];
    if (t < 16)  { sPB[t] = PhaB[t]; sB2[t] = g_b2[t]; }
    __syncthreads();
    int n = blockIdx.y;
    int p = blockIdx.x * 128 + t;
    int h = p >> 7, w = p & 127;
    bool inside = (h >= 19 && h < 109 && w >= 19 && w < 109);
    size_t base = (size_t)n * 16 * PP;
    float ph[16], mg[16];
#pragma unroll
    for (int c = 0; c < 16; c++) ph[c] = Pha[base + (size_t)c * PP + p];
    if (!inside) {
#pragma unroll
        for (int c = 0; c < 16; c++) mg[c] = Mag[base + (size_t)c * PP + p];
    }
#pragma unroll
    for (int o = 0; o < 16; o++) {
        float po = sPB[o];
#pragma unroll
        for (int c = 0; c < 16; c++) po += sPW[o * 16 + c] * ph[c];
        float m;
        if (inside) {
            m = MagO[base + (size_t)o * PP + p];
        } else {
            m = sB2[o];
#pragma unroll
            for (int c = 0; c < 16; c++) m += sW2[o * 16 + c] * mg[c];
        }
        float sn, cs;
        __sincosf(po, &sn, &cs);
        F[base + (size_t)o * PP + p] = make_float2(m * cs, m * sn);
    }
}

// ---------------- fused rfft mag/pha mix + makec (1 px/thread) ------------
__global__ void __launch_bounds__(128)
k_fmfp(const float* __restrict__ Fm, const float* __restrict__ Fp,
       const float* __restrict__ W, const float* __restrict__ B,
       float2* __restrict__ F) {
    __shared__ float sW[256];
    __shared__ float sB[16];
    int t = threadIdx.x;
    sW[t] = W[t]; sW[t + 128] = W[t + 128];
    if (t < 16)  sB[t] = B[t];
    __syncthreads();
    int n = blockIdx.y;
    int p = blockIdx.x * 128 + t;
    if (p >= P65) return;
    size_t base = (size_t)n * 16 * P65;
    float fm[16], fp[16];
#pragma unroll
    for (int c = 0; c < 16; c++) {
        fm[c] = Fm[base + (size_t)c * P65 + p];
        fp[c] = Fp[base + (size_t)c * P65 + p];
    }
#pragma unroll
    for (int o = 0; o < 16; o++) {
        float mo = sB[o], po = sB[o];
#pragma unroll
        for (int c = 0; c < 16; c++) {
            mo += sW[o * 16 + c] * fm[c];
            po += sW[o * 16 + c] * fp[c];
        }
        float sn, cs;
        __sincosf(po, &sn, &cs);
        F[base + (size_t)o * P65 + p] = make_float2(mo * cs, mo * sn);
    }
}

// ---------------- launch ----------------
extern "C" void kernel_launch(void* const* d_in, const int* in_sizes, int n_in,
                              void* d_out, int out_size) {
    const float* x        = (const float*)d_in[0];
    const float* conv1_w  = (const float*)d_in[1];
    const float* mag_s_w  = (const float*)d_in[2];
    const float* mag_s_b  = (const float*)d_in[3];
    const float* mag_f_w  = (const float*)d_in[4];
    const float* mag_f_b  = (const float*)d_in[5];
    const float* mag_w    = (const float*)d_in[6];
    const float* mag_b    = (const float*)d_in[7];
    const float* pha_w    = (const float*)d_in[8];
    const float* pha_b    = (const float*)d_in[9];
    const float* conv_0_w = (const float*)d_in[10];
    const float* conv_0_b = (const float*)d_in[11];
    const float* conv_1_w = (const float*)d_in[12];
    const float* conv_1_b = (const float*)d_in[13];
    const float* conv2_w  = (const float*)d_in[14];
    float* out = (float*)d_out;

    float  *px1, *pmag, *ppha, *pmagout, *pfm, *pfp, *pcat;
    float2 *pM, *pMinv, *pFh, *pFhi, *pFw, *pT, *pF, *pT65, *pF65;
    cudaGetSymbolAddress((void**)&px1,    g_x1);
    cudaGetSymbolAddress((void**)&pmag,   g_mag);
    cudaGetSymbolAddress((void**)&ppha,   g_pha);
    cudaGetSymbolAddress((void**)&pmagout,g_magout);
    cudaGetSymbolAddress((void**)&pfm,    g_fm);
    cudaGetSymbolAddress((void**)&pfp,    g_fp);
    cudaGetSymbolAddress((void**)&pcat,   g_cat);
    cudaGetSymbolAddress((void**)&pM,     g_M);
    cudaGetSymbolAddress((void**)&pMinv,  g_Minv);
    cudaGetSymbolAddress((void**)&pFh,    g_Fh);
    cudaGetSymbolAddress((void**)&pFhi,   g_Fhi);
    cudaGetSymbolAddress((void**)&pFw,    g_Fw);
    cudaGetSymbolAddress((void**)&pT,     g_T);
    cudaGetSymbolAddress((void**)&pF,     g_F);
    cudaGetSymbolAddress((void**)&pT65,   g_T65);
    cudaGetSymbolAddress((void**)&pF65,   g_F65);

    // constant matrices + folded weights
    k_setup<<<64, 256>>>();
    k_buildM<<<64, 256>>>();
    k_buildMinv<<<128, 512>>>();
    k_fold<<<13, 256>>>(conv2_w, conv_0_w, conv_0_b, mag_w, mag_f_w, mag_f_b, mag_b);

    // conv1: 192 -> 48
    k_g1x1<<<dim3(32, 3, NB), 128>>>(x, conv1_w, px1, 192, PP, 192 * PP, 48 * PP);

    // ---- FRFT forward: Fre = M @ X @ M^T  (x_05 = channels 16..31) ----
    k_rxMT64<<<dim3(2, 2, BATCH), 256>>>(px1, C1c, 16, pM, pT, 128);
    k_MxX64<1><<<dim3(2, 2, BATCH), 256>>>(pM, pT, nullptr, pmag, ppha, 128);

    // mag path: conv3 + magw fused (inside); pha mix + outside mag + makec fused
    k_conv3m<<<dim3(4, 12, NB), dim3(32, 8)>>>(pmag, mag_s_w, mag_s_b, mag_w, mag_b, pmagout);
    k_phamc<<<dim3(128, NB), 128>>>(ppha, pmag, pmagout, pha_w, pha_b, pF);

    // ---- FRFT inverse: |Minv @ FreOut @ Minv^T| -> cat ch16..31 ----
    k_cMT64<<<dim3(2, 2, BATCH), 256>>>(pF, pMinv, pT, 128);
    k_MxX64<2><<<dim3(2, 2, BATCH), 256>>>(pMinv, pT, nullptr, pcat, nullptr, 128);

    // ---- rfft2 branch (x_1 = channels 32..47) ----
    k_rxMT64<<<dim3(2, 2, BATCH), 256>>>(px1, C1c, 32, pFw, pT65, JW);
    k_MxX64<1><<<dim3(2, 2, BATCH), 256>>>(pFh, pT65, nullptr, pfm, pfp, JW);
    k_fmfp<<<dim3(65, NB), 128>>>(pfm, pfp, conv_1_w, conv_1_b, pF65);
    k_MxX64<0><<<dim3(2, 2, BATCH), 256>>>(pFhi, pF65, pT65, nullptr, nullptr, JW);
    k_irfft_w<<<dim3(1, 8, BATCH), dim3(128, 4)>>>(pT65, pcat);

    // ---- conv2 (conv_0 folded in): 48 -> 192 ----
    k_conv2<<<dim3(32, 12, NB), 128>>>(px1, pcat, conv2_w, out);
}

// round 10
// speedup vs baseline: 1.9949x; 1.0123x over previous
#include <cuda_runtime.h>
#include <math.h>

#define NB   4
#define CIN  192
#define HH   128
#define WW   128
#define PP   (HH*WW)       // 16384
#define C1c  48
#define C0c  16
#define CMc  16
#define BATCH 64           // NB * CMc
#define JW   65
#define P65  (128*JW)      // 8320

// ---------------- device scratch (no allocation allowed) ----------------
static __device__ float2 gf_chrp1[255];
static __device__ float2 gf_E[509];
static __device__ float  gf_S[509];
static __device__ float2 gf_fac[128];

static __device__ float2  g_M   [128*128];
static __device__ float2  g_Cm  [128*128];
static __device__ float2  g_Minv[128*128];
static __device__ float2  g_Fh  [128*128];
static __device__ float2  g_Fhi [128*128];
static __device__ float2  g_Fw  [JW*128];
static __device__ float2  g_Bw  [JW*128];

static __device__ float   g_W2[256];      // magw @ magf
static __device__ float   g_b2[16];       // magw @ magf_b + mag_b
static __device__ float   g_Wc[192*16];   // conv2[:, :16] @ conv0_w
static __device__ float   g_bc[192];      // conv2[:, :16] @ conv0_b

static __device__ float   g_x1 [NB*C1c*PP];
static __device__ float2  g_T  [BATCH*128*128];
static __device__ float2  g_F  [BATCH*128*128];
static __device__ float   g_mag[BATCH*PP];
static __device__ float   g_pha[BATCH*PP];
static __device__ float   g_magout[BATCH*PP];
static __device__ float2  g_T65[BATCH*P65];
static __device__ float2  g_F65[BATCH*P65];
static __device__ float   g_fm[BATCH*P65];
static __device__ float   g_fp[BATCH*P65];
static __device__ float   g_cat[NB*C1c*PP];   // ch 16..47 used

// ---------------- merged table + DFT construction ----------------
__global__ void k_setup() {
    int t = threadIdx.x;
    const double PI = 3.14159265358979323846;
    if (blockIdx.x == 0) {
        double tana2 = tan(PI / 8.0);
        double sina  = sin(PI / 4.0);
        double coef  = tana2 / 512.0;
        double ec    = 1.0 / (512.0 * sina);
        for (int j = t; j < 255; j += 256) {
            double n = (double)(j - 127);
            double s, c; sincospi(-coef * n * n, &s, &c);
            gf_chrp1[j] = make_float2((float)c, (float)s);
        }
        double amp = sqrt(1.0 / (512.0 * sina));
        double ps, pc; sincospi(-0.125, &ps, &pc);
        for (int r = t; r < 128; r += 256) {
            double n = 2.0 * r - 127.0;
            double s, c; sincospi(-coef * n * n, &s, &c);
            gf_fac[r] = make_float2((float)(amp * (pc * c - ps * s)),
                                    (float)(amp * (pc * s + ps * c)));
        }
        for (int i = t; i < 509; i += 256) {
            double d = (double)(i - 254);
            double s, c; sincospi(ec * d * d, &s, &c);
            gf_E[i] = make_float2((float)c, (float)s);
            int m = i - 254;
            double sv;
            if (m == 0) sv = 1.0;
            else if ((m & 1) == 0) sv = 0.0;
            else {
                double x = 0.5 * (double)m;
                sv = sinpi(x) / (PI * x);
            }
            gf_S[i] = (float)sv;
        }
    }
    int idx = blockIdx.x * 256 + t;
    if (idx < 128 * 128) {
        int u = idx >> 7, v = idx & 127;
        int e1 = ((u + 64) * (v + 64)) & 127;
        double s, c; sincospi(2.0 * e1 / 128.0, &s, &c);
        double inv = 1.0 / sqrt(128.0);
        g_Cm[idx] = make_float2((float)(c * inv), (float)(s * inv));
        int e2 = (u * v) & 127;
        double s2, c2; sincospi(-2.0 * e2 / 128.0, &s2, &c2);
        g_Fh[idx] = make_float2((float)c2, (float)s2);
        double s3, c3; sincospi(2.0 * e2 / 128.0, &s3, &c3);
        g_Fhi[idx] = make_float2((float)(c3 / 128.0), (float)(s3 / 128.0));
    }
    if (idx < JW * 128) {
        int k = idx / 128, w = idx & 127;
        int e = (k * w) & 127;
        double s, c; sincospi(-2.0 * e / 128.0, &s, &c);
        g_Fw[idx] = make_float2((float)c, (float)s);
        float2 bw;
        if (k == 0)       bw = make_float2(1.0f / 128.0f, 0.f);
        else if (k == 64) bw = make_float2(((w & 1) ? -1.0f : 1.0f) / 128.0f, 0.f);
        else {
            double s4, c4; sincospi(2.0 * e / 128.0, &s4, &c4);
            bw = make_float2((float)(c4 * 2.0 / 128.0), (float)(s4 * 2.0 / 128.0));
        }
        g_Bw[idx] = bw;
    }
}

__global__ void k_buildM() {
    int idx = blockIdx.x * 256 + threadIdx.x;
    if (idx >= 128 * 128) return;
    int r = idx >> 7, k = idx & 127;
    float ax = 0.f, ay = 0.f;
    {
        int j = 2 * k;
        float2 c1 = gf_chrp1[j];
        float2 e  = gf_E[2 * r - j + 254];
        ax += c1.x * e.x - c1.y * e.y;
        ay += c1.x * e.y + c1.y * e.x;
    }
    for (int j = 1; j < 255; j += 2) {
        float s = gf_S[j - 2 * k + 254];
        float2 c1 = gf_chrp1[j];
        float2 e  = gf_E[2 * r - j + 254];
        ax += (c1.x * e.x - c1.y * e.y) * s;
        ay += (c1.x * e.y + c1.y * e.x) * s;
    }
    float2 f = gf_fac[r];
    g_M[idx] = make_float2(f.x * ax - f.y * ay, f.x * ay + f.y * ax);
}

// K-split x4: 128 blocks x 512 threads
__global__ void __launch_bounds__(512) k_buildMinv() {
    __shared__ float2 sM[128];
    __shared__ float2 sP[512];
    int r = blockIdx.x;
    int t = threadIdx.x, v = t & 127, seg = t >> 7;
    if (t < 128) sM[t] = g_M[r * 128 + t];
    __syncthreads();
    float ax = 0.f, ay = 0.f;
    int u0 = seg * 32;
#pragma unroll 8
    for (int u = u0; u < u0 + 32; u++) {
        float2 a = sM[u];
        float2 b = g_Cm[u * 128 + v];
        ax += a.x * b.x - a.y * b.y;
        ay += a.x * b.y + a.y * b.x;
    }
    sP[t] = make_float2(ax, ay);
    __syncthreads();
    if (t < 128) {
        float2 p0 = sP[t], p1 = sP[t + 128], p2 = sP[t + 256], p3 = sP[t + 384];
        g_Minv[r * 128 + v] = make_float2(p0.x + p1.x + p2.x + p3.x,
                                          p0.y + p1.y + p2.y + p3.y);
    }
}

// merged weight folding: blocks 0..11 -> Wc/bc, block 12 -> W2/b2
__global__ void k_fold(const float* __restrict__ conv2w, const float* __restrict__ conv0w,
                       const float* __restrict__ conv0b,
                       const float* __restrict__ magw, const float* __restrict__ magf,
                       const float* __restrict__ magfb, const float* __restrict__ magb) {
    if (blockIdx.x < 12) {
        int idx = blockIdx.x * 256 + threadIdx.x;
        if (idx < 192 * 16) {
            int o = idx >> 4, c = idx & 15;
            float a = 0.f;
#pragma unroll
            for (int m = 0; m < 16; m++) a += conv2w[o * 48 + m] * conv0w[m * 16 + c];
            g_Wc[idx] = a;
        }
        if (idx < 192) {
            float b = 0.f;
#pragma unroll
            for (int m = 0; m < 16; m++) b += conv2w[idx * 48 + m] * conv0b[m];
            g_bc[idx] = b;
        }
    } else {
        int t = threadIdx.x;
        int o = t >> 4, c = t & 15;
        float a = 0.f;
#pragma unroll
        for (int m = 0; m < 16; m++) a += magw[o * 16 + m] * magf[m * 16 + c];
        g_W2[t] = a;
        if (t < 16) {
            float b = magb[t];
#pragma unroll
            for (int m = 0; m < 16; m++) b += magw[t * 16 + m] * magfb[m];
            g_b2[t] = b;
        }
    }
}

// ---------------- generic 1x1 conv (GEMM) — used for conv1 ----------------
__global__ void __launch_bounds__(128)
k_g1x1(const float* __restrict__ X, const float* __restrict__ Wt,
       float* __restrict__ Y, int Cc, int P, int xStrideN, int yStrideN) {
    __shared__ float sW[16 * 192];
    int n = blockIdx.z, ob = blockIdx.y * 16;
    int tx = threadIdx.x;
    for (int e = tx; e < 16 * Cc; e += 128) sW[e] = Wt[ob * Cc + e];
    __syncthreads();
    const float* Xn = X + (size_t)n * xStrideN;
    int pb = blockIdx.x * 512;
    float acc[16][4];
#pragma unroll
    for (int o = 0; o < 16; o++)
#pragma unroll
        for (int s = 0; s < 4; s++) acc[o][s] = 0.f;
#pragma unroll 4
    for (int c = 0; c < Cc; c++) {
        float xv[4];
#pragma unroll
        for (int s = 0; s < 4; s++)
            xv[s] = Xn[(size_t)c * P + pb + s * 128 + tx];
#pragma unroll
        for (int o = 0; o < 16; o++) {
            float w = sW[o * Cc + c];
#pragma unroll
            for (int s = 0; s < 4; s++) acc[o][s] += w * xv[s];
        }
    }
#pragma unroll
    for (int o = 0; o < 16; o++)
#pragma unroll
        for (int s = 0; s < 4; s++)
            Y[(size_t)n * yStrideN + (size_t)(ob + o) * P + pb + s * 128 + tx] = acc[o][s];
}

// ---------------- conv2 with folded conv_0 branch ----------------
__global__ void __launch_bounds__(128)
k_conv2(const float* __restrict__ X1, const float* __restrict__ Cat,
        const float* __restrict__ conv2w, float* __restrict__ Y) {
    __shared__ float sWa[16 * 16];
    __shared__ float sWb[16 * 32];
    __shared__ float sB[16];
    int n = blockIdx.z, ob = blockIdx.y * 16;
    int tx = threadIdx.x;
    for (int e = tx; e < 256; e += 128)
        sWa[e] = g_Wc[(ob + (e >> 4)) * 16 + (e & 15)];
    for (int e = tx; e < 512; e += 128) {
        int o = e >> 5, c = e & 31;
        sWb[e] = conv2w[(ob + o) * 48 + 16 + c];
    }
    if (tx < 16) sB[tx] = g_bc[ob + tx];
    __syncthreads();
    const float* Xn = X1 + (size_t)n * 48 * PP;
    const float* Cn = Cat + (size_t)n * 48 * PP + (size_t)16 * PP;
    int pb = blockIdx.x * 512;
    float acc[16][4];
#pragma unroll
    for (int o = 0; o < 16; o++)
#pragma unroll
        for (int s = 0; s < 4; s++) acc[o][s] = 0.f;
#pragma unroll 4
    for (int c = 0; c < 16; c++) {
        float xv[4];
#pragma unroll
        for (int s = 0; s < 4; s++)
            xv[s] = Xn[(size_t)c * PP + pb + s * 128 + tx];
#pragma unroll
        for (int o = 0; o < 16; o++) {
            float w = sWa[o * 16 + c];
#pragma unroll
            for (int s = 0; s < 4; s++) acc[o][s] += w * xv[s];
        }
    }
#pragma unroll 4
    for (int c = 0; c < 32; c++) {
        float xv[4];
#pragma unroll
        for (int s = 0; s < 4; s++)
            xv[s] = Cn[(size_t)c * PP + pb + s * 128 + tx];
#pragma unroll
        for (int o = 0; o < 16; o++) {
            float w = sWb[o * 32 + c];
#pragma unroll
            for (int s = 0; s < 4; s++) acc[o][s] += w * xv[s];
        }
    }
#pragma unroll
    for (int o = 0; o < 16; o++)
#pragma unroll
        for (int s = 0; s < 4; s++)
            Y[(size_t)n * 192 * PP + (size_t)(ob + o) * PP + pb + s * 128 + tx] =
                acc[o][s] + sB[o];
}

// ---------------- 64x64-tile complex GEMMs (double-buffered) --------------
__global__ void __launch_bounds__(256)
k_rxMT64(const float* __restrict__ Xb, int cPerN, int cOff,
         const float2* __restrict__ M, float2* __restrict__ Y, int J) {
    __shared__ float  sA[2][64][17];
    __shared__ float2 sB[2][16][65];
    int b = blockIdx.z;
    const float* X = Xb + (size_t)((b >> 4) * cPerN + cOff + (b & 15)) * PP;
    int j0 = blockIdx.x * 64, i0 = blockIdx.y * 64;
    int tid = threadIdx.x;
    int tx = tid & 15, ty = tid >> 4;
    float2 acc[4][4];
#pragma unroll
    for (int a = 0; a < 4; a++)
#pragma unroll
        for (int c = 0; c < 4; c++) acc[a][c] = make_float2(0.f, 0.f);
    float  ra[4]; float2 rb[4];
#pragma unroll
    for (int s = 0; s < 4; s++) {
        int e = tid + s * 256; int r = e >> 4, c = e & 15;
        ra[s] = X[(i0 + r) * 128 + c];
        rb[s] = (j0 + r < J) ? M[(j0 + r) * 128 + c] : make_float2(0.f, 0.f);
    }
#pragma unroll
    for (int s = 0; s < 4; s++) {
        int e = tid + s * 256; int r = e >> 4, c = e & 15;
        sA[0][r][c] = ra[s]; sB[0][c][r] = rb[s];
    }
    __syncthreads();
    for (int ch = 0; ch < 8; ch++) {
        if (ch < 7) {
            int kt = (ch + 1) * 16;
#pragma unroll
            for (int s = 0; s < 4; s++) {
                int e = tid + s * 256; int r = e >> 4, c = e & 15;
                ra[s] = X[(i0 + r) * 128 + kt + c];
                rb[s] = (j0 + r < J) ? M[(j0 + r) * 128 + kt + c] : make_float2(0.f, 0.f);
            }
        }
        int pb = ch & 1;
#pragma unroll
        for (int kk = 0; kk < 16; kk++) {
            float av[4]; float2 bv[4];
#pragma unroll
            for (int ii = 0; ii < 4; ii++) av[ii] = sA[pb][ty * 4 + ii][kk];
#pragma unroll
            for (int jj = 0; jj < 4; jj++) bv[jj] = sB[pb][kk][tx * 4 + jj];
#pragma unroll
            for (int ii = 0; ii < 4; ii++)
#pragma unroll
                for (int jj = 0; jj < 4; jj++) {
                    acc[ii][jj].x += av[ii] * bv[jj].x;
                    acc[ii][jj].y += av[ii] * bv[jj].y;
                }
        }
        if (ch < 7) {
            int nb = (ch + 1) & 1;
#pragma unroll
            for (int s = 0; s < 4; s++) {
                int e = tid + s * 256; int r = e >> 4, c = e & 15;
                sA[nb][r][c] = ra[s]; sB[nb][c][r] = rb[s];
            }
            __syncthreads();
        }
    }
#pragma unroll
    for (int ii = 0; ii < 4; ii++)
#pragma unroll
        for (int jj = 0; jj < 4; jj++) {
            int j = j0 + tx * 4 + jj;
            if (j < J)
                Y[((size_t)b * 128 + i0 + ty * 4 + ii) * J + j] = acc[ii][jj];
        }
}

__global__ void __launch_bounds__(256)
k_cMT64(const float2* __restrict__ Xc, const float2* __restrict__ M,
        float2* __restrict__ Y, int J) {
    __shared__ float2 sA[2][64][17];
    __shared__ float2 sB[2][16][65];
    int b = blockIdx.z;
    const float2* X = Xc + (size_t)b * 128 * 128;
    int j0 = blockIdx.x * 64, i0 = blockIdx.y * 64;
    int tid = threadIdx.x;
    int tx = tid & 15, ty = tid >> 4;
    float2 acc[4][4];
#pragma unroll
    for (int a = 0; a < 4; a++)
#pragma unroll
        for (int c = 0; c < 4; c++) acc[a][c] = make_float2(0.f, 0.f);
    float2 ra[4], rb[4];
#pragma unroll
    for (int s = 0; s < 4; s++) {
        int e = tid + s * 256; int r = e >> 4, c = e & 15;
        ra[s] = X[(i0 + r) * 128 + c];
        rb[s] = (j0 + r < J) ? M[(j0 + r) * 128 + c] : make_float2(0.f, 0.f);
    }
#pragma unroll
    for (int s = 0; s < 4; s++) {
        int e = tid + s * 256; int r = e >> 4, c = e & 15;
        sA[0][r][c] = ra[s]; sB[0][c][r] = rb[s];
    }
    __syncthreads();
    for (int ch = 0; ch < 8; ch++) {
        if (ch < 7) {
            int kt = (ch + 1) * 16;
#pragma unroll
            for (int s = 0; s < 4; s++) {
                int e = tid + s * 256; int r = e >> 4, c = e & 15;
                ra[s] = X[(i0 + r) * 128 + kt + c];
                rb[s] = (j0 + r < J) ? M[(j0 + r) * 128 + kt + c] : make_float2(0.f, 0.f);
            }
        }
        int pb = ch & 1;
#pragma unroll
        for (int kk = 0; kk < 16; kk++) {
            float2 av[4]; float2 bv[4];
#pragma unroll
            for (int ii = 0; ii < 4; ii++) av[ii] = sA[pb][ty * 4 + ii][kk];
#pragma unroll
            for (int jj = 0; jj < 4; jj++) bv[jj] = sB[pb][kk][tx * 4 + jj];
#pragma unroll
            for (int ii = 0; ii < 4; ii++)
#pragma unroll
                for (int jj = 0; jj < 4; jj++) {
                    acc[ii][jj].x += av[ii].x * bv[jj].x - av[ii].y * bv[jj].y;
                    acc[ii][jj].y += av[ii].x * bv[jj].y + av[ii].y * bv[jj].x;
                }
        }
        if (ch < 7) {
            int nb = (ch + 1) & 1;
#pragma unroll
            for (int s = 0; s < 4; s++) {
                int e = tid + s * 256; int r = e >> 4, c = e & 15;
                sA[nb][r][c] = ra[s]; sB[nb][c][r] = rb[s];
            }
            __syncthreads();
        }
    }
#pragma unroll
    for (int ii = 0; ii < 4; ii++)
#pragma unroll
        for (int jj = 0; jj < 4; jj++) {
            int j = j0 + tx * 4 + jj;
            if (j < J)
                Y[((size_t)b * 128 + i0 + ty * 4 + ii) * J + j] = acc[ii][jj];
        }
}

// MODE 0: complex Y ; MODE 1: o1=mag, o2=pha ; MODE 2: |.| into cat ch16..31
template <int MODE>
__global__ void __launch_bounds__(256)
k_MxX64(const float2* __restrict__ M, const float2* __restrict__ Xc,
        float2* __restrict__ Y, float* __restrict__ o1, float* __restrict__ o2,
        int J) {
    __shared__ float2 sA[2][64][17];
    __shared__ float2 sB[2][16][65];
    int b = blockIdx.z;
    const float2* X = Xc + (size_t)b * 128 * J;
    int j0 = blockIdx.x * 64, i0 = blockIdx.y * 64;
    int tid = threadIdx.x;
    int tx = tid & 15, ty = tid >> 4;
    float2 acc[4][4];
#pragma unroll
    for (int a = 0; a < 4; a++)
#pragma unroll
        for (int c = 0; c < 4; c++) acc[a][c] = make_float2(0.f, 0.f);
    float2 ra[4], rb[4];
#pragma unroll
    for (int s = 0; s < 4; s++) {
        int e = tid + s * 256;
        int r = e >> 4, c = e & 15;
        ra[s] = M[(i0 + r) * 128 + c];
        int r2 = e >> 6, c2 = e & 63;
        rb[s] = (j0 + c2 < J) ? X[(size_t)r2 * J + j0 + c2] : make_float2(0.f, 0.f);
    }
#pragma unroll
    for (int s = 0; s < 4; s++) {
        int e = tid + s * 256;
        int r = e >> 4, c = e & 15;
        sA[0][r][c] = ra[s];
        int r2 = e >> 6, c2 = e & 63;
        sB[0][r2][c2] = rb[s];
    }
    __syncthreads();
    for (int ch = 0; ch < 8; ch++) {
        if (ch < 7) {
            int kt = (ch + 1) * 16;
#pragma unroll
            for (int s = 0; s < 4; s++) {
                int e = tid + s * 256;
                int r = e >> 4, c = e & 15;
                ra[s] = M[(i0 + r) * 128 + kt + c];
                int r2 = e >> 6, c2 = e & 63;
                rb[s] = (j0 + c2 < J) ? X[(size_t)(kt + r2) * J + j0 + c2]
                                      : make_float2(0.f, 0.f);
            }
        }
        int pb = ch & 1;
#pragma unroll
        for (int kk = 0; kk < 16; kk++) {
            float2 av[4]; float2 bv[4];
#pragma unroll
            for (int ii = 0; ii < 4; ii++) av[ii] = sA[pb][ty * 4 + ii][kk];
#pragma unroll
            for (int jj = 0; jj < 4; jj++) bv[jj] = sB[pb][kk][tx * 4 + jj];
#pragma unroll
            for (int ii = 0; ii < 4; ii++)
#pragma unroll
                for (int jj = 0; jj < 4; jj++) {
                    acc[ii][jj].x += av[ii].x * bv[jj].x - av[ii].y * bv[jj].y;
                    acc[ii][jj].y += av[ii].x * bv[jj].y + av[ii].y * bv[jj].x;
                }
        }
        if (ch < 7) {
            int nb = (ch + 1) & 1;
#pragma unroll
            for (int s = 0; s < 4; s++) {
                int e = tid + s * 256;
                int r = e >> 4, c = e & 15;
                sA[nb][r][c] = ra[s];
                int r2 = e >> 6, c2 = e & 63;
                sB[nb][r2][c2] = rb[s];
            }
            __syncthreads();
        }
    }
#pragma unroll
    for (int ii = 0; ii < 4; ii++)
#pragma unroll
        for (int jj = 0; jj < 4; jj++) {
            int i = i0 + ty * 4 + ii;
            int j = j0 + tx * 4 + jj;
            if (j >= J) continue;
            float2 v = acc[ii][jj];
            if (MODE == 0) {
                Y[((size_t)b * 128 + i) * J + j] = v;
            } else if (MODE == 1) {
                size_t idx = ((size_t)b * 128 + i) * J + j;
                float m = sqrtf(v.x * v.x + v.y * v.y);
                o1[idx] = m;
                o2[idx] = atan2f(v.y, v.x);
            } else {
                int n = b >> 4, c = b & 15;
                o1[(size_t)(n * C1c + 16 + c) * PP + i * 128 + j] =
                    sqrtf(v.x * v.x + v.y * v.y);
            }
        }
}

// ---------------- Nyquist-column (j=64) slim kernels ----------------------
// fm/fp[b][i][64] = |.|,angle of  Fh @ T_nyq,  T_nyq[k] = sum_w X[k][w]*(-1)^w
__global__ void __launch_bounds__(128)
k_nyqB(const float* __restrict__ Xb, const float2* __restrict__ Fh,
       float* __restrict__ fm, float* __restrict__ fp) {
    __shared__ float sTn[128];
    int b = blockIdx.x;
    const float* X = Xb + (size_t)((b >> 4) * C1c + 32 + (b & 15)) * PP;
    int t = threadIdx.x;
    float s = 0.f;
    const float* row = X + t * 128;
#pragma unroll 16
    for (int w = 0; w < 128; w += 2) s += row[w] - row[w + 1];
    sTn[t] = s;
    __syncthreads();
    float ax = 0.f, ay = 0.f;
#pragma unroll 8
    for (int k = 0; k < 128; k++) {
        float2 f = Fh[t * 128 + k];
        float v = sTn[k];
        ax += f.x * v; ay += f.y * v;
    }
    size_t idx = ((size_t)b * 128 + t) * JW + 64;
    fm[idx] = sqrtf(ax * ax + ay * ay);
    fp[idx] = atan2f(ay, ax);
}

// T65[b][i][64] = Fhi @ F65[b][:,64]
__global__ void __launch_bounds__(128)
k_nyqC(const float2* __restrict__ Fhi, const float2* __restrict__ F65,
       float2* __restrict__ T65) {
    __shared__ float2 sC[128];
    int b = blockIdx.x;
    int t = threadIdx.x;
    sC[t] = F65[((size_t)b * 128 + t) * JW + 64];
    __syncthreads();
    float ax = 0.f, ay = 0.f;
#pragma unroll 8
    for (int k = 0; k < 128; k++) {
        float2 m = Fhi[t * 128 + k];
        float2 v = sC[k];
        ax += m.x * v.x - m.y * v.y;
        ay += m.x * v.y + m.y * v.x;
    }
    T65[((size_t)b * 128 + t) * JW + 64] = make_float2(ax, ay);
}

// x_1o = Re(T3 @ Bw) -> cat ch 32..47
__global__ void k_irfft_w(const float2* __restrict__ T3, float* __restrict__ Ybase) {
    int b = blockIdx.z;
    int tx = threadIdx.x, ty = threadIdx.y;
    int hbase = blockIdx.y * 16;
    float acc[4] = {0.f, 0.f, 0.f, 0.f};
    for (int k = 0; k < JW; k++) {
        float2 bw = g_Bw[k * 128 + tx];
#pragma unroll
        for (int s = 0; s < 4; s++) {
            float2 a = T3[((size_t)b * 128 + hbase + ty * 4 + s) * JW + k];
            acc[s] += a.x * bw.x - a.y * bw.y;
        }
    }
    int n = b >> 4, c = b & 15;
    float* Yp = Ybase + (size_t)(n * C1c + 32 + c) * PP;
#pragma unroll
    for (int s = 0; s < 4; s++)
        Yp[(hbase + ty * 4 + s) * WW + tx] = acc[s];
}

// ---------------- 3x3 masked conv, fused with magw ----------------
__global__ void __launch_bounds__(256)
k_conv3m(const float* __restrict__ X, const float* __restrict__ Wt,
         const float* __restrict__ Bs, const float* __restrict__ MagW,
         const float* __restrict__ MagB, float* __restrict__ Y) {
    __shared__ float sW[CMc * CMc * 9];
    __shared__ float sMW[256];
    __shared__ float sSB[16];
    __shared__ float sMB[16];
    __shared__ float sT[10][34];
    int tid = threadIdx.y * 32 + threadIdx.x;
    for (int e = tid; e < CMc * CMc * 9; e += 256) sW[e] = Wt[e];
    if (tid < 256) sMW[tid] = MagW[tid];
    if (tid < 16) { sSB[tid] = Bs[tid]; sMB[tid] = MagB[tid]; }
    int n = blockIdx.z;
    int wb = blockIdx.x * 32, hb = 16 + blockIdx.y * 8;
    const float* Xn = X + (size_t)n * CMc * PP;
    float acc[CMc];
#pragma unroll
    for (int o = 0; o < CMc; o++) acc[o] = 0.f;
    for (int c = 0; c < CMc; c++) {
        __syncthreads();
        for (int e = tid; e < 340; e += 256) {
            int ly = e / 34, lx = e % 34;
            int gy = hb - 1 + ly, gx = wb - 1 + lx;
            float v = 0.f;
            if (gy >= 19 && gy < 109 && gx >= 19 && gx < 109)
                v = Xn[(size_t)c * PP + gy * WW + gx];
            sT[ly][lx] = v;
        }
        __syncthreads();
#pragma unroll
        for (int kh = 0; kh < 3; kh++)
#pragma unroll
            for (int kw = 0; kw < 3; kw++) {
                float xv = sT[threadIdx.y + kh][threadIdx.x + kw];
#pragma unroll
                for (int o = 0; o < CMc; o++)
                    acc[o] += sW[(o * CMc + c) * 9 + kh * 3 + kw] * xv;
            }
    }
    int h = hb + threadIdx.y, w = wb + threadIdx.x;
    if (h >= 19 && h < 109 && w >= 19 && w < 109) {
#pragma unroll
        for (int m = 0; m < CMc; m++) acc[m] += sSB[m];
        float* Yn = Y + (size_t)n * CMc * PP;
#pragma unroll
        for (int o = 0; o < CMc; o++) {
            float s = sMB[o];
#pragma unroll
            for (int m = 0; m < CMc; m++) s += sMW[o * 16 + m] * acc[m];
            Yn[(size_t)o * PP + h * WW + w] = s;
        }
    }
}

// ---------------- fused pha-mix + mag-outside + makec (1 px/thread) -------
__global__ void __launch_bounds__(128)
k_phamc(const float* __restrict__ Pha, const float* __restrict__ Mag,
        const float* __restrict__ MagO, const float* __restrict__ PhaW,
        const float* __restrict__ PhaB, float2* __restrict__ F) {
    __shared__ float sPW[256];
    __shared__ float sW2[256];
    __shared__ float sPB[16];
    __shared__ float sB2[16];
    int t = threadIdx.x;
    sPW[t] = PhaW[t]; sPW[t + 128] = PhaW[t + 128];
    sW2[t] = g_W2[t]; sW2[t + 128] = g_W2[t + 128];
    if (t < 16)  { sPB[t] = PhaB[t]; sB2[t] = g_b2[t]; }
    __syncthreads();
    int n = blockIdx.y;
    int p = blockIdx.x * 128 + t;
    int h = p >> 7, w = p & 127;
    bool inside = (h >= 19 && h < 109 && w >= 19 && w < 109);
    size_t base = (size_t)n * 16 * PP;
    float ph[16], mg[16];
#pragma unroll
    for (int c = 0; c < 16; c++) ph[c] = Pha[base + (size_t)c * PP + p];
    if (!inside) {
#pragma unroll
        for (int c = 0; c < 16; c++) mg[c] = Mag[base + (size_t)c * PP + p];
    }
#pragma unroll
    for (int o = 0; o < 16; o++) {
        float po = sPB[o];
#pragma unroll
        for (int c = 0; c < 16; c++) po += sPW[o * 16 + c] * ph[c];
        float m;
        if (inside) {
            m = MagO[base + (size_t)o * PP + p];
        } else {
            m = sB2[o];
#pragma unroll
            for (int c = 0; c < 16; c++) m += sW2[o * 16 + c] * mg[c];
        }
        float sn, cs;
        __sincosf(po, &sn, &cs);
        F[base + (size_t)o * PP + p] = make_float2(m * cs, m * sn);
    }
}

// ---------------- fused rfft mag/pha mix + makec (1 px/thread) ------------
__global__ void __launch_bounds__(128)
k_fmfp(const float* __restrict__ Fm, const float* __restrict__ Fp,
       const float* __restrict__ W, const float* __restrict__ B,
       float2* __restrict__ F) {
    __shared__ float sW[256];
    __shared__ float sB[16];
    int t = threadIdx.x;
    sW[t] = W[t]; sW[t + 128] = W[t + 128];
    if (t < 16)  sB[t] = B[t];
    __syncthreads();
    int n = blockIdx.y;
    int p = blockIdx.x * 128 + t;
    if (p >= P65) return;
    size_t base = (size_t)n * 16 * P65;
    float fm[16], fp[16];
#pragma unroll
    for (int c = 0; c < 16; c++) {
        fm[c] = Fm[base + (size_t)c * P65 + p];
        fp[c] = Fp[base + (size_t)c * P65 + p];
    }
#pragma unroll
    for (int o = 0; o < 16; o++) {
        float mo = sB[o], po = sB[o];
#pragma unroll
        for (int c = 0; c < 16; c++) {
            mo += sW[o * 16 + c] * fm[c];
            po += sW[o * 16 + c] * fp[c];
        }
        float sn, cs;
        __sincosf(po, &sn, &cs);
        F[base + (size_t)o * P65 + p] = make_float2(mo * cs, mo * sn);
    }
}

// ---------------- launch ----------------
extern "C" void kernel_launch(void* const* d_in, const int* in_sizes, int n_in,
                              void* d_out, int out_size) {
    const float* x        = (const float*)d_in[0];
    const float* conv1_w  = (const float*)d_in[1];
    const float* mag_s_w  = (const float*)d_in[2];
    const float* mag_s_b  = (const float*)d_in[3];
    const float* mag_f_w  = (const float*)d_in[4];
    const float* mag_f_b  = (const float*)d_in[5];
    const float* mag_w    = (const float*)d_in[6];
    const float* mag_b    = (const float*)d_in[7];
    const float* pha_w    = (const float*)d_in[8];
    const float* pha_b    = (const float*)d_in[9];
    const float* conv_0_w = (const float*)d_in[10];
    const float* conv_0_b = (const float*)d_in[11];
    const float* conv_1_w = (const float*)d_in[12];
    const float* conv_1_b = (const float*)d_in[13];
    const float* conv2_w  = (const float*)d_in[14];
    float* out = (float*)d_out;

    float  *px1, *pmag, *ppha, *pmagout, *pfm, *pfp, *pcat;
    float2 *pM, *pMinv, *pFh, *pFhi, *pFw, *pT, *pF, *pT65, *pF65;
    cudaGetSymbolAddress((void**)&px1,    g_x1);
    cudaGetSymbolAddress((void**)&pmag,   g_mag);
    cudaGetSymbolAddress((void**)&ppha,   g_pha);
    cudaGetSymbolAddress((void**)&pmagout,g_magout);
    cudaGetSymbolAddress((void**)&pfm,    g_fm);
    cudaGetSymbolAddress((void**)&pfp,    g_fp);
    cudaGetSymbolAddress((void**)&pcat,   g_cat);
    cudaGetSymbolAddress((void**)&pM,     g_M);
    cudaGetSymbolAddress((void**)&pMinv,  g_Minv);
    cudaGetSymbolAddress((void**)&pFh,    g_Fh);
    cudaGetSymbolAddress((void**)&pFhi,   g_Fhi);
    cudaGetSymbolAddress((void**)&pFw,    g_Fw);
    cudaGetSymbolAddress((void**)&pT,     g_T);
    cudaGetSymbolAddress((void**)&pF,     g_F);
    cudaGetSymbolAddress((void**)&pT65,   g_T65);
    cudaGetSymbolAddress((void**)&pF65,   g_F65);

    // constant matrices + folded weights
    k_setup<<<64, 256>>>();
    k_buildM<<<64, 256>>>();
    k_buildMinv<<<128, 512>>>();
    k_fold<<<13, 256>>>(conv2_w, conv_0_w, conv_0_b, mag_w, mag_f_w, mag_f_b, mag_b);

    // conv1: 192 -> 48
    k_g1x1<<<dim3(32, 3, NB), 128>>>(x, conv1_w, px1, 192, PP, 192 * PP, 48 * PP);

    // ---- FRFT forward: Fre = M @ X @ M^T  (x_05 = channels 16..31) ----
    k_rxMT64<<<dim3(2, 2, BATCH), 256>>>(px1, C1c, 16, pM, pT, 128);
    k_MxX64<1><<<dim3(2, 2, BATCH), 256>>>(pM, pT, nullptr, pmag, ppha, 128);

    // mag path: conv3 + magw fused (inside); pha mix + outside mag + makec fused
    k_conv3m<<<dim3(4, 12, NB), dim3(32, 8)>>>(pmag, mag_s_w, mag_s_b, mag_w, mag_b, pmagout);
    k_phamc<<<dim3(128, NB), 128>>>(ppha, pmag, pmagout, pha_w, pha_b, pF);

    // ---- FRFT inverse: |Minv @ FreOut @ Minv^T| -> cat ch16..31 ----
    k_cMT64<<<dim3(2, 2, BATCH), 256>>>(pF, pMinv, pT, 128);
    k_MxX64<2><<<dim3(2, 2, BATCH), 256>>>(pMinv, pT, nullptr, pcat, nullptr, 128);

    // ---- rfft2 branch (x_1 = channels 32..47), Nyquist column split off ----
    k_rxMT64<<<dim3(1, 2, BATCH), 256>>>(px1, C1c, 32, pFw, pT65, JW);
    k_MxX64<1><<<dim3(1, 2, BATCH), 256>>>(pFh, pT65, nullptr, pfm, pfp, JW);
    k_nyqB<<<BATCH, 128>>>(px1, pFh, pfm, pfp);
    k_fmfp<<<dim3(65, NB), 128>>>(pfm, pfp, conv_1_w, conv_1_b, pF65);
    k_MxX64<0><<<dim3(1, 2, BATCH), 256>>>(pFhi, pF65, pT65, nullptr, nullptr, JW);
    k_nyqC<<<BATCH, 128>>>(pFhi, pF65, pT65);
    k_irfft_w<<<dim3(1, 8, BATCH), dim3(128, 4)>>>(pT65, pcat);

    // ---- conv2 (conv_0 folded in): 48 -> 192 ----
    k_conv2<<<dim3(32, 12, NB), 128>>>(px1, pcat, conv2_w, out);
}

// round 11
// speedup vs baseline: 2.0817x; 1.0435x over previous
#include <cuda_runtime.h>
#include <math.h>

#define NB   4
#define CIN  192
#define HH   128
#define WW   128
#define PP   (HH*WW)       // 16384
#define C1c  48
#define C0c  16
#define CMc  16
#define BATCH 64           // NB * CMc
#define JW   65
#define P65  (128*JW)      // 8320

// ---------------- device scratch (no allocation allowed) ----------------
static __device__ float2 gf_chrp1[255];
static __device__ float2 gf_E[509];
static __device__ float  gf_S[509];
static __device__ float2 gf_fac[128];

static __device__ float2  g_M   [128*128];
static __device__ float2  g_Cm  [128*128];
static __device__ float2  g_Minv[128*128];
static __device__ float2  g_Fh  [128*128];
static __device__ float2  g_Fhi [128*128];
static __device__ float2  g_Fw  [JW*128];
static __device__ float2  g_Bw  [JW*128];

static __device__ float   g_W2[256];      // magw @ magf
static __device__ float   g_b2[16];       // magw @ magf_b + mag_b
static __device__ float   g_Wc[192*16];   // conv2[:, :16] @ conv0_w
static __device__ float   g_bc[192];      // conv2[:, :16] @ conv0_b

static __device__ float   g_x1 [NB*C1c*PP];
static __device__ float2  g_T  [BATCH*128*128];
static __device__ float2  g_F  [BATCH*128*128];
static __device__ float   g_mag[BATCH*PP];
static __device__ float   g_pha[BATCH*PP];
static __device__ float2  g_T65[BATCH*P65];
static __device__ float2  g_F65[BATCH*P65];
static __device__ float   g_fm[BATCH*P65];
static __device__ float   g_fp[BATCH*P65];
static __device__ float   g_cat[NB*C1c*PP];   // ch 16..47 used

// ---------------- merged table + DFT construction ----------------
__global__ void k_setup() {
    int t = threadIdx.x;
    const double PI = 3.14159265358979323846;
    if (blockIdx.x == 0) {
        double tana2 = tan(PI / 8.0);
        double sina  = sin(PI / 4.0);
        double coef  = tana2 / 512.0;
        double ec    = 1.0 / (512.0 * sina);
        for (int j = t; j < 255; j += 256) {
            double n = (double)(j - 127);
            double s, c; sincospi(-coef * n * n, &s, &c);
            gf_chrp1[j] = make_float2((float)c, (float)s);
        }
        double amp = sqrt(1.0 / (512.0 * sina));
        double ps, pc; sincospi(-0.125, &ps, &pc);
        for (int r = t; r < 128; r += 256) {
            double n = 2.0 * r - 127.0;
            double s, c; sincospi(-coef * n * n, &s, &c);
            gf_fac[r] = make_float2((float)(amp * (pc * c - ps * s)),
                                    (float)(amp * (pc * s + ps * c)));
        }
        for (int i = t; i < 509; i += 256) {
            double d = (double)(i - 254);
            double s, c; sincospi(ec * d * d, &s, &c);
            gf_E[i] = make_float2((float)c, (float)s);
            int m = i - 254;
            double sv;
            if (m == 0) sv = 1.0;
            else if ((m & 1) == 0) sv = 0.0;
            else {
                double x = 0.5 * (double)m;
                sv = sinpi(x) / (PI * x);
            }
            gf_S[i] = (float)sv;
        }
    }
    int idx = blockIdx.x * 256 + t;
    if (idx < 128 * 128) {
        int u = idx >> 7, v = idx & 127;
        int e1 = ((u + 64) * (v + 64)) & 127;
        double s, c; sincospi(2.0 * e1 / 128.0, &s, &c);
        double inv = 1.0 / sqrt(128.0);
        g_Cm[idx] = make_float2((float)(c * inv), (float)(s * inv));
        int e2 = (u * v) & 127;
        double s2, c2; sincospi(-2.0 * e2 / 128.0, &s2, &c2);
        g_Fh[idx] = make_float2((float)c2, (float)s2);
        double s3, c3; sincospi(2.0 * e2 / 128.0, &s3, &c3);
        g_Fhi[idx] = make_float2((float)(c3 / 128.0), (float)(s3 / 128.0));
    }
    if (idx < JW * 128) {
        int k = idx / 128, w = idx & 127;
        int e = (k * w) & 127;
        double s, c; sincospi(-2.0 * e / 128.0, &s, &c);
        g_Fw[idx] = make_float2((float)c, (float)s);
        float2 bw;
        if (k == 0)       bw = make_float2(1.0f / 128.0f, 0.f);
        else if (k == 64) bw = make_float2(((w & 1) ? -1.0f : 1.0f) / 128.0f, 0.f);
        else {
            double s4, c4; sincospi(2.0 * e / 128.0, &s4, &c4);
            bw = make_float2((float)(c4 * 2.0 / 128.0), (float)(s4 * 2.0 / 128.0));
        }
        g_Bw[idx] = bw;
    }
}

__global__ void k_buildM() {
    int idx = blockIdx.x * 256 + threadIdx.x;
    if (idx >= 128 * 128) return;
    int r = idx >> 7, k = idx & 127;
    float ax = 0.f, ay = 0.f;
    {
        int j = 2 * k;
        float2 c1 = gf_chrp1[j];
        float2 e  = gf_E[2 * r - j + 254];
        ax += c1.x * e.x - c1.y * e.y;
        ay += c1.x * e.y + c1.y * e.x;
    }
    for (int j = 1; j < 255; j += 2) {
        float s = gf_S[j - 2 * k + 254];
        float2 c1 = gf_chrp1[j];
        float2 e  = gf_E[2 * r - j + 254];
        ax += (c1.x * e.x - c1.y * e.y) * s;
        ay += (c1.x * e.y + c1.y * e.x) * s;
    }
    float2 f = gf_fac[r];
    g_M[idx] = make_float2(f.x * ax - f.y * ay, f.x * ay + f.y * ax);
}

// K-split x4: 128 blocks x 512 threads
__global__ void __launch_bounds__(512) k_buildMinv() {
    __shared__ float2 sM[128];
    __shared__ float2 sP[512];
    int r = blockIdx.x;
    int t = threadIdx.x, v = t & 127, seg = t >> 7;
    if (t < 128) sM[t] = g_M[r * 128 + t];
    __syncthreads();
    float ax = 0.f, ay = 0.f;
    int u0 = seg * 32;
#pragma unroll 8
    for (int u = u0; u < u0 + 32; u++) {
        float2 a = sM[u];
        float2 b = g_Cm[u * 128 + v];
        ax += a.x * b.x - a.y * b.y;
        ay += a.x * b.y + a.y * b.x;
    }
    sP[t] = make_float2(ax, ay);
    __syncthreads();
    if (t < 128) {
        float2 p0 = sP[t], p1 = sP[t + 128], p2 = sP[t + 256], p3 = sP[t + 384];
        g_Minv[r * 128 + v] = make_float2(p0.x + p1.x + p2.x + p3.x,
                                          p0.y + p1.y + p2.y + p3.y);
    }
}

// merged weight folding: blocks 0..11 -> Wc/bc, block 12 -> W2/b2
__global__ void k_fold(const float* __restrict__ conv2w, const float* __restrict__ conv0w,
                       const float* __restrict__ conv0b,
                       const float* __restrict__ magw, const float* __restrict__ magf,
                       const float* __restrict__ magfb, const float* __restrict__ magb) {
    if (blockIdx.x < 12) {
        int idx = blockIdx.x * 256 + threadIdx.x;
        if (idx < 192 * 16) {
            int o = idx >> 4, c = idx & 15;
            float a = 0.f;
#pragma unroll
            for (int m = 0; m < 16; m++) a += conv2w[o * 48 + m] * conv0w[m * 16 + c];
            g_Wc[idx] = a;
        }
        if (idx < 192) {
            float b = 0.f;
#pragma unroll
            for (int m = 0; m < 16; m++) b += conv2w[idx * 48 + m] * conv0b[m];
            g_bc[idx] = b;
        }
    } else {
        int t = threadIdx.x;
        int o = t >> 4, c = t & 15;
        float a = 0.f;
#pragma unroll
        for (int m = 0; m < 16; m++) a += magw[o * 16 + m] * magf[m * 16 + c];
        g_W2[t] = a;
        if (t < 16) {
            float b = magb[t];
#pragma unroll
            for (int m = 0; m < 16; m++) b += magw[t * 16 + m] * magfb[m];
            g_b2[t] = b;
        }
    }
}

// ---------------- generic 1x1 conv (GEMM) — used for conv1 ----------------
__global__ void __launch_bounds__(128)
k_g1x1(const float* __restrict__ X, const float* __restrict__ Wt,
       float* __restrict__ Y, int Cc, int P, int xStrideN, int yStrideN) {
    __shared__ float sW[16 * 192];
    int n = blockIdx.z, ob = blockIdx.y * 16;
    int tx = threadIdx.x;
    for (int e = tx; e < 16 * Cc; e += 128) sW[e] = Wt[ob * Cc + e];
    __syncthreads();
    const float* Xn = X + (size_t)n * xStrideN;
    int pb = blockIdx.x * 512;
    float acc[16][4];
#pragma unroll
    for (int o = 0; o < 16; o++)
#pragma unroll
        for (int s = 0; s < 4; s++) acc[o][s] = 0.f;
#pragma unroll 4
    for (int c = 0; c < Cc; c++) {
        float xv[4];
#pragma unroll
        for (int s = 0; s < 4; s++)
            xv[s] = Xn[(size_t)c * P + pb + s * 128 + tx];
#pragma unroll
        for (int o = 0; o < 16; o++) {
            float w = sW[o * Cc + c];
#pragma unroll
            for (int s = 0; s < 4; s++) acc[o][s] += w * xv[s];
        }
    }
#pragma unroll
    for (int o = 0; o < 16; o++)
#pragma unroll
        for (int s = 0; s < 4; s++)
            Y[(size_t)n * yStrideN + (size_t)(ob + o) * P + pb + s * 128 + tx] = acc[o][s];
}

// ---------------- conv2 with folded conv_0 branch ----------------
__global__ void __launch_bounds__(128)
k_conv2(const float* __restrict__ X1, const float* __restrict__ Cat,
        const float* __restrict__ conv2w, float* __restrict__ Y) {
    __shared__ float sWa[16 * 16];
    __shared__ float sWb[16 * 32];
    __shared__ float sB[16];
    int n = blockIdx.z, ob = blockIdx.y * 16;
    int tx = threadIdx.x;
    for (int e = tx; e < 256; e += 128)
        sWa[e] = g_Wc[(ob + (e >> 4)) * 16 + (e & 15)];
    for (int e = tx; e < 512; e += 128) {
        int o = e >> 5, c = e & 31;
        sWb[e] = conv2w[(ob + o) * 48 + 16 + c];
    }
    if (tx < 16) sB[tx] = g_bc[ob + tx];
    __syncthreads();
    const float* Xn = X1 + (size_t)n * 48 * PP;
    const float* Cn = Cat + (size_t)n * 48 * PP + (size_t)16 * PP;
    int pb = blockIdx.x * 512;
    float acc[16][4];
#pragma unroll
    for (int o = 0; o < 16; o++)
#pragma unroll
        for (int s = 0; s < 4; s++) acc[o][s] = 0.f;
#pragma unroll 4
    for (int c = 0; c < 16; c++) {
        float xv[4];
#pragma unroll
        for (int s = 0; s < 4; s++)
            xv[s] = Xn[(size_t)c * PP + pb + s * 128 + tx];
#pragma unroll
        for (int o = 0; o < 16; o++) {
            float w = sWa[o * 16 + c];
#pragma unroll
            for (int s = 0; s < 4; s++) acc[o][s] += w * xv[s];
        }
    }
#pragma unroll 4
    for (int c = 0; c < 32; c++) {
        float xv[4];
#pragma unroll
        for (int s = 0; s < 4; s++)
            xv[s] = Cn[(size_t)c * PP + pb + s * 128 + tx];
#pragma unroll
        for (int o = 0; o < 16; o++) {
            float w = sWb[o * 32 + c];
#pragma unroll
            for (int s = 0; s < 4; s++) acc[o][s] += w * xv[s];
        }
    }
#pragma unroll
    for (int o = 0; o < 16; o++)
#pragma unroll
        for (int s = 0; s < 4; s++)
            Y[(size_t)n * 192 * PP + (size_t)(ob + o) * PP + pb + s * 128 + tx] =
                acc[o][s] + sB[o];
}

// ---------------- merged rxMT: frft job (256 blk) + rfft job (128 blk) ----
__global__ void __launch_bounds__(256)
k_rxMT64D(const float* __restrict__ X1,
          const float2* __restrict__ Ma, float2* __restrict__ Ya,
          const float2* __restrict__ Mb, float2* __restrict__ Yb) {
    int bid = blockIdx.x;
    const float* X; const float2* M; float2* Y; int J, j0, i0;
    if (bid < 256) {
        int b = bid >> 2;
        i0 = ((bid >> 1) & 1) * 64; j0 = (bid & 1) * 64;
        X = X1 + (size_t)((b >> 4) * C1c + 16 + (b & 15)) * PP;
        M = Ma; Y = Ya + (size_t)b * 128 * 128; J = 128;
    } else {
        int r = bid - 256; int b = r >> 1;
        i0 = (r & 1) * 64; j0 = 0;
        X = X1 + (size_t)((b >> 4) * C1c + 32 + (b & 15)) * PP;
        M = Mb; Y = Yb + (size_t)b * 128 * JW; J = JW;
    }
    __shared__ float  sA[2][64][17];
    __shared__ float2 sB[2][16][65];
    int tid = threadIdx.x;
    int tx = tid & 15, ty = tid >> 4;
    float2 acc[4][4];
#pragma unroll
    for (int a = 0; a < 4; a++)
#pragma unroll
        for (int c = 0; c < 4; c++) acc[a][c] = make_float2(0.f, 0.f);
    float  ra[4]; float2 rb[4];
#pragma unroll
    for (int s = 0; s < 4; s++) {
        int e = tid + s * 256; int r = e >> 4, c = e & 15;
        ra[s] = X[(i0 + r) * 128 + c];
        rb[s] = (j0 + r < J) ? M[(j0 + r) * 128 + c] : make_float2(0.f, 0.f);
    }
#pragma unroll
    for (int s = 0; s < 4; s++) {
        int e = tid + s * 256; int r = e >> 4, c = e & 15;
        sA[0][r][c] = ra[s]; sB[0][c][r] = rb[s];
    }
    __syncthreads();
    for (int ch = 0; ch < 8; ch++) {
        if (ch < 7) {
            int kt = (ch + 1) * 16;
#pragma unroll
            for (int s = 0; s < 4; s++) {
                int e = tid + s * 256; int r = e >> 4, c = e & 15;
                ra[s] = X[(i0 + r) * 128 + kt + c];
                rb[s] = (j0 + r < J) ? M[(j0 + r) * 128 + kt + c] : make_float2(0.f, 0.f);
            }
        }
        int pb = ch & 1;
#pragma unroll
        for (int kk = 0; kk < 16; kk++) {
            float av[4]; float2 bv[4];
#pragma unroll
            for (int ii = 0; ii < 4; ii++) av[ii] = sA[pb][ty * 4 + ii][kk];
#pragma unroll
            for (int jj = 0; jj < 4; jj++) bv[jj] = sB[pb][kk][tx * 4 + jj];
#pragma unroll
            for (int ii = 0; ii < 4; ii++)
#pragma unroll
                for (int jj = 0; jj < 4; jj++) {
                    acc[ii][jj].x += av[ii] * bv[jj].x;
                    acc[ii][jj].y += av[ii] * bv[jj].y;
                }
        }
        if (ch < 7) {
            int nb = (ch + 1) & 1;
#pragma unroll
            for (int s = 0; s < 4; s++) {
                int e = tid + s * 256; int r = e >> 4, c = e & 15;
                sA[nb][r][c] = ra[s]; sB[nb][c][r] = rb[s];
            }
            __syncthreads();
        }
    }
#pragma unroll
    for (int ii = 0; ii < 4; ii++)
#pragma unroll
        for (int jj = 0; jj < 4; jj++) {
            int j = j0 + tx * 4 + jj;
            if (j < J)
                Y[(size_t)(i0 + ty * 4 + ii) * J + j] = acc[ii][jj];
        }
}

// ---------------- merged MxX (mag/pha epilogue): frft + rfft --------------
__global__ void __launch_bounds__(256)
k_MxXD(const float2* __restrict__ Ma, const float2* __restrict__ Xa,
       float* __restrict__ m1, float* __restrict__ p1,
       const float2* __restrict__ Mb, const float2* __restrict__ Xb,
       float* __restrict__ m2, float* __restrict__ p2) {
    int bid = blockIdx.x;
    const float2* M; const float2* X; float* o1; float* o2; int J, j0, i0; size_t ob;
    if (bid < 256) {
        int b = bid >> 2;
        i0 = ((bid >> 1) & 1) * 64; j0 = (bid & 1) * 64;
        M = Ma; X = Xa + (size_t)b * 128 * 128; J = 128;
        o1 = m1; o2 = p1; ob = (size_t)b * 128;
    } else {
        int r = bid - 256; int b = r >> 1;
        i0 = (r & 1) * 64; j0 = 0;
        M = Mb; X = Xb + (size_t)b * 128 * JW; J = JW;
        o1 = m2; o2 = p2; ob = (size_t)b * 128;
    }
    __shared__ float2 sA[2][64][17];
    __shared__ float2 sB[2][16][65];
    int tid = threadIdx.x;
    int tx = tid & 15, ty = tid >> 4;
    float2 acc[4][4];
#pragma unroll
    for (int a = 0; a < 4; a++)
#pragma unroll
        for (int c = 0; c < 4; c++) acc[a][c] = make_float2(0.f, 0.f);
    float2 ra[4], rb[4];
#pragma unroll
    for (int s = 0; s < 4; s++) {
        int e = tid + s * 256;
        int r = e >> 4, c = e & 15;
        ra[s] = M[(i0 + r) * 128 + c];
        int r2 = e >> 6, c2 = e & 63;
        rb[s] = (j0 + c2 < J) ? X[(size_t)r2 * J + j0 + c2] : make_float2(0.f, 0.f);
    }
#pragma unroll
    for (int s = 0; s < 4; s++) {
        int e = tid + s * 256;
        int r = e >> 4, c = e & 15;
        sA[0][r][c] = ra[s];
        int r2 = e >> 6, c2 = e & 63;
        sB[0][r2][c2] = rb[s];
    }
    __syncthreads();
    for (int ch = 0; ch < 8; ch++) {
        if (ch < 7) {
            int kt = (ch + 1) * 16;
#pragma unroll
            for (int s = 0; s < 4; s++) {
                int e = tid + s * 256;
                int r = e >> 4, c = e & 15;
                ra[s] = M[(i0 + r) * 128 + kt + c];
                int r2 = e >> 6, c2 = e & 63;
                rb[s] = (j0 + c2 < J) ? X[(size_t)(kt + r2) * J + j0 + c2]
                                      : make_float2(0.f, 0.f);
            }
        }
        int pb = ch & 1;
#pragma unroll
        for (int kk = 0; kk < 16; kk++) {
            float2 av[4]; float2 bv[4];
#pragma unroll
            for (int ii = 0; ii < 4; ii++) av[ii] = sA[pb][ty * 4 + ii][kk];
#pragma unroll
            for (int jj = 0; jj < 4; jj++) bv[jj] = sB[pb][kk][tx * 4 + jj];
#pragma unroll
            for (int ii = 0; ii < 4; ii++)
#pragma unroll
                for (int jj = 0; jj < 4; jj++) {
                    acc[ii][jj].x += av[ii].x * bv[jj].x - av[ii].y * bv[jj].y;
                    acc[ii][jj].y += av[ii].x * bv[jj].y + av[ii].y * bv[jj].x;
                }
        }
        if (ch < 7) {
            int nb = (ch + 1) & 1;
#pragma unroll
            for (int s = 0; s < 4; s++) {
                int e = tid + s * 256;
                int r = e >> 4, c = e & 15;
                sA[nb][r][c] = ra[s];
                int r2 = e >> 6, c2 = e & 63;
                sB[nb][r2][c2] = rb[s];
            }
            __syncthreads();
        }
    }
#pragma unroll
    for (int ii = 0; ii < 4; ii++)
#pragma unroll
        for (int jj = 0; jj < 4; jj++) {
            int i = i0 + ty * 4 + ii;
            int j = j0 + tx * 4 + jj;
            if (j >= J) continue;
            float2 v = acc[ii][jj];
            size_t idx = (ob + i) * J + j;
            float m = sqrtf(v.x * v.x + v.y * v.y);
            o1[idx] = m;
            o2[idx] = atan2f(v.y, v.x);
        }
}

__global__ void __launch_bounds__(256)
k_cMT64(const float2* __restrict__ Xc, const float2* __restrict__ M,
        float2* __restrict__ Y, int J) {
    __shared__ float2 sA[2][64][17];
    __shared__ float2 sB[2][16][65];
    int b = blockIdx.z;
    const float2* X = Xc + (size_t)b * 128 * 128;
    int j0 = blockIdx.x * 64, i0 = blockIdx.y * 64;
    int tid = threadIdx.x;
    int tx = tid & 15, ty = tid >> 4;
    float2 acc[4][4];
#pragma unroll
    for (int a = 0; a < 4; a++)
#pragma unroll
        for (int c = 0; c < 4; c++) acc[a][c] = make_float2(0.f, 0.f);
    float2 ra[4], rb[4];
#pragma unroll
    for (int s = 0; s < 4; s++) {
        int e = tid + s * 256; int r = e >> 4, c = e & 15;
        ra[s] = X[(i0 + r) * 128 + c];
        rb[s] = (j0 + r < J) ? M[(j0 + r) * 128 + c] : make_float2(0.f, 0.f);
    }
#pragma unroll
    for (int s = 0; s < 4; s++) {
        int e = tid + s * 256; int r = e >> 4, c = e & 15;
        sA[0][r][c] = ra[s]; sB[0][c][r] = rb[s];
    }
    __syncthreads();
    for (int ch = 0; ch < 8; ch++) {
        if (ch < 7) {
            int kt = (ch + 1) * 16;
#pragma unroll
            for (int s = 0; s < 4; s++) {
                int e = tid + s * 256; int r = e >> 4, c = e & 15;
                ra[s] = X[(i0 + r) * 128 + kt + c];
                rb[s] = (j0 + r < J) ? M[(j0 + r) * 128 + kt + c] : make_float2(0.f, 0.f);
            }
        }
        int pb = ch & 1;
#pragma unroll
        for (int kk = 0; kk < 16; kk++) {
            float2 av[4]; float2 bv[4];
#pragma unroll
            for (int ii = 0; ii < 4; ii++) av[ii] = sA[pb][ty * 4 + ii][kk];
#pragma unroll
            for (int jj = 0; jj < 4; jj++) bv[jj] = sB[pb][kk][tx * 4 + jj];
#pragma unroll
            for (int ii = 0; ii < 4; ii++)
#pragma unroll
                for (int jj = 0; jj < 4; jj++) {
                    acc[ii][jj].x += av[ii].x * bv[jj].x - av[ii].y * bv[jj].y;
                    acc[ii][jj].y += av[ii].x * bv[jj].y + av[ii].y * bv[jj].x;
                }
        }
        if (ch < 7) {
            int nb = (ch + 1) & 1;
#pragma unroll
            for (int s = 0; s < 4; s++) {
                int e = tid + s * 256; int r = e >> 4, c = e & 15;
                sA[nb][r][c] = ra[s]; sB[nb][c][r] = rb[s];
            }
            __syncthreads();
        }
    }
#pragma unroll
    for (int ii = 0; ii < 4; ii++)
#pragma unroll
        for (int jj = 0; jj < 4; jj++) {
            int j = j0 + tx * 4 + jj;
            if (j < J)
                Y[((size_t)b * 128 + i0 + ty * 4 + ii) * J + j] = acc[ii][jj];
        }
}

// MODE 0: complex Y ; MODE 2: |.| into cat ch16..31
template <int MODE>
__global__ void __launch_bounds__(256)
k_MxX64(const float2* __restrict__ M, const float2* __restrict__ Xc,
        float2* __restrict__ Y, float* __restrict__ o1, int J) {
    __shared__ float2 sA[2][64][17];
    __shared__ float2 sB[2][16][65];
    int b = blockIdx.z;
    const float2* X = Xc + (size_t)b * 128 * J;
    int j0 = blockIdx.x * 64, i0 = blockIdx.y * 64;
    int tid = threadIdx.x;
    int tx = tid & 15, ty = tid >> 4;
    float2 acc[4][4];
#pragma unroll
    for (int a = 0; a < 4; a++)
#pragma unroll
        for (int c = 0; c < 4; c++) acc[a][c] = make_float2(0.f, 0.f);
    float2 ra[4], rb[4];
#pragma unroll
    for (int s = 0; s < 4; s++) {
        int e = tid + s * 256;
        int r = e >> 4, c = e & 15;
        ra[s] = M[(i0 + r) * 128 + c];
        int r2 = e >> 6, c2 = e & 63;
        rb[s] = (j0 + c2 < J) ? X[(size_t)r2 * J + j0 + c2] : make_float2(0.f, 0.f);
    }
#pragma unroll
    for (int s = 0; s < 4; s++) {
        int e = tid + s * 256;
        int r = e >> 4, c = e & 15;
        sA[0][r][c] = ra[s];
        int r2 = e >> 6, c2 = e & 63;
        sB[0][r2][c2] = rb[s];
    }
    __syncthreads();
    for (int ch = 0; ch < 8; ch++) {
        if (ch < 7) {
            int kt = (ch + 1) * 16;
#pragma unroll
            for (int s = 0; s < 4; s++) {
                int e = tid + s * 256;
                int r = e >> 4, c = e & 15;
                ra[s] = M[(i0 + r) * 128 + kt + c];
                int r2 = e >> 6, c2 = e & 63;
                rb[s] = (j0 + c2 < J) ? X[(size_t)(kt + r2) * J + j0 + c2]
                                      : make_float2(0.f, 0.f);
            }
        }
        int pb = ch & 1;
#pragma unroll
        for (int kk = 0; kk < 16; kk++) {
            float2 av[4]; float2 bv[4];
#pragma unroll
            for (int ii = 0; ii < 4; ii++) av[ii] = sA[pb][ty * 4 + ii][kk];
#pragma unroll
            for (int jj = 0; jj < 4; jj++) bv[jj] = sB[pb][kk][tx * 4 + jj];
#pragma unroll
            for (int ii = 0; ii < 4; ii++)
#pragma unroll
                for (int jj = 0; jj < 4; jj++) {
                    acc[ii][jj].x += av[ii].x * bv[jj].x - av[ii].y * bv[jj].y;
                    acc[ii][jj].y += av[ii].x * bv[jj].y + av[ii].y * bv[jj].x;
                }
        }
        if (ch < 7) {
            int nb = (ch + 1) & 1;
#pragma unroll
            for (int s = 0; s < 4; s++) {
                int e = tid + s * 256;
                int r = e >> 4, c = e & 15;
                sA[nb][r][c] = ra[s];
                int r2 = e >> 6, c2 = e & 63;
                sB[nb][r2][c2] = rb[s];
            }
            __syncthreads();
        }
    }
#pragma unroll
    for (int ii = 0; ii < 4; ii++)
#pragma unroll
        for (int jj = 0; jj < 4; jj++) {
            int i = i0 + ty * 4 + ii;
            int j = j0 + tx * 4 + jj;
            if (j >= J) continue;
            float2 v = acc[ii][jj];
            if (MODE == 0) {
                Y[((size_t)b * 128 + i) * J + j] = v;
            } else {
                int n = b >> 4, c = b & 15;
                o1[(size_t)(n * C1c + 16 + c) * PP + i * 128 + j] =
                    sqrtf(v.x * v.x + v.y * v.y);
            }
        }
}

// ---------------- Nyquist-column (j=64) slim kernels ----------------------
__global__ void __launch_bounds__(128)
k_nyqB(const float* __restrict__ Xb, const float2* __restrict__ Fh,
       float* __restrict__ fm, float* __restrict__ fp) {
    __shared__ float sTn[128];
    int b = blockIdx.x;
    const float* X = Xb + (size_t)((b >> 4) * C1c + 32 + (b & 15)) * PP;
    int t = threadIdx.x;
    float s = 0.f;
    const float* row = X + t * 128;
#pragma unroll 16
    for (int w = 0; w < 128; w += 2) s += row[w] - row[w + 1];
    sTn[t] = s;
    __syncthreads();
    float ax = 0.f, ay = 0.f;
#pragma unroll 8
    for (int k = 0; k < 128; k++) {
        float2 f = Fh[t * 128 + k];
        float v = sTn[k];
        ax += f.x * v; ay += f.y * v;
    }
    size_t idx = ((size_t)b * 128 + t) * JW + 64;
    fm[idx] = sqrtf(ax * ax + ay * ay);
    fp[idx] = atan2f(ay, ax);
}

__global__ void __launch_bounds__(128)
k_nyqC(const float2* __restrict__ Fhi, const float2* __restrict__ F65,
       float2* __restrict__ T65) {
    __shared__ float2 sC[128];
    int b = blockIdx.x;
    int t = threadIdx.x;
    sC[t] = F65[((size_t)b * 128 + t) * JW + 64];
    __syncthreads();
    float ax = 0.f, ay = 0.f;
#pragma unroll 8
    for (int k = 0; k < 128; k++) {
        float2 m = Fhi[t * 128 + k];
        float2 v = sC[k];
        ax += m.x * v.x - m.y * v.y;
        ay += m.x * v.y + m.y * v.x;
    }
    T65[((size_t)b * 128 + t) * JW + 64] = make_float2(ax, ay);
}

// x_1o = Re(T3 @ Bw) -> cat ch 32..47
__global__ void k_irfft_w(const float2* __restrict__ T3, float* __restrict__ Ybase) {
    int b = blockIdx.z;
    int tx = threadIdx.x, ty = threadIdx.y;
    int hbase = blockIdx.y * 16;
    float acc[4] = {0.f, 0.f, 0.f, 0.f};
    for (int k = 0; k < JW; k++) {
        float2 bw = g_Bw[k * 128 + tx];
#pragma unroll
        for (int s = 0; s < 4; s++) {
            float2 a = T3[((size_t)b * 128 + hbase + ty * 4 + s) * JW + k];
            acc[s] += a.x * bw.x - a.y * bw.y;
        }
    }
    int n = b >> 4, c = b & 15;
    float* Yp = Ybase + (size_t)(n * C1c + 32 + c) * PP;
#pragma unroll
    for (int s = 0; s < 4; s++)
        Yp[(hbase + ty * 4 + s) * WW + tx] = acc[s];
}

// ---------------- 3x3 masked conv + magw + pha-mix + makec (inside px) ----
__global__ void __launch_bounds__(256)
k_conv3mF(const float* __restrict__ X, const float* __restrict__ Pha,
          const float* __restrict__ Wt, const float* __restrict__ Bs,
          const float* __restrict__ MagW, const float* __restrict__ MagB,
          const float* __restrict__ PhaW, const float* __restrict__ PhaB,
          float2* __restrict__ F) {
    __shared__ float sW[CMc * CMc * 9];
    __shared__ float sMW[256];
    __shared__ float sPW[256];
    __shared__ float sSB[16];
    __shared__ float sMB[16];
    __shared__ float sPB[16];
    __shared__ float sT[10][34];
    int tid = threadIdx.y * 32 + threadIdx.x;
    for (int e = tid; e < CMc * CMc * 9; e += 256) sW[e] = Wt[e];
    if (tid < 256) { sMW[tid] = MagW[tid]; sPW[tid] = PhaW[tid]; }
    if (tid < 16) { sSB[tid] = Bs[tid]; sMB[tid] = MagB[tid]; sPB[tid] = PhaB[tid]; }
    int n = blockIdx.z;
    int wb = blockIdx.x * 32, hb = 16 + blockIdx.y * 8;
    const float* Xn = X + (size_t)n * CMc * PP;
    float acc[CMc];
#pragma unroll
    for (int o = 0; o < CMc; o++) acc[o] = 0.f;
    for (int c = 0; c < CMc; c++) {
        __syncthreads();
        for (int e = tid; e < 340; e += 256) {
            int ly = e / 34, lx = e % 34;
            int gy = hb - 1 + ly, gx = wb - 1 + lx;
            float v = 0.f;
            if (gy >= 19 && gy < 109 && gx >= 19 && gx < 109)
                v = Xn[(size_t)c * PP + gy * WW + gx];
            sT[ly][lx] = v;
        }
        __syncthreads();
#pragma unroll
        for (int kh = 0; kh < 3; kh++)
#pragma unroll
            for (int kw = 0; kw < 3; kw++) {
                float xv = sT[threadIdx.y + kh][threadIdx.x + kw];
#pragma unroll
                for (int o = 0; o < CMc; o++)
                    acc[o] += sW[(o * CMc + c) * 9 + kh * 3 + kw] * xv;
            }
    }
    int h = hb + threadIdx.y, w = wb + threadIdx.x;
    if (h >= 19 && h < 109 && w >= 19 && w < 109) {
        int p = h * WW + w;
        size_t base = (size_t)n * 16 * PP;
#pragma unroll
        for (int m = 0; m < CMc; m++) acc[m] += sSB[m];
        float ph[16];
#pragma unroll
        for (int c = 0; c < 16; c++) ph[c] = Pha[base + (size_t)c * PP + p];
#pragma unroll
        for (int o = 0; o < CMc; o++) {
            float mo = sMB[o];
#pragma unroll
            for (int m = 0; m < CMc; m++) mo += sMW[o * 16 + m] * acc[m];
            float po = sPB[o];
#pragma unroll
            for (int c = 0; c < 16; c++) po += sPW[o * 16 + c] * ph[c];
            float sn, cs;
            __sincosf(po, &sn, &cs);
            F[base + (size_t)o * PP + p] = make_float2(mo * cs, mo * sn);
        }
    }
}

// ---------------- outside-mask pha-mix + mag-mix + makec ------------------
__global__ void __launch_bounds__(128)
k_phaO(const float* __restrict__ Pha, const float* __restrict__ Mag,
       const float* __restrict__ PhaW, const float* __restrict__ PhaB,
       float2* __restrict__ F) {
    __shared__ float sPW[256];
    __shared__ float sW2[256];
    __shared__ float sPB[16];
    __shared__ float sB2[16];
    int t = threadIdx.x;
    sPW[t] = PhaW[t]; sPW[t + 128] = PhaW[t + 128];
    sW2[t] = g_W2[t]; sW2[t + 128] = g_W2[t + 128];
    if (t < 16)  { sPB[t] = PhaB[t]; sB2[t] = g_b2[t]; }
    __syncthreads();
    int n = blockIdx.y;
    int p = blockIdx.x * 128 + t;
    int h = p >> 7, w = p & 127;
    if (h >= 19 && h < 109 && w >= 19 && w < 109) return;  // inside handled by conv3mF
    size_t base = (size_t)n * 16 * PP;
    float ph[16], mg[16];
#pragma unroll
    for (int c = 0; c < 16; c++) {
        ph[c] = Pha[base + (size_t)c * PP + p];
        mg[c] = Mag[base + (size_t)c * PP + p];
    }
#pragma unroll
    for (int o = 0; o < 16; o++) {
        float po = sPB[o];
        float m = sB2[o];
#pragma unroll
        for (int c = 0; c < 16; c++) {
            po += sPW[o * 16 + c] * ph[c];
            m  += sW2[o * 16 + c] * mg[c];
        }
        float sn, cs;
        __sincosf(po, &sn, &cs);
        F[base + (size_t)o * PP + p] = make_float2(m * cs, m * sn);
    }
}

// ---------------- fused rfft mag/pha mix + makec (1 px/thread) ------------
__global__ void __launch_bounds__(128)
k_fmfp(const float* __restrict__ Fm, const float* __restrict__ Fp,
       const float* __restrict__ W, const float* __restrict__ B,
       float2* __restrict__ F) {
    __shared__ float sW[256];
    __shared__ float sB[16];
    int t = threadIdx.x;
    sW[t] = W[t]; sW[t + 128] = W[t + 128];
    if (t < 16)  sB[t] = B[t];
    __syncthreads();
    int n = blockIdx.y;
    int p = blockIdx.x * 128 + t;
    if (p >= P65) return;
    size_t base = (size_t)n * 16 * P65;
    float fm[16], fp[16];
#pragma unroll
    for (int c = 0; c < 16; c++) {
        fm[c] = Fm[base + (size_t)c * P65 + p];
        fp[c] = Fp[base + (size_t)c * P65 + p];
    }
#pragma unroll
    for (int o = 0; o < 16; o++) {
        float mo = sB[o], po = sB[o];
#pragma unroll
        for (int c = 0; c < 16; c++) {
            mo += sW[o * 16 + c] * fm[c];
            po += sW[o * 16 + c] * fp[c];
        }
        float sn, cs;
        __sincosf(po, &sn, &cs);
        F[base + (size_t)o * P65 + p] = make_float2(mo * cs, mo * sn);
    }
}

// ---------------- launch ----------------
extern "C" void kernel_launch(void* const* d_in, const int* in_sizes, int n_in,
                              void* d_out, int out_size) {
    const float* x        = (const float*)d_in[0];
    const float* conv1_w  = (const float*)d_in[1];
    const float* mag_s_w  = (const float*)d_in[2];
    const float* mag_s_b  = (const float*)d_in[3];
    const float* mag_f_w  = (const float*)d_in[4];
    const float* mag_f_b  = (const float*)d_in[5];
    const float* mag_w    = (const float*)d_in[6];
    const float* mag_b    = (const float*)d_in[7];
    const float* pha_w    = (const float*)d_in[8];
    const float* pha_b    = (const float*)d_in[9];
    const float* conv_0_w = (const float*)d_in[10];
    const float* conv_0_b = (const float*)d_in[11];
    const float* conv_1_w = (const float*)d_in[12];
    const float* conv_1_b = (const float*)d_in[13];
    const float* conv2_w  = (const float*)d_in[14];
    float* out = (float*)d_out;

    float  *px1, *pmag, *ppha, *pfm, *pfp, *pcat;
    float2 *pM, *pMinv, *pFh, *pFhi, *pFw, *pT, *pF, *pT65, *pF65;
    cudaGetSymbolAddress((void**)&px1,    g_x1);
    cudaGetSymbolAddress((void**)&pmag,   g_mag);
    cudaGetSymbolAddress((void**)&ppha,   g_pha);
    cudaGetSymbolAddress((void**)&pfm,    g_fm);
    cudaGetSymbolAddress((void**)&pfp,    g_fp);
    cudaGetSymbolAddress((void**)&pcat,   g_cat);
    cudaGetSymbolAddress((void**)&pM,     g_M);
    cudaGetSymbolAddress((void**)&pMinv,  g_Minv);
    cudaGetSymbolAddress((void**)&pFh,    g_Fh);
    cudaGetSymbolAddress((void**)&pFhi,   g_Fhi);
    cudaGetSymbolAddress((void**)&pFw,    g_Fw);
    cudaGetSymbolAddress((void**)&pT,     g_T);
    cudaGetSymbolAddress((void**)&pF,     g_F);
    cudaGetSymbolAddress((void**)&pT65,   g_T65);
    cudaGetSymbolAddress((void**)&pF65,   g_F65);

    // constant matrices + folded weights
    k_setup<<<64, 256>>>();
    k_buildM<<<64, 256>>>();
    k_buildMinv<<<128, 512>>>();
    k_fold<<<13, 256>>>(conv2_w, conv_0_w, conv_0_b, mag_w, mag_f_w, mag_f_b, mag_b);

    // conv1: 192 -> 48
    k_g1x1<<<dim3(32, 3, NB), 128>>>(x, conv1_w, px1, 192, PP, 192 * PP, 48 * PP);

    // ---- stage 1 merged: frft rxMT (256 blk) + rfft rxMT (128 blk) ----
    k_rxMT64D<<<384, 256>>>(px1, pM, pT, pFw, pT65);

    // ---- stage 2 merged: frft MxX->mag/pha + rfft MxX->fm/fp ----
    k_MxXD<<<384, 256>>>(pM, pT, pmag, ppha, pFh, pT65, pfm, pfp);
    k_nyqB<<<BATCH, 128>>>(px1, pFh, pfm, pfp);

    // mag/pha paths: conv3+magw+pha-mix+makec inside; outside-only kernel
    k_conv3mF<<<dim3(4, 12, NB), dim3(32, 8)>>>(pmag, ppha, mag_s_w, mag_s_b,
                                                mag_w, mag_b, pha_w, pha_b, pF);
    k_phaO<<<dim3(128, NB), 128>>>(ppha, pmag, pha_w, pha_b, pF);
    k_fmfp<<<dim3(65, NB), 128>>>(pfm, pfp, conv_1_w, conv_1_b, pF65);

    // ---- FRFT inverse: |Minv @ FreOut @ Minv^T| -> cat ch16..31 ----
    k_cMT64<<<dim3(2, 2, BATCH), 256>>>(pF, pMinv, pT, 128);
    k_MxX64<0><<<dim3(1, 2, BATCH), 256>>>(pFhi, pF65, pT65, nullptr, JW);
    k_nyqC<<<BATCH, 128>>>(pFhi, pF65, pT65);
    k_MxX64<2><<<dim3(2, 2, BATCH), 256>>>(pMinv, pT, nullptr, pcat, 128);
    k_irfft_w<<<dim3(1, 8, BATCH), dim3(128, 4)>>>(pT65, pcat);

    // ---- conv2 (conv_0 folded in): 48 -> 192 ----
    k_conv2<<<dim3(32, 12, NB), 128>>>(px1, pcat, conv2_w, out);
}

// round 12
// speedup vs baseline: 2.1311x; 1.0237x over previous
#include <cuda_runtime.h>
#include <math.h>

#define NB   4
#define CIN  192
#define HH   128
#define WW   128
#define PP   (HH*WW)       // 16384
#define C1c  48
#define C0c  16
#define CMc  16
#define BATCH 64           // NB * CMc
#define JW   65
#define P65  (128*JW)      // 8320

// ---------------- device scratch ----------------
static __device__ float2  g_M   [128*128];
static __device__ float2  g_Cm  [128*128];
static __device__ float2  g_Minv[128*128];
static __device__ float2  g_Fh  [128*128];
static __device__ float2  g_Fhi [128*128];
static __device__ float2  g_Fw  [JW*128];
static __device__ float2  g_Bw  [JW*128];

static __device__ float   g_W2[256];      // magw @ magf
static __device__ float   g_b2[16];       // magw @ magf_b + mag_b
static __device__ float   g_Wc[192*16];   // conv2[:, :16] @ conv0_w
static __device__ float   g_bc[192];      // conv2[:, :16] @ conv0_b

static __device__ float   g_x1 [NB*C1c*PP];
static __device__ float2  g_T  [BATCH*128*128];
static __device__ float2  g_F  [BATCH*128*128];
static __device__ float   g_mag[BATCH*PP];
static __device__ float   g_pha[BATCH*PP];
static __device__ float2  g_T65[BATCH*P65];
static __device__ float2  g_F65[BATCH*P65];
static __device__ float   g_fm[BATCH*P65];
static __device__ float   g_fp[BATCH*P65];
static __device__ float   g_cat[NB*C1c*PP];   // ch 16..47 used

// ---------------- k_init: DFT matrices (blk 0..63) + M build (blk 64..127)
__global__ void __launch_bounds__(256) k_init() {
    int bid = blockIdx.x, t = threadIdx.x;
    const double PI = 3.14159265358979323846;
    if (bid < 64) {
        int idx = bid * 256 + t;
        {
            int u = idx >> 7, v = idx & 127;
            int e1 = ((u + 64) * (v + 64)) & 127;
            double s, c; sincospi(2.0 * e1 / 128.0, &s, &c);
            double inv = 1.0 / sqrt(128.0);
            g_Cm[idx] = make_float2((float)(c * inv), (float)(s * inv));
            int e2 = (u * v) & 127;
            double s2, c2; sincospi(-2.0 * e2 / 128.0, &s2, &c2);
            g_Fh[idx] = make_float2((float)c2, (float)s2);
            double s3, c3; sincospi(2.0 * e2 / 128.0, &s3, &c3);
            g_Fhi[idx] = make_float2((float)(c3 / 128.0), (float)(s3 / 128.0));
        }
        if (idx < JW * 128) {
            int k = idx / 128, w = idx & 127;
            int e = (k * w) & 127;
            double s, c; sincospi(-2.0 * e / 128.0, &s, &c);
            g_Fw[idx] = make_float2((float)c, (float)s);
            float2 bw;
            if (k == 0)       bw = make_float2(1.0f / 128.0f, 0.f);
            else if (k == 64) bw = make_float2(((w & 1) ? -1.0f : 1.0f) / 128.0f, 0.f);
            else {
                double s4, c4; sincospi(2.0 * e / 128.0, &s4, &c4);
                bw = make_float2((float)(c4 * 2.0 / 128.0), (float)(s4 * 2.0 / 128.0));
            }
            g_Bw[idx] = bw;
        }
    } else {
        // build 2 rows of M; local tables in smem (bit-identical to fp64 path)
        __shared__ float2 sC1[255];
        __shared__ float2 sE[509];
        __shared__ float  sS[509];
        __shared__ float2 sFac[2];
        int B = bid - 64;
        double tana2 = tan(PI / 8.0);
        double sina  = sin(PI / 4.0);
        double coef  = tana2 / 512.0;
        double ec    = 1.0 / (512.0 * sina);
        for (int j = t; j < 255; j += 256) {
            double n = (double)(j - 127);
            double s, c; sincospi(-coef * n * n, &s, &c);
            sC1[j] = make_float2((float)c, (float)s);
        }
        for (int i = t; i < 509; i += 256) {
            double d = (double)(i - 254);
            double s, c; sincospi(ec * d * d, &s, &c);
            sE[i] = make_float2((float)c, (float)s);
            int m = i - 254;
            double sv;
            if (m == 0) sv = 1.0;
            else if ((m & 1) == 0) sv = 0.0;
            else {
                double x = 0.5 * (double)m;
                sv = sinpi(x) / (PI * x);
            }
            sS[i] = (float)sv;
        }
        if (t < 2) {
            double amp = sqrt(1.0 / (512.0 * sina));
            double ps, pc; sincospi(-0.125, &ps, &pc);
            int r = 2 * B + t;
            double n = 2.0 * r - 127.0;
            double s, c; sincospi(-coef * n * n, &s, &c);
            sFac[t] = make_float2((float)(amp * (pc * c - ps * s)),
                                  (float)(amp * (pc * s + ps * c)));
        }
        __syncthreads();
        int idx = B * 256 + t;
        int r = idx >> 7, k = idx & 127;
        float ax = 0.f, ay = 0.f;
        {
            int j = 2 * k;
            float2 c1 = sC1[j];
            float2 e  = sE[2 * r - j + 254];
            ax += c1.x * e.x - c1.y * e.y;
            ay += c1.x * e.y + c1.y * e.x;
        }
        for (int j = 1; j < 255; j += 2) {
            float s = sS[j - 2 * k + 254];
            float2 c1 = sC1[j];
            float2 e  = sE[2 * r - j + 254];
            ax += (c1.x * e.x - c1.y * e.y) * s;
            ay += (c1.x * e.y + c1.y * e.x) * s;
        }
        float2 f = sFac[r - 2 * B];
        g_M[idx] = make_float2(f.x * ax - f.y * ay, f.x * ay + f.y * ax);
    }
}

// ---------------- k_init2: buildMinv (blk 0..127) + fold (blk 128..140) ---
__global__ void __launch_bounds__(512) k_init2(
        const float* __restrict__ conv2w, const float* __restrict__ conv0w,
        const float* __restrict__ conv0b,
        const float* __restrict__ magw, const float* __restrict__ magf,
        const float* __restrict__ magfb, const float* __restrict__ magb) {
    int bid = blockIdx.x, t = threadIdx.x;
    if (bid < 128) {
        __shared__ float2 sM[128];
        __shared__ float2 sP[512];
        int r = bid;
        int v = t & 127, seg = t >> 7;
        if (t < 128) sM[t] = g_M[r * 128 + t];
        __syncthreads();
        float ax = 0.f, ay = 0.f;
        int u0 = seg * 32;
#pragma unroll 8
        for (int u = u0; u < u0 + 32; u++) {
            float2 a = sM[u];
            float2 b = g_Cm[u * 128 + v];
            ax += a.x * b.x - a.y * b.y;
            ay += a.x * b.y + a.y * b.x;
        }
        sP[t] = make_float2(ax, ay);
        __syncthreads();
        if (t < 128) {
            float2 p0 = sP[t], p1 = sP[t + 128], p2 = sP[t + 256], p3 = sP[t + 384];
            g_Minv[r * 128 + v] = make_float2(p0.x + p1.x + p2.x + p3.x,
                                              p0.y + p1.y + p2.y + p3.y);
        }
    } else if (bid < 140) {
        if (t >= 256) return;
        int idx = (bid - 128) * 256 + t;
        if (idx < 192 * 16) {
            int o = idx >> 4, c = idx & 15;
            float a = 0.f;
#pragma unroll
            for (int m = 0; m < 16; m++) a += conv2w[o * 48 + m] * conv0w[m * 16 + c];
            g_Wc[idx] = a;
        }
        if (idx < 192) {
            float b = 0.f;
#pragma unroll
            for (int m = 0; m < 16; m++) b += conv2w[idx * 48 + m] * conv0b[m];
            g_bc[idx] = b;
        }
    } else {
        if (t >= 256) return;
        int o = t >> 4, c = t & 15;
        float a = 0.f;
#pragma unroll
        for (int m = 0; m < 16; m++) a += magw[o * 16 + m] * magf[m * 16 + c];
        g_W2[t] = a;
        if (t < 16) {
            float b = magb[t];
#pragma unroll
            for (int m = 0; m < 16; m++) b += magw[t * 16 + m] * magfb[m];
            g_b2[t] = b;
        }
    }
}

// ---------------- conv1 (float4 loads) ----------------
__global__ void __launch_bounds__(128)
k_g1x1(const float* __restrict__ X, const float* __restrict__ Wt,
       float* __restrict__ Y, int Cc, int xStrideN, int yStrideN) {
    __shared__ float sW[16 * 192];
    int n = blockIdx.z, ob = blockIdx.y * 16;
    int tx = threadIdx.x;
    for (int e = tx; e < 16 * Cc; e += 128) sW[e] = Wt[ob * Cc + e];
    __syncthreads();
    const float* Xn = X + (size_t)n * xStrideN;
    int p4 = blockIdx.x * 512 + tx * 4;
    float acc[16][4];
#pragma unroll
    for (int o = 0; o < 16; o++)
#pragma unroll
        for (int s = 0; s < 4; s++) acc[o][s] = 0.f;
#pragma unroll 4
    for (int c = 0; c < Cc; c++) {
        float4 xv = *(const float4*)&Xn[(size_t)c * PP + p4];
#pragma unroll
        for (int o = 0; o < 16; o++) {
            float w = sW[o * Cc + c];
            acc[o][0] += w * xv.x; acc[o][1] += w * xv.y;
            acc[o][2] += w * xv.z; acc[o][3] += w * xv.w;
        }
    }
#pragma unroll
    for (int o = 0; o < 16; o++) {
        float4 r = make_float4(acc[o][0], acc[o][1], acc[o][2], acc[o][3]);
        *(float4*)&Y[(size_t)n * yStrideN + (size_t)(ob + o) * PP + p4] = r;
    }
}

// ---------------- conv2 (folded conv_0, float4) ----------------
__global__ void __launch_bounds__(128)
k_conv2(const float* __restrict__ X1, const float* __restrict__ Cat,
        const float* __restrict__ conv2w, float* __restrict__ Y) {
    __shared__ float sWa[16 * 16];
    __shared__ float sWb[16 * 32];
    __shared__ float sB[16];
    int n = blockIdx.z, ob = blockIdx.y * 16;
    int tx = threadIdx.x;
    for (int e = tx; e < 256; e += 128)
        sWa[e] = g_Wc[(ob + (e >> 4)) * 16 + (e & 15)];
    for (int e = tx; e < 512; e += 128) {
        int o = e >> 5, c = e & 31;
        sWb[e] = conv2w[(ob + o) * 48 + 16 + c];
    }
    if (tx < 16) sB[tx] = g_bc[ob + tx];
    __syncthreads();
    const float* Xn = X1 + (size_t)n * 48 * PP;
    const float* Cn = Cat + (size_t)n * 48 * PP + (size_t)16 * PP;
    int p4 = blockIdx.x * 512 + tx * 4;
    float acc[16][4];
#pragma unroll
    for (int o = 0; o < 16; o++)
#pragma unroll
        for (int s = 0; s < 4; s++) acc[o][s] = 0.f;
#pragma unroll 4
    for (int c = 0; c < 16; c++) {
        float4 xv = *(const float4*)&Xn[(size_t)c * PP + p4];
#pragma unroll
        for (int o = 0; o < 16; o++) {
            float w = sWa[o * 16 + c];
            acc[o][0] += w * xv.x; acc[o][1] += w * xv.y;
            acc[o][2] += w * xv.z; acc[o][3] += w * xv.w;
        }
    }
#pragma unroll 4
    for (int c = 0; c < 32; c++) {
        float4 xv = *(const float4*)&Cn[(size_t)c * PP + p4];
#pragma unroll
        for (int o = 0; o < 16; o++) {
            float w = sWb[o * 32 + c];
            acc[o][0] += w * xv.x; acc[o][1] += w * xv.y;
            acc[o][2] += w * xv.z; acc[o][3] += w * xv.w;
        }
    }
#pragma unroll
    for (int o = 0; o < 16; o++) {
        float4 r = make_float4(acc[o][0] + sB[o], acc[o][1] + sB[o],
                               acc[o][2] + sB[o], acc[o][3] + sB[o]);
        *(float4*)&Y[(size_t)n * 192 * PP + (size_t)(ob + o) * PP + p4] = r;
    }
}

// ---------------- merged rxMT: frft (256 blk) + rfft (128 blk) ----
__global__ void __launch_bounds__(256)
k_rxMT64D(const float* __restrict__ X1,
          const float2* __restrict__ Ma, float2* __restrict__ Ya,
          const float2* __restrict__ Mb, float2* __restrict__ Yb) {
    int bid = blockIdx.x;
    const float* X; const float2* M; float2* Y; int J, j0, i0;
    if (bid < 256) {
        int b = bid >> 2;
        i0 = ((bid >> 1) & 1) * 64; j0 = (bid & 1) * 64;
        X = X1 + (size_t)((b >> 4) * C1c + 16 + (b & 15)) * PP;
        M = Ma; Y = Ya + (size_t)b * 128 * 128; J = 128;
    } else {
        int r = bid - 256; int b = r >> 1;
        i0 = (r & 1) * 64; j0 = 0;
        X = X1 + (size_t)((b >> 4) * C1c + 32 + (b & 15)) * PP;
        M = Mb; Y = Yb + (size_t)b * 128 * JW; J = JW;
    }
    __shared__ float  sA[2][64][17];
    __shared__ float2 sB[2][16][65];
    int tid = threadIdx.x;
    int tx = tid & 15, ty = tid >> 4;
    float2 acc[4][4];
#pragma unroll
    for (int a = 0; a < 4; a++)
#pragma unroll
        for (int c = 0; c < 4; c++) acc[a][c] = make_float2(0.f, 0.f);
    float  ra[4]; float2 rb[4];
#pragma unroll
    for (int s = 0; s < 4; s++) {
        int e = tid + s * 256; int r = e >> 4, c = e & 15;
        ra[s] = X[(i0 + r) * 128 + c];
        rb[s] = (j0 + r < J) ? M[(j0 + r) * 128 + c] : make_float2(0.f, 0.f);
    }
#pragma unroll
    for (int s = 0; s < 4; s++) {
        int e = tid + s * 256; int r = e >> 4, c = e & 15;
        sA[0][r][c] = ra[s]; sB[0][c][r] = rb[s];
    }
    __syncthreads();
    for (int ch = 0; ch < 8; ch++) {
        if (ch < 7) {
            int kt = (ch + 1) * 16;
#pragma unroll
            for (int s = 0; s < 4; s++) {
                int e = tid + s * 256; int r = e >> 4, c = e & 15;
                ra[s] = X[(i0 + r) * 128 + kt + c];
                rb[s] = (j0 + r < J) ? M[(j0 + r) * 128 + kt + c] : make_float2(0.f, 0.f);
            }
        }
        int pb = ch & 1;
#pragma unroll
        for (int kk = 0; kk < 16; kk++) {
            float av[4]; float2 bv[4];
#pragma unroll
            for (int ii = 0; ii < 4; ii++) av[ii] = sA[pb][ty * 4 + ii][kk];
#pragma unroll
            for (int jj = 0; jj < 4; jj++) bv[jj] = sB[pb][kk][tx * 4 + jj];
#pragma unroll
            for (int ii = 0; ii < 4; ii++)
#pragma unroll
                for (int jj = 0; jj < 4; jj++) {
                    acc[ii][jj].x += av[ii] * bv[jj].x;
                    acc[ii][jj].y += av[ii] * bv[jj].y;
                }
        }
        if (ch < 7) {
            int nb = (ch + 1) & 1;
#pragma unroll
            for (int s = 0; s < 4; s++) {
                int e = tid + s * 256; int r = e >> 4, c = e & 15;
                sA[nb][r][c] = ra[s]; sB[nb][c][r] = rb[s];
            }
            __syncthreads();
        }
    }
#pragma unroll
    for (int ii = 0; ii < 4; ii++)
#pragma unroll
        for (int jj = 0; jj < 4; jj++) {
            int j = j0 + tx * 4 + jj;
            if (j < J)
                Y[(size_t)(i0 + ty * 4 + ii) * J + j] = acc[ii][jj];
        }
}

// ---------------- merged MxX (mag/pha epilogue) + nyqB --------------------
__global__ void __launch_bounds__(256)
k_MxXD(const float* __restrict__ X1,
       const float2* __restrict__ Ma, const float2* __restrict__ Xa,
       float* __restrict__ m1, float* __restrict__ p1,
       const float2* __restrict__ Mb, const float2* __restrict__ Xb,
       float* __restrict__ m2, float* __restrict__ p2) {
    int bid = blockIdx.x;
    int tid = threadIdx.x;
    if (bid >= 384) {
        // nyqB: 2 images per block
        __shared__ float sTn[2][128];
        int half = tid >> 7, lane = tid & 127;
        int b = (bid - 384) * 2 + half;
        const float* X = X1 + (size_t)((b >> 4) * C1c + 32 + (b & 15)) * PP;
        float s = 0.f;
        const float* row = X + lane * 128;
#pragma unroll 16
        for (int w = 0; w < 128; w += 2) s += row[w] - row[w + 1];
        sTn[half][lane] = s;
        __syncthreads();
        float ax = 0.f, ay = 0.f;
#pragma unroll 8
        for (int k = 0; k < 128; k++) {
            float2 f = Mb[lane * 128 + k];
            float v = sTn[half][k];
            ax += f.x * v; ay += f.y * v;
        }
        size_t idx = ((size_t)b * 128 + lane) * JW + 64;
        m2[idx] = sqrtf(ax * ax + ay * ay);
        p2[idx] = atan2f(ay, ax);
        return;
    }
    const float2* M; const float2* X; float* o1; float* o2; int J, j0, i0; size_t ob;
    if (bid < 256) {
        int b = bid >> 2;
        i0 = ((bid >> 1) & 1) * 64; j0 = (bid & 1) * 64;
        M = Ma; X = Xa + (size_t)b * 128 * 128; J = 128;
        o1 = m1; o2 = p1; ob = (size_t)b * 128;
    } else {
        int r = bid - 256; int b = r >> 1;
        i0 = (r & 1) * 64; j0 = 0;
        M = Mb; X = Xb + (size_t)b * 128 * JW; J = JW;
        o1 = m2; o2 = p2; ob = (size_t)b * 128;
    }
    __shared__ float2 sA[2][64][17];
    __shared__ float2 sB[2][16][65];
    int tx = tid & 15, ty = tid >> 4;
    float2 acc[4][4];
#pragma unroll
    for (int a = 0; a < 4; a++)
#pragma unroll
        for (int c = 0; c < 4; c++) acc[a][c] = make_float2(0.f, 0.f);
    float2 ra[4], rb[4];
#pragma unroll
    for (int s = 0; s < 4; s++) {
        int e = tid + s * 256;
        int r = e >> 4, c = e & 15;
        ra[s] = M[(i0 + r) * 128 + c];
        int r2 = e >> 6, c2 = e & 63;
        rb[s] = (j0 + c2 < J) ? X[(size_t)r2 * J + j0 + c2] : make_float2(0.f, 0.f);
    }
#pragma unroll
    for (int s = 0; s < 4; s++) {
        int e = tid + s * 256;
        int r = e >> 4, c = e & 15;
        sA[0][r][c] = ra[s];
        int r2 = e >> 6, c2 = e & 63;
        sB[0][r2][c2] = rb[s];
    }
    __syncthreads();
    for (int ch = 0; ch < 8; ch++) {
        if (ch < 7) {
            int kt = (ch + 1) * 16;
#pragma unroll
            for (int s = 0; s < 4; s++) {
                int e = tid + s * 256;
                int r = e >> 4, c = e & 15;
                ra[s] = M[(i0 + r) * 128 + kt + c];
                int r2 = e >> 6, c2 = e & 63;
                rb[s] = (j0 + c2 < J) ? X[(size_t)(kt + r2) * J + j0 + c2]
                                      : make_float2(0.f, 0.f);
            }
        }
        int pb = ch & 1;
#pragma unroll
        for (int kk = 0; kk < 16; kk++) {
            float2 av[4]; float2 bv[4];
#pragma unroll
            for (int ii = 0; ii < 4; ii++) av[ii] = sA[pb][ty * 4 + ii][kk];
#pragma unroll
            for (int jj = 0; jj < 4; jj++) bv[jj] = sB[pb][kk][tx * 4 + jj];
#pragma unroll
            for (int ii = 0; ii < 4; ii++)
#pragma unroll
                for (int jj = 0; jj < 4; jj++) {
                    acc[ii][jj].x += av[ii].x * bv[jj].x - av[ii].y * bv[jj].y;
                    acc[ii][jj].y += av[ii].x * bv[jj].y + av[ii].y * bv[jj].x;
                }
        }
        if (ch < 7) {
            int nb = (ch + 1) & 1;
#pragma unroll
            for (int s = 0; s < 4; s++) {
                int e = tid + s * 256;
                int r = e >> 4, c = e & 15;
                sA[nb][r][c] = ra[s];
                int r2 = e >> 6, c2 = e & 63;
                sB[nb][r2][c2] = rb[s];
            }
            __syncthreads();
        }
    }
#pragma unroll
    for (int ii = 0; ii < 4; ii++)
#pragma unroll
        for (int jj = 0; jj < 4; jj++) {
            int i = i0 + ty * 4 + ii;
            int j = j0 + tx * 4 + jj;
            if (j >= J) continue;
            float2 v = acc[ii][jj];
            size_t idx = (ob + i) * J + j;
            float m = sqrtf(v.x * v.x + v.y * v.y);
            o1[idx] = m;
            o2[idx] = atan2f(v.y, v.x);
        }
}

// ---------------- k_invA: cMT(frft) + MxX0(rfft) + nyqC -------------------
__global__ void __launch_bounds__(256)
k_invA(const float2* __restrict__ Fc, const float2* __restrict__ Minv,
       float2* __restrict__ T,
       const float2* __restrict__ Fhi, const float2* __restrict__ F65,
       float2* __restrict__ T65) {
    int bid = blockIdx.x;
    int tid = threadIdx.x;
    if (bid >= 384) {
        // nyqC: 2 images per block
        __shared__ float2 sC[2][128];
        int half = tid >> 7, lane = tid & 127;
        int b = (bid - 384) * 2 + half;
        sC[half][lane] = F65[((size_t)b * 128 + lane) * JW + 64];
        __syncthreads();
        float ax = 0.f, ay = 0.f;
#pragma unroll 8
        for (int k = 0; k < 128; k++) {
            float2 m = Fhi[lane * 128 + k];
            float2 v = sC[half][k];
            ax += m.x * v.x - m.y * v.y;
            ay += m.x * v.y + m.y * v.x;
        }
        T65[((size_t)b * 128 + lane) * JW + 64] = make_float2(ax, ay);
        return;
    }
    __shared__ float2 sA[2][64][17];
    __shared__ float2 sB[2][16][65];
    int tx = tid & 15, ty = tid >> 4;
    float2 acc[4][4];
#pragma unroll
    for (int a = 0; a < 4; a++)
#pragma unroll
        for (int c = 0; c < 4; c++) acc[a][c] = make_float2(0.f, 0.f);
    if (bid < 256) {
        // cMT: T[b][i][j] = sum_k Fc[b][i][k] * Minv[j][k]
        int b = bid >> 2;
        int i0 = ((bid >> 1) & 1) * 64, j0 = (bid & 1) * 64;
        const float2* X = Fc + (size_t)b * 128 * 128;
        float2 ra[4], rb[4];
#pragma unroll
        for (int s = 0; s < 4; s++) {
            int e = tid + s * 256; int r = e >> 4, c = e & 15;
            ra[s] = X[(i0 + r) * 128 + c];
            rb[s] = Minv[(j0 + r) * 128 + c];
        }
#pragma unroll
        for (int s = 0; s < 4; s++) {
            int e = tid + s * 256; int r = e >> 4, c = e & 15;
            sA[0][r][c] = ra[s]; sB[0][c][r] = rb[s];
        }
        __syncthreads();
        for (int ch = 0; ch < 8; ch++) {
            if (ch < 7) {
                int kt = (ch + 1) * 16;
#pragma unroll
                for (int s = 0; s < 4; s++) {
                    int e = tid + s * 256; int r = e >> 4, c = e & 15;
                    ra[s] = X[(i0 + r) * 128 + kt + c];
                    rb[s] = Minv[(j0 + r) * 128 + kt + c];
                }
            }
            int pb = ch & 1;
#pragma unroll
            for (int kk = 0; kk < 16; kk++) {
                float2 av[4]; float2 bv[4];
#pragma unroll
                for (int ii = 0; ii < 4; ii++) av[ii] = sA[pb][ty * 4 + ii][kk];
#pragma unroll
                for (int jj = 0; jj < 4; jj++) bv[jj] = sB[pb][kk][tx * 4 + jj];
#pragma unroll
                for (int ii = 0; ii < 4; ii++)
#pragma unroll
                    for (int jj = 0; jj < 4; jj++) {
                        acc[ii][jj].x += av[ii].x * bv[jj].x - av[ii].y * bv[jj].y;
                        acc[ii][jj].y += av[ii].x * bv[jj].y + av[ii].y * bv[jj].x;
                    }
            }
            if (ch < 7) {
                int nb = (ch + 1) & 1;
#pragma unroll
                for (int s = 0; s < 4; s++) {
                    int e = tid + s * 256; int r = e >> 4, c = e & 15;
                    sA[nb][r][c] = ra[s]; sB[nb][c][r] = rb[s];
                }
                __syncthreads();
            }
        }
#pragma unroll
        for (int ii = 0; ii < 4; ii++)
#pragma unroll
            for (int jj = 0; jj < 4; jj++)
                T[((size_t)b * 128 + i0 + ty * 4 + ii) * 128 + j0 + tx * 4 + jj] = acc[ii][jj];
    } else {
        // MxX0: T65[b][i][j] = sum_k Fhi[i][k] * F65[b][k][j], j<64
        int r0 = bid - 256; int b = r0 >> 1;
        int i0 = (r0 & 1) * 64, j0 = 0;
        const float2* X = F65 + (size_t)b * 128 * JW;
        float2 ra[4], rb[4];
#pragma unroll
        for (int s = 0; s < 4; s++) {
            int e = tid + s * 256;
            int r = e >> 4, c = e & 15;
            ra[s] = Fhi[(i0 + r) * 128 + c];
            int r2 = e >> 6, c2 = e & 63;
            rb[s] = X[(size_t)r2 * JW + j0 + c2];
        }
#pragma unroll
        for (int s = 0; s < 4; s++) {
            int e = tid + s * 256;
            int r = e >> 4, c = e & 15;
            sA[0][r][c] = ra[s];
            int r2 = e >> 6, c2 = e & 63;
            sB[0][r2][c2] = rb[s];
        }
        __syncthreads();
        for (int ch = 0; ch < 8; ch++) {
            if (ch < 7) {
                int kt = (ch + 1) * 16;
#pragma unroll
                for (int s = 0; s < 4; s++) {
                    int e = tid + s * 256;
                    int r = e >> 4, c = e & 15;
                    ra[s] = Fhi[(i0 + r) * 128 + kt + c];
                    int r2 = e >> 6, c2 = e & 63;
                    rb[s] = X[(size_t)(kt + r2) * JW + j0 + c2];
                }
            }
            int pb = ch & 1;
#pragma unroll
            for (int kk = 0; kk < 16; kk++) {
                float2 av[4]; float2 bv[4];
#pragma unroll
                for (int ii = 0; ii < 4; ii++) av[ii] = sA[pb][ty * 4 + ii][kk];
#pragma unroll
                for (int jj = 0; jj < 4; jj++) bv[jj] = sB[pb][kk][tx * 4 + jj];
#pragma unroll
                for (int ii = 0; ii < 4; ii++)
#pragma unroll
                    for (int jj = 0; jj < 4; jj++) {
                        acc[ii][jj].x += av[ii].x * bv[jj].x - av[ii].y * bv[jj].y;
                        acc[ii][jj].y += av[ii].x * bv[jj].y + av[ii].y * bv[jj].x;
                    }
            }
            if (ch < 7) {
                int nb = (ch + 1) & 1;
#pragma unroll
                for (int s = 0; s < 4; s++) {
                    int e = tid + s * 256;
                    int r = e >> 4, c = e & 15;
                    sA[nb][r][c] = ra[s];
                    int r2 = e >> 6, c2 = e & 63;
                    sB[nb][r2][c2] = rb[s];
                }
                __syncthreads();
            }
        }
#pragma unroll
        for (int ii = 0; ii < 4; ii++)
#pragma unroll
            for (int jj = 0; jj < 4; jj++)
                T65[((size_t)b * 128 + i0 + ty * 4 + ii) * JW + j0 + tx * 4 + jj] = acc[ii][jj];
    }
}

// ---------------- k_invB: MxX2 (|.|->cat) + irfft_w -----------------------
__global__ void __launch_bounds__(256)
k_invB(const float2* __restrict__ Minv, const float2* __restrict__ T,
       float* __restrict__ cat, const float2* __restrict__ T65) {
    int bid = blockIdx.x;
    int tid = threadIdx.x;
    if (bid >= 256) {
        // irfft_w: 256 threads, 8 rows per block
        int r0 = bid - 256;
        int b = r0 >> 4;
        int hb = (r0 & 15) * 8;
        int tx = tid & 127, ty = tid >> 7;
        float acc[4] = {0.f, 0.f, 0.f, 0.f};
        for (int k = 0; k < JW; k++) {
            float2 bw = g_Bw[k * 128 + tx];
#pragma unroll
            for (int s = 0; s < 4; s++) {
                float2 a = T65[((size_t)b * 128 + hb + ty * 4 + s) * JW + k];
                acc[s] += a.x * bw.x - a.y * bw.y;
            }
        }
        int n = b >> 4, c = b & 15;
        float* Yp = cat + (size_t)(n * C1c + 32 + c) * PP;
#pragma unroll
        for (int s = 0; s < 4; s++)
            Yp[(hb + ty * 4 + s) * WW + tx] = acc[s];
        return;
    }
    // MxX2: |Minv @ T|  -> cat ch16..31
    __shared__ float2 sA[2][64][17];
    __shared__ float2 sB[2][16][65];
    int tx = tid & 15, ty = tid >> 4;
    int b = bid >> 2;
    int i0 = ((bid >> 1) & 1) * 64, j0 = (bid & 1) * 64;
    const float2* X = T + (size_t)b * 128 * 128;
    float2 acc[4][4];
#pragma unroll
    for (int a = 0; a < 4; a++)
#pragma unroll
        for (int c = 0; c < 4; c++) acc[a][c] = make_float2(0.f, 0.f);
    float2 ra[4], rb[4];
#pragma unroll
    for (int s = 0; s < 4; s++) {
        int e = tid + s * 256;
        int r = e >> 4, c = e & 15;
        ra[s] = Minv[(i0 + r) * 128 + c];
        int r2 = e >> 6, c2 = e & 63;
        rb[s] = X[(size_t)r2 * 128 + j0 + c2];
    }
#pragma unroll
    for (int s = 0; s < 4; s++) {
        int e = tid + s * 256;
        int r = e >> 4, c = e & 15;
        sA[0][r][c] = ra[s];
        int r2 = e >> 6, c2 = e & 63;
        sB[0][r2][c2] = rb[s];
    }
    __syncthreads();
    for (int ch = 0; ch < 8; ch++) {
        if (ch < 7) {
            int kt = (ch + 1) * 16;
#pragma unroll
            for (int s = 0; s < 4; s++) {
                int e = tid + s * 256;
                int r = e >> 4, c = e & 15;
                ra[s] = Minv[(i0 + r) * 128 + kt + c];
                int r2 = e >> 6, c2 = e & 63;
                rb[s] = X[(size_t)(kt + r2) * 128 + j0 + c2];
            }
        }
        int pb = ch & 1;
#pragma unroll
        for (int kk = 0; kk < 16; kk++) {
            float2 av[4]; float2 bv[4];
#pragma unroll
            for (int ii = 0; ii < 4; ii++) av[ii] = sA[pb][ty * 4 + ii][kk];
#pragma unroll
            for (int jj = 0; jj < 4; jj++) bv[jj] = sB[pb][kk][tx * 4 + jj];
#pragma unroll
            for (int ii = 0; ii < 4; ii++)
#pragma unroll
                for (int jj = 0; jj < 4; jj++) {
                    acc[ii][jj].x += av[ii].x * bv[jj].x - av[ii].y * bv[jj].y;
                    acc[ii][jj].y += av[ii].x * bv[jj].y + av[ii].y * bv[jj].x;
                }
        }
        if (ch < 7) {
            int nb = (ch + 1) & 1;
#pragma unroll
            for (int s = 0; s < 4; s++) {
                int e = tid + s * 256;
                int r = e >> 4, c = e & 15;
                sA[nb][r][c] = ra[s];
                int r2 = e >> 6, c2 = e & 63;
                sB[nb][r2][c2] = rb[s];
            }
            __syncthreads();
        }
    }
    int n = b >> 4, c = b & 15;
    float* O = cat + (size_t)(n * C1c + 16 + c) * PP;
#pragma unroll
    for (int ii = 0; ii < 4; ii++)
#pragma unroll
        for (int jj = 0; jj < 4; jj++) {
            float2 v = acc[ii][jj];
            O[(size_t)(i0 + ty * 4 + ii) * 128 + j0 + tx * 4 + jj] =
                sqrtf(v.x * v.x + v.y * v.y);
        }
}

// ---------------- 3x3 masked conv + magw + pha-mix + makec (inside px) ----
__global__ void __launch_bounds__(256)
k_conv3mF(const float* __restrict__ X, const float* __restrict__ Pha,
          const float* __restrict__ Wt, const float* __restrict__ Bs,
          const float* __restrict__ MagW, const float* __restrict__ MagB,
          const float* __restrict__ PhaW, const float* __restrict__ PhaB,
          float2* __restrict__ F) {
    __shared__ float sW[CMc * CMc * 9];
    __shared__ float sMW[256];
    __shared__ float sPW[256];
    __shared__ float sSB[16];
    __shared__ float sMB[16];
    __shared__ float sPB[16];
    __shared__ float sT[10][34];
    int tid = threadIdx.y * 32 + threadIdx.x;
    for (int e = tid; e < CMc * CMc * 9; e += 256) sW[e] = Wt[e];
    if (tid < 256) { sMW[tid] = MagW[tid]; sPW[tid] = PhaW[tid]; }
    if (tid < 16) { sSB[tid] = Bs[tid]; sMB[tid] = MagB[tid]; sPB[tid] = PhaB[tid]; }
    int n = blockIdx.z;
    int wb = blockIdx.x * 32, hb = 16 + blockIdx.y * 8;
    const float* Xn = X + (size_t)n * CMc * PP;
    float acc[CMc];
#pragma unroll
    for (int o = 0; o < CMc; o++) acc[o] = 0.f;
    for (int c = 0; c < CMc; c++) {
        __syncthreads();
        for (int e = tid; e < 340; e += 256) {
            int ly = e / 34, lx = e % 34;
            int gy = hb - 1 + ly, gx = wb - 1 + lx;
            float v = 0.f;
            if (gy >= 19 && gy < 109 && gx >= 19 && gx < 109)
                v = Xn[(size_t)c * PP + gy * WW + gx];
            sT[ly][lx] = v;
        }
        __syncthreads();
#pragma unroll
        for (int kh = 0; kh < 3; kh++)
#pragma unroll
            for (int kw = 0; kw < 3; kw++) {
                float xv = sT[threadIdx.y + kh][threadIdx.x + kw];
#pragma unroll
                for (int o = 0; o < CMc; o++)
                    acc[o] += sW[(o * CMc + c) * 9 + kh * 3 + kw] * xv;
            }
    }
    int h = hb + threadIdx.y, w = wb + threadIdx.x;
    if (h >= 19 && h < 109 && w >= 19 && w < 109) {
        int p = h * WW + w;
        size_t base = (size_t)n * 16 * PP;
#pragma unroll
        for (int m = 0; m < CMc; m++) acc[m] += sSB[m];
        float ph[16];
#pragma unroll
        for (int c = 0; c < 16; c++) ph[c] = Pha[base + (size_t)c * PP + p];
#pragma unroll
        for (int o = 0; o < CMc; o++) {
            float mo = sMB[o];
#pragma unroll
            for (int m = 0; m < CMc; m++) mo += sMW[o * 16 + m] * acc[m];
            float po = sPB[o];
#pragma unroll
            for (int c = 0; c < 16; c++) po += sPW[o * 16 + c] * ph[c];
            float sn, cs;
            __sincosf(po, &sn, &cs);
            F[base + (size_t)o * PP + p] = make_float2(mo * cs, mo * sn);
        }
    }
}

// ---------------- merged: phaO (blk 0..511) + fmfp (blk 512..771) ---------
__global__ void __launch_bounds__(128)
k_phaOF(const float* __restrict__ Pha, const float* __restrict__ Mag,
        const float* __restrict__ PhaW, const float* __restrict__ PhaB,
        float2* __restrict__ F,
        const float* __restrict__ Fm, const float* __restrict__ Fp,
        const float* __restrict__ W1, const float* __restrict__ B1,
        float2* __restrict__ F65) {
    int bid = blockIdx.x;
    int t = threadIdx.x;
    if (bid < 512) {
        __shared__ float sPW[256];
        __shared__ float sW2[256];
        __shared__ float sPB[16];
        __shared__ float sB2[16];
        sPW[t] = PhaW[t]; sPW[t + 128] = PhaW[t + 128];
        sW2[t] = g_W2[t]; sW2[t + 128] = g_W2[t + 128];
        if (t < 16)  { sPB[t] = PhaB[t]; sB2[t] = g_b2[t]; }
        __syncthreads();
        int n = bid >> 7;
        int p = (bid & 127) * 128 + t;
        int h = p >> 7, w = p & 127;
        if (h >= 19 && h < 109 && w >= 19 && w < 109) return;  // inside handled by conv3mF
        size_t base = (size_t)n * 16 * PP;
        float ph[16], mg[16];
#pragma unroll
        for (int c = 0; c < 16; c++) {
            ph[c] = Pha[base + (size_t)c * PP + p];
            mg[c] = Mag[base + (size_t)c * PP + p];
        }
#pragma unroll
        for (int o = 0; o < 16; o++) {
            float po = sPB[o];
            float m = sB2[o];
#pragma unroll
            for (int c = 0; c < 16; c++) {
                po += sPW[o * 16 + c] * ph[c];
                m  += sW2[o * 16 + c] * mg[c];
            }
            float sn, cs;
            __sincosf(po, &sn, &cs);
            F[base + (size_t)o * PP + p] = make_float2(m * cs, m * sn);
        }
    } else {
        __shared__ float sW[256];
        __shared__ float sB[16];
        sW[t] = W1[t]; sW[t + 128] = W1[t + 128];
        if (t < 16)  sB[t] = B1[t];
        __syncthreads();
        int r = bid - 512;
        int n = r / 65;
        int p = (r % 65) * 128 + t;
        if (p >= P65) return;
        size_t base = (size_t)n * 16 * P65;
        float fm[16], fp[16];
#pragma unroll
        for (int c = 0; c < 16; c++) {
            fm[c] = Fm[base + (size_t)c * P65 + p];
            fp[c] = Fp[base + (size_t)c * P65 + p];
        }
#pragma unroll
        for (int o = 0; o < 16; o++) {
            float mo = sB[o], po = sB[o];
#pragma unroll
            for (int c = 0; c < 16; c++) {
                mo += sW[o * 16 + c] * fm[c];
                po += sW[o * 16 + c] * fp[c];
            }
            float sn, cs;
            __sincosf(po, &sn, &cs);
            F65[base + (size_t)o * P65 + p] = make_float2(mo * cs, mo * sn);
        }
    }
}

// ---------------- launch ----------------
extern "C" void kernel_launch(void* const* d_in, const int* in_sizes, int n_in,
                              void* d_out, int out_size) {
    const float* x        = (const float*)d_in[0];
    const float* conv1_w  = (const float*)d_in[1];
    const float* mag_s_w  = (const float*)d_in[2];
    const float* mag_s_b  = (const float*)d_in[3];
    const float* mag_f_w  = (const float*)d_in[4];
    const float* mag_f_b  = (const float*)d_in[5];
    const float* mag_w    = (const float*)d_in[6];
    const float* mag_b    = (const float*)d_in[7];
    const float* pha_w    = (const float*)d_in[8];
    const float* pha_b    = (const float*)d_in[9];
    const float* conv_0_w = (const float*)d_in[10];
    const float* conv_0_b = (const float*)d_in[11];
    const float* conv_1_w = (const float*)d_in[12];
    const float* conv_1_b = (const float*)d_in[13];
    const float* conv2_w  = (const float*)d_in[14];
    float* out = (float*)d_out;

    float  *px1, *pmag, *ppha, *pfm, *pfp, *pcat;
    float2 *pM, *pMinv, *pFh, *pFhi, *pFw, *pT, *pF, *pT65, *pF65;
    cudaGetSymbolAddress((void**)&px1,    g_x1);
    cudaGetSymbolAddress((void**)&pmag,   g_mag);
    cudaGetSymbolAddress((void**)&ppha,   g_pha);
    cudaGetSymbolAddress((void**)&pfm,    g_fm);
    cudaGetSymbolAddress((void**)&pfp,    g_fp);
    cudaGetSymbolAddress((void**)&pcat,   g_cat);
    cudaGetSymbolAddress((void**)&pM,     g_M);
    cudaGetSymbolAddress((void**)&pMinv,  g_Minv);
    cudaGetSymbolAddress((void**)&pFh,    g_Fh);
    cudaGetSymbolAddress((void**)&pFhi,   g_Fhi);
    cudaGetSymbolAddress((void**)&pFw,    g_Fw);
    cudaGetSymbolAddress((void**)&pT,     g_T);
    cudaGetSymbolAddress((void**)&pF,     g_F);
    cudaGetSymbolAddress((void**)&pT65,   g_T65);
    cudaGetSymbolAddress((void**)&pF65,   g_F65);

    // setup: 2 kernels
    k_init <<<128, 256>>>();
    k_init2<<<141, 512>>>(conv2_w, conv_0_w, conv_0_b, mag_w, mag_f_w, mag_f_b, mag_b);

    // conv1: 192 -> 48
    k_g1x1<<<dim3(32, 3, NB), 128>>>(x, conv1_w, px1, 192, 192 * PP, 48 * PP);

    // stage 1: frft rxMT + rfft rxMT
    k_rxMT64D<<<384, 256>>>(px1, pM, pT, pFw, pT65);

    // stage 2: frft MxX->mag/pha + rfft MxX->fm/fp + nyqB
    k_MxXD<<<416, 256>>>(px1, pM, pT, pmag, ppha, pFh, pT65, pfm, pfp);

    // mag/pha paths
    k_conv3mF<<<dim3(4, 12, NB), dim3(32, 8)>>>(pmag, ppha, mag_s_w, mag_s_b,
                                                mag_w, mag_b, pha_w, pha_b, pF);
    k_phaOF<<<772, 128>>>(ppha, pmag, pha_w, pha_b, pF,
                          pfm, pfp, conv_1_w, conv_1_b, pF65);

    // inverse stage A: cMT(frft) + MxX0(rfft) + nyqC
    k_invA<<<416, 256>>>(pF, pMinv, pT, pFhi, pF65, pT65);

    // inverse stage B: MxX2(->cat) + irfft_w(->cat)
    k_invB<<<1280, 256>>>(pMinv, pT, pcat, pT65);

    // conv2 (conv_0 folded in): 48 -> 192
    k_conv2<<<dim3(32, 12, NB), 128>>>(px1, pcat, conv2_w, out);
}

// round 14
// speedup vs baseline: 2.1783x; 1.0222x over previous
#include <cuda_runtime.h>
#include <math.h>

#define NB   4
#define CIN  192
#define HH   128
#define WW   128
#define PP   (HH*WW)       // 16384
#define C1c  48
#define C0c  16
#define CMc  16
#define BATCH 64           // NB * CMc
#define JW   65
#define P65  (128*JW)      // 8320

// ---------------- device scratch ----------------
static __device__ float2  g_M   [128*128];
static __device__ float2  g_Cm  [128*128];
static __device__ float2  g_Minv[128*128];
static __device__ float2  g_Fh  [128*128];
static __device__ float2  g_Fhi [128*128];
static __device__ float2  g_Fw  [JW*128];
static __device__ float2  g_Bw  [JW*128];

static __device__ float   g_W2[256];
static __device__ float   g_b2[16];
static __device__ float   g_Wc[192*16];
static __device__ float   g_bc[192];

static __device__ float   g_x1 [NB*C1c*PP];
static __device__ float2  g_T  [BATCH*128*128];
static __device__ float2  g_F  [BATCH*128*128];
static __device__ float   g_mag[BATCH*PP];
static __device__ float   g_pha[BATCH*PP];
static __device__ float2  g_T65[BATCH*P65];
static __device__ float2  g_F65[BATCH*P65];
static __device__ float   g_fm[BATCH*P65];
static __device__ float   g_fp[BATCH*P65];
static __device__ float   g_cat[NB*C1c*PP];

// ---------------- k_init ----------------
__global__ void __launch_bounds__(256) k_init() {
    int bid = blockIdx.x, t = threadIdx.x;
    const double PI = 3.14159265358979323846;
    if (bid < 64) {
        int idx = bid * 256 + t;
        {
            int u = idx >> 7, v = idx & 127;
            int e1 = ((u + 64) * (v + 64)) & 127;
            double s, c; sincospi(2.0 * e1 / 128.0, &s, &c);
            double inv = 1.0 / sqrt(128.0);
            g_Cm[idx] = make_float2((float)(c * inv), (float)(s * inv));
            int e2 = (u * v) & 127;
            double s2, c2; sincospi(-2.0 * e2 / 128.0, &s2, &c2);
            g_Fh[idx] = make_float2((float)c2, (float)s2);
            double s3, c3; sincospi(2.0 * e2 / 128.0, &s3, &c3);
            g_Fhi[idx] = make_float2((float)(c3 / 128.0), (float)(s3 / 128.0));
        }
        if (idx < JW * 128) {
            int k = idx / 128, w = idx & 127;
            int e = (k * w) & 127;
            double s, c; sincospi(-2.0 * e / 128.0, &s, &c);
            g_Fw[idx] = make_float2((float)c, (float)s);
            float2 bw;
            if (k == 0)       bw = make_float2(1.0f / 128.0f, 0.f);
            else if (k == 64) bw = make_float2(((w & 1) ? -1.0f : 1.0f) / 128.0f, 0.f);
            else {
                double s4, c4; sincospi(2.0 * e / 128.0, &s4, &c4);
                bw = make_float2((float)(c4 * 2.0 / 128.0), (float)(s4 * 2.0 / 128.0));
            }
            g_Bw[idx] = bw;
        }
    } else {
        __shared__ float2 sC1[255];
        __shared__ float2 sE[509];
        __shared__ float  sS[509];
        __shared__ float2 sFac[2];
        int B = bid - 64;
        double tana2 = tan(PI / 8.0);
        double sina  = sin(PI / 4.0);
        double coef  = tana2 / 512.0;
        double ec    = 1.0 / (512.0 * sina);
        for (int j = t; j < 255; j += 256) {
            double n = (double)(j - 127);
            double s, c; sincospi(-coef * n * n, &s, &c);
            sC1[j] = make_float2((float)c, (float)s);
        }
        for (int i = t; i < 509; i += 256) {
            double d = (double)(i - 254);
            double s, c; sincospi(ec * d * d, &s, &c);
            sE[i] = make_float2((float)c, (float)s);
            int m = i - 254;
            double sv;
            if (m == 0) sv = 1.0;
            else if ((m & 1) == 0) sv = 0.0;
            else {
                double x = 0.5 * (double)m;
                sv = sinpi(x) / (PI * x);
            }
            sS[i] = (float)sv;
        }
        if (t < 2) {
            double amp = sqrt(1.0 / (512.0 * sina));
            double ps, pc; sincospi(-0.125, &ps, &pc);
            int r = 2 * B + t;
            double n = 2.0 * r - 127.0;
            double s, c; sincospi(-coef * n * n, &s, &c);
            sFac[t] = make_float2((float)(amp * (pc * c - ps * s)),
                                  (float)(amp * (pc * s + ps * c)));
        }
        __syncthreads();
        int idx = B * 256 + t;
        int r = idx >> 7, k = idx & 127;
        float ax = 0.f, ay = 0.f;
        {
            int j = 2 * k;
            float2 c1 = sC1[j];
            float2 e  = sE[2 * r - j + 254];
            ax += c1.x * e.x - c1.y * e.y;
            ay += c1.x * e.y + c1.y * e.x;
        }
        for (int j = 1; j < 255; j += 2) {
            float s = sS[j - 2 * k + 254];
            float2 c1 = sC1[j];
            float2 e  = sE[2 * r - j + 254];
            ax += (c1.x * e.x - c1.y * e.y) * s;
            ay += (c1.x * e.y + c1.y * e.x) * s;
        }
        float2 f = sFac[r - 2 * B];
        g_M[idx] = make_float2(f.x * ax - f.y * ay, f.x * ay + f.y * ax);
    }
}

// ---------------- k_init2 ----------------
__global__ void __launch_bounds__(512) k_init2(
        const float* __restrict__ conv2w, const float* __restrict__ conv0w,
        const float* __restrict__ conv0b,
        const float* __restrict__ magw, const float* __restrict__ magf,
        const float* __restrict__ magfb, const float* __restrict__ magb) {
    int bid = blockIdx.x, t = threadIdx.x;
    if (bid < 128) {
        __shared__ float2 sM[128];
        __shared__ float2 sP[512];
        int r = bid;
        int v = t & 127, seg = t >> 7;
        if (t < 128) sM[t] = g_M[r * 128 + t];
        __syncthreads();
        float ax = 0.f, ay = 0.f;
        int u0 = seg * 32;
#pragma unroll 8
        for (int u = u0; u < u0 + 32; u++) {
            float2 a = sM[u];
            float2 b = g_Cm[u * 128 + v];
            ax += a.x * b.x - a.y * b.y;
            ay += a.x * b.y + a.y * b.x;
        }
        sP[t] = make_float2(ax, ay);
        __syncthreads();
        if (t < 128) {
            float2 p0 = sP[t], p1 = sP[t + 128], p2 = sP[t + 256], p3 = sP[t + 384];
            g_Minv[r * 128 + v] = make_float2(p0.x + p1.x + p2.x + p3.x,
                                              p0.y + p1.y + p2.y + p3.y);
        }
    } else if (bid < 140) {
        if (t >= 256) return;
        int idx = (bid - 128) * 256 + t;
        if (idx < 192 * 16) {
            int o = idx >> 4, c = idx & 15;
            float a = 0.f;
#pragma unroll
            for (int m = 0; m < 16; m++) a += conv2w[o * 48 + m] * conv0w[m * 16 + c];
            g_Wc[idx] = a;
        }
        if (idx < 192) {
            float b = 0.f;
#pragma unroll
            for (int m = 0; m < 16; m++) b += conv2w[idx * 48 + m] * conv0b[m];
            g_bc[idx] = b;
        }
    } else {
        if (t >= 256) return;
        int o = t >> 4, c = t & 15;
        float a = 0.f;
#pragma unroll
        for (int m = 0; m < 16; m++) a += magw[o * 16 + m] * magf[m * 16 + c];
        g_W2[t] = a;
        if (t < 16) {
            float b = magb[t];
#pragma unroll
            for (int m = 0; m < 16; m++) b += magw[t * 16 + m] * magfb[m];
            g_b2[t] = b;
        }
    }
}

// ---------------- conv1 (float4) ----------------
__global__ void __launch_bounds__(128)
k_g1x1(const float* __restrict__ X, const float* __restrict__ Wt,
       float* __restrict__ Y, int Cc, int xStrideN, int yStrideN) {
    __shared__ float sW[16 * 192];
    int n = blockIdx.z, ob = blockIdx.y * 16;
    int tx = threadIdx.x;
    for (int e = tx; e < 16 * Cc; e += 128) sW[e] = Wt[ob * Cc + e];
    __syncthreads();
    const float* Xn = X + (size_t)n * xStrideN;
    int p4 = blockIdx.x * 512 + tx * 4;
    float acc[16][4];
#pragma unroll
    for (int o = 0; o < 16; o++)
#pragma unroll
        for (int s = 0; s < 4; s++) acc[o][s] = 0.f;
#pragma unroll 4
    for (int c = 0; c < Cc; c++) {
        float4 xv = *(const float4*)&Xn[(size_t)c * PP + p4];
#pragma unroll
        for (int o = 0; o < 16; o++) {
            float w = sW[o * Cc + c];
            acc[o][0] += w * xv.x; acc[o][1] += w * xv.y;
            acc[o][2] += w * xv.z; acc[o][3] += w * xv.w;
        }
    }
#pragma unroll
    for (int o = 0; o < 16; o++) {
        float4 r = make_float4(acc[o][0], acc[o][1], acc[o][2], acc[o][3]);
        *(float4*)&Y[(size_t)n * yStrideN + (size_t)(ob + o) * PP + p4] = r;
    }
}

// ---------------- conv2 (folded conv_0, float4) ----------------
__global__ void __launch_bounds__(128)
k_conv2(const float* __restrict__ X1, const float* __restrict__ Cat,
        const float* __restrict__ conv2w, float* __restrict__ Y) {
    __shared__ float sWa[16 * 16];
    __shared__ float sWb[16 * 32];
    __shared__ float sB[16];
    int n = blockIdx.z, ob = blockIdx.y * 16;
    int tx = threadIdx.x;
    for (int e = tx; e < 256; e += 128)
        sWa[e] = g_Wc[(ob + (e >> 4)) * 16 + (e & 15)];
    for (int e = tx; e < 512; e += 128) {
        int o = e >> 5, c = e & 31;
        sWb[e] = conv2w[(ob + o) * 48 + 16 + c];
    }
    if (tx < 16) sB[tx] = g_bc[ob + tx];
    __syncthreads();
    const float* Xn = X1 + (size_t)n * 48 * PP;
    const float* Cn = Cat + (size_t)n * 48 * PP + (size_t)16 * PP;
    int p4 = blockIdx.x * 512 + tx * 4;
    float acc[16][4];
#pragma unroll
    for (int o = 0; o < 16; o++)
#pragma unroll
        for (int s = 0; s < 4; s++) acc[o][s] = 0.f;
#pragma unroll 4
    for (int c = 0; c < 16; c++) {
        float4 xv = *(const float4*)&Xn[(size_t)c * PP + p4];
#pragma unroll
        for (int o = 0; o < 16; o++) {
            float w = sWa[o * 16 + c];
            acc[o][0] += w * xv.x; acc[o][1] += w * xv.y;
            acc[o][2] += w * xv.z; acc[o][3] += w * xv.w;
        }
    }
#pragma unroll 4
    for (int c = 0; c < 32; c++) {
        float4 xv = *(const float4*)&Cn[(size_t)c * PP + p4];
#pragma unroll
        for (int o = 0; o < 16; o++) {
            float w = sWb[o * 32 + c];
            acc[o][0] += w * xv.x; acc[o][1] += w * xv.y;
            acc[o][2] += w * xv.z; acc[o][3] += w * xv.w;
        }
    }
#pragma unroll
    for (int o = 0; o < 16; o++) {
        float4 r = make_float4(acc[o][0] + sB[o], acc[o][1] + sB[o],
                               acc[o][2] + sB[o], acc[o][3] + sB[o]);
        *(float4*)&Y[(size_t)n * 192 * PP + (size_t)(ob + o) * PP + p4] = r;
    }
}

// ---------------- merged rxMT (k-major smem, vector LDS) ------------------
__global__ void __launch_bounds__(256)
k_rxMT64D(const float* __restrict__ X1,
          const float2* __restrict__ Ma, float2* __restrict__ Ya,
          const float2* __restrict__ Mb, float2* __restrict__ Yb) {
    int bid = blockIdx.x;
    const float* X; const float2* M; float2* Y; int J, j0, i0;
    if (bid < 256) {
        int b = bid >> 2;
        i0 = ((bid >> 1) & 1) * 64; j0 = (bid & 1) * 64;
        X = X1 + (size_t)((b >> 4) * C1c + 16 + (b & 15)) * PP;
        M = Ma; Y = Ya + (size_t)b * 128 * 128; J = 128;
    } else {
        int r = bid - 256; int b = r >> 1;
        i0 = (r & 1) * 64; j0 = 0;
        X = X1 + (size_t)((b >> 4) * C1c + 32 + (b & 15)) * PP;
        M = Mb; Y = Yb + (size_t)b * 128 * JW; J = JW;
    }
    __shared__ __align__(16) float  sA[2][16][68];   // [k][i]
    __shared__ __align__(16) float2 sB[2][16][66];   // [k][j]
    int tid = threadIdx.x;
    int tx = tid & 15, ty = tid >> 4;
    float2 acc[4][4];
#pragma unroll
    for (int a = 0; a < 4; a++)
#pragma unroll
        for (int c = 0; c < 4; c++) acc[a][c] = make_float2(0.f, 0.f);
    float  ra[4]; float2 rb[4];
#pragma unroll
    for (int s = 0; s < 4; s++) {
        int e = tid + s * 256; int r = e >> 4, c = e & 15;
        ra[s] = X[(i0 + r) * 128 + c];
        rb[s] = (j0 + r < J) ? M[(j0 + r) * 128 + c] : make_float2(0.f, 0.f);
    }
#pragma unroll
    for (int s = 0; s < 4; s++) {
        int e = tid + s * 256; int r = e >> 4, c = e & 15;
        sA[0][c][r] = ra[s]; sB[0][c][r] = rb[s];
    }
    __syncthreads();
    for (int ch = 0; ch < 8; ch++) {
        if (ch < 7) {
            int kt = (ch + 1) * 16;
#pragma unroll
            for (int s = 0; s < 4; s++) {
                int e = tid + s * 256; int r = e >> 4, c = e & 15;
                ra[s] = X[(i0 + r) * 128 + kt + c];
                rb[s] = (j0 + r < J) ? M[(j0 + r) * 128 + kt + c] : make_float2(0.f, 0.f);
            }
        }
        int pb = ch & 1;
#pragma unroll
        for (int kk = 0; kk < 16; kk++) {
            float4 a4 = *(const float4*)&sA[pb][kk][ty * 4];
            float4 b0 = *(const float4*)&sB[pb][kk][tx * 4];
            float4 b1 = *(const float4*)&sB[pb][kk][tx * 4 + 2];
            float av[4] = {a4.x, a4.y, a4.z, a4.w};
            float2 bv[4] = {{b0.x, b0.y}, {b0.z, b0.w}, {b1.x, b1.y}, {b1.z, b1.w}};
#pragma unroll
            for (int ii = 0; ii < 4; ii++)
#pragma unroll
                for (int jj = 0; jj < 4; jj++) {
                    acc[ii][jj].x += av[ii] * bv[jj].x;
                    acc[ii][jj].y += av[ii] * bv[jj].y;
                }
        }
        if (ch < 7) {
            int nb = (ch + 1) & 1;
#pragma unroll
            for (int s = 0; s < 4; s++) {
                int e = tid + s * 256; int r = e >> 4, c = e & 15;
                sA[nb][c][r] = ra[s]; sB[nb][c][r] = rb[s];
            }
            __syncthreads();
        }
    }
#pragma unroll
    for (int ii = 0; ii < 4; ii++)
#pragma unroll
        for (int jj = 0; jj < 4; jj++) {
            int j = j0 + tx * 4 + jj;
            if (j < J)
                Y[(size_t)(i0 + ty * 4 + ii) * J + j] = acc[ii][jj];
        }
}

// ---------------- merged MxX (mag/pha epilogue) + nyqB --------------------
__global__ void __launch_bounds__(256)
k_MxXD(const float* __restrict__ X1,
       const float2* __restrict__ Ma, const float2* __restrict__ Xa,
       float* __restrict__ m1, float* __restrict__ p1,
       const float2* __restrict__ Mb, const float2* __restrict__ Xb,
       float* __restrict__ m2, float* __restrict__ p2) {
    int bid = blockIdx.x;
    int tid = threadIdx.x;
    if (bid >= 384) {
        __shared__ float sTn[2][128];
        int half = tid >> 7, lane = tid & 127;
        int b = (bid - 384) * 2 + half;
        const float* X = X1 + (size_t)((b >> 4) * C1c + 32 + (b & 15)) * PP;
        float s = 0.f;
        const float* row = X + lane * 128;
#pragma unroll 16
        for (int w = 0; w < 128; w += 2) s += row[w] - row[w + 1];
        sTn[half][lane] = s;
        __syncthreads();
        float ax = 0.f, ay = 0.f;
#pragma unroll 8
        for (int k = 0; k < 128; k++) {
            float2 f = Mb[lane * 128 + k];
            float v = sTn[half][k];
            ax += f.x * v; ay += f.y * v;
        }
        size_t idx = ((size_t)b * 128 + lane) * JW + 64;
        m2[idx] = sqrtf(ax * ax + ay * ay);
        p2[idx] = atan2f(ay, ax);
        return;
    }
    const float2* M; const float2* X; float* o1; float* o2; int J, j0, i0; size_t ob;
    if (bid < 256) {
        int b = bid >> 2;
        i0 = ((bid >> 1) & 1) * 64; j0 = (bid & 1) * 64;
        M = Ma; X = Xa + (size_t)b * 128 * 128; J = 128;
        o1 = m1; o2 = p1; ob = (size_t)b * 128;
    } else {
        int r = bid - 256; int b = r >> 1;
        i0 = (r & 1) * 64; j0 = 0;
        M = Mb; X = Xb + (size_t)b * 128 * JW; J = JW;
        o1 = m2; o2 = p2; ob = (size_t)b * 128;
    }
    __shared__ __align__(16) float2 sA[2][16][66];   // [k][i]
    __shared__ __align__(16) float2 sB[2][16][66];   // [k][j]
    int tx = tid & 15, ty = tid >> 4;
    float2 acc[4][4];
#pragma unroll
    for (int a = 0; a < 4; a++)
#pragma unroll
        for (int c = 0; c < 4; c++) acc[a][c] = make_float2(0.f, 0.f);
    float2 ra[4], rb[4];
#pragma unroll
    for (int s = 0; s < 4; s++) {
        int e = tid + s * 256;
        int r = e >> 4, c = e & 15;
        ra[s] = M[(i0 + r) * 128 + c];
        int r2 = e >> 6, c2 = e & 63;
        rb[s] = (j0 + c2 < J) ? X[(size_t)r2 * J + j0 + c2] : make_float2(0.f, 0.f);
    }
#pragma unroll
    for (int s = 0; s < 4; s++) {
        int e = tid + s * 256;
        int r = e >> 4, c = e & 15;
        sA[0][c][r] = ra[s];
        int r2 = e >> 6, c2 = e & 63;
        sB[0][r2][c2] = rb[s];
    }
    __syncthreads();
    for (int ch = 0; ch < 8; ch++) {
        if (ch < 7) {
            int kt = (ch + 1) * 16;
#pragma unroll
            for (int s = 0; s < 4; s++) {
                int e = tid + s * 256;
                int r = e >> 4, c = e & 15;
                ra[s] = M[(i0 + r) * 128 + kt + c];
                int r2 = e >> 6, c2 = e & 63;
                rb[s] = (j0 + c2 < J) ? X[(size_t)(kt + r2) * J + j0 + c2]
                                      : make_float2(0.f, 0.f);
            }
        }
        int pb = ch & 1;
#pragma unroll
        for (int kk = 0; kk < 16; kk++) {
            float4 a0 = *(const float4*)&sA[pb][kk][ty * 4];
            float4 a1 = *(const float4*)&sA[pb][kk][ty * 4 + 2];
            float4 b0 = *(const float4*)&sB[pb][kk][tx * 4];
            float4 b1 = *(const float4*)&sB[pb][kk][tx * 4 + 2];
            float2 av[4] = {{a0.x, a0.y}, {a0.z, a0.w}, {a1.x, a1.y}, {a1.z, a1.w}};
            float2 bv[4] = {{b0.x, b0.y}, {b0.z, b0.w}, {b1.x, b1.y}, {b1.z, b1.w}};
#pragma unroll
            for (int ii = 0; ii < 4; ii++)
#pragma unroll
                for (int jj = 0; jj < 4; jj++) {
                    acc[ii][jj].x += av[ii].x * bv[jj].x - av[ii].y * bv[jj].y;
                    acc[ii][jj].y += av[ii].x * bv[jj].y + av[ii].y * bv[jj].x;
                }
        }
        if (ch < 7) {
            int nb = (ch + 1) & 1;
#pragma unroll
            for (int s = 0; s < 4; s++) {
                int e = tid + s * 256;
                int r = e >> 4, c = e & 15;
                sA[nb][c][r] = ra[s];
                int r2 = e >> 6, c2 = e & 63;
                sB[nb][r2][c2] = rb[s];
            }
            __syncthreads();
        }
    }
#pragma unroll
    for (int ii = 0; ii < 4; ii++)
#pragma unroll
        for (int jj = 0; jj < 4; jj++) {
            int i = i0 + ty * 4 + ii;
            int j = j0 + tx * 4 + jj;
            if (j >= J) continue;
            float2 v = acc[ii][jj];
            size_t idx = (ob + i) * J + j;
            float m = sqrtf(v.x * v.x + v.y * v.y);
            o1[idx] = m;
            o2[idx] = atan2f(v.y, v.x);
        }
}

// ---------------- k_invA: cMT(frft) + MxX0(rfft) + nyqC -------------------
__global__ void __launch_bounds__(256)
k_invA(const float2* __restrict__ Fc, const float2* __restrict__ Minv,
       float2* __restrict__ T,
       const float2* __restrict__ Fhi, const float2* __restrict__ F65,
       float2* __restrict__ T65) {
    int bid = blockIdx.x;
    int tid = threadIdx.x;
    if (bid >= 384) {
        __shared__ float2 sC[2][128];
        int half = tid >> 7, lane = tid & 127;
        int b = (bid - 384) * 2 + half;
        sC[half][lane] = F65[((size_t)b * 128 + lane) * JW + 64];
        __syncthreads();
        float ax = 0.f, ay = 0.f;
#pragma unroll 8
        for (int k = 0; k < 128; k++) {
            float2 m = Fhi[lane * 128 + k];
            float2 v = sC[half][k];
            ax += m.x * v.x - m.y * v.y;
            ay += m.x * v.y + m.y * v.x;
        }
        T65[((size_t)b * 128 + lane) * JW + 64] = make_float2(ax, ay);
        return;
    }
    __shared__ __align__(16) float2 sA[2][16][66];
    __shared__ __align__(16) float2 sB[2][16][66];
    int tx = tid & 15, ty = tid >> 4;
    float2 acc[4][4];
#pragma unroll
    for (int a = 0; a < 4; a++)
#pragma unroll
        for (int c = 0; c < 4; c++) acc[a][c] = make_float2(0.f, 0.f);
    if (bid < 256) {
        // cMT: T[b][i][j] = sum_k Fc[b][i][k] * Minv[j][k]
        int b = bid >> 2;
        int i0 = ((bid >> 1) & 1) * 64, j0 = (bid & 1) * 64;
        const float2* X = Fc + (size_t)b * 128 * 128;
        float2 ra[4], rb[4];
#pragma unroll
        for (int s = 0; s < 4; s++) {
            int e = tid + s * 256; int r = e >> 4, c = e & 15;
            ra[s] = X[(i0 + r) * 128 + c];
            rb[s] = Minv[(j0 + r) * 128 + c];
        }
#pragma unroll
        for (int s = 0; s < 4; s++) {
            int e = tid + s * 256; int r = e >> 4, c = e & 15;
            sA[0][c][r] = ra[s]; sB[0][c][r] = rb[s];
        }
        __syncthreads();
        for (int ch = 0; ch < 8; ch++) {
            if (ch < 7) {
                int kt = (ch + 1) * 16;
#pragma unroll
                for (int s = 0; s < 4; s++) {
                    int e = tid + s * 256; int r = e >> 4, c = e & 15;
                    ra[s] = X[(i0 + r) * 128 + kt + c];
                    rb[s] = Minv[(j0 + r) * 128 + kt + c];
                }
            }
            int pb = ch & 1;
#pragma unroll
            for (int kk = 0; kk < 16; kk++) {
                float4 a0 = *(const float4*)&sA[pb][kk][ty * 4];
                float4 a1 = *(const float4*)&sA[pb][kk][ty * 4 + 2];
                float4 b0 = *(const float4*)&sB[pb][kk][tx * 4];
                float4 b1 = *(const float4*)&sB[pb][kk][tx * 4 + 2];
                float2 av[4] = {{a0.x, a0.y}, {a0.z, a0.w}, {a1.x, a1.y}, {a1.z, a1.w}};
                float2 bv[4] = {{b0.x, b0.y}, {b0.z, b0.w}, {b1.x, b1.y}, {b1.z, b1.w}};
#pragma unroll
                for (int ii = 0; ii < 4; ii++)
#pragma unroll
                    for (int jj = 0; jj < 4; jj++) {
                        acc[ii][jj].x += av[ii].x * bv[jj].x - av[ii].y * bv[jj].y;
                        acc[ii][jj].y += av[ii].x * bv[jj].y + av[ii].y * bv[jj].x;
                    }
            }
            if (ch < 7) {
                int nb = (ch + 1) & 1;
#pragma unroll
                for (int s = 0; s < 4; s++) {
                    int e = tid + s * 256; int r = e >> 4, c = e & 15;
                    sA[nb][c][r] = ra[s]; sB[nb][c][r] = rb[s];
                }
                __syncthreads();
            }
        }
#pragma unroll
        for (int ii = 0; ii < 4; ii++)
#pragma unroll
            for (int jj = 0; jj < 4; jj++)
                T[((size_t)b * 128 + i0 + ty * 4 + ii) * 128 + j0 + tx * 4 + jj] = acc[ii][jj];
    } else {
        // MxX0: T65[b][i][j] = sum_k Fhi[i][k] * F65[b][k][j], j<64
        int r0 = bid - 256; int b = r0 >> 1;
        int i0 = (r0 & 1) * 64, j0 = 0;
        const float2* X = F65 + (size_t)b * 128 * JW;
        float2 ra[4], rb[4];
#pragma unroll
        for (int s = 0; s < 4; s++) {
            int e = tid + s * 256;
            int r = e >> 4, c = e & 15;
            ra[s] = Fhi[(i0 + r) * 128 + c];
            int r2 = e >> 6, c2 = e & 63;
            rb[s] = X[(size_t)r2 * JW + j0 + c2];
        }
#pragma unroll
        for (int s = 0; s < 4; s++) {
            int e = tid + s * 256;
            int r = e >> 4, c = e & 15;
            sA[0][c][r] = ra[s];
            int r2 = e >> 6, c2 = e & 63;
            sB[0][r2][c2] = rb[s];
        }
        __syncthreads();
        for (int ch = 0; ch < 8; ch++) {
            if (ch < 7) {
                int kt = (ch + 1) * 16;
#pragma unroll
                for (int s = 0; s < 4; s++) {
                    int e = tid + s * 256;
                    int r = e >> 4, c = e & 15;
                    ra[s] = Fhi[(i0 + r) * 128 + kt + c];
                    int r2 = e >> 6, c2 = e & 63;
                    rb[s] = X[(size_t)(kt + r2) * JW + j0 + c2];
                }
            }
            int pb = ch & 1;
#pragma unroll
            for (int kk = 0; kk < 16; kk++) {
                float4 a0 = *(const float4*)&sA[pb][kk][ty * 4];
                float4 a1 = *(const float4*)&sA[pb][kk][ty * 4 + 2];
                float4 b0 = *(const float4*)&sB[pb][kk][tx * 4];
                float4 b1 = *(const float4*)&sB[pb][kk][tx * 4 + 2];
                float2 av[4] = {{a0.x, a0.y}, {a0.z, a0.w}, {a1.x, a1.y}, {a1.z, a1.w}};
                float2 bv[4] = {{b0.x, b0.y}, {b0.z, b0.w}, {b1.x, b1.y}, {b1.z, b1.w}};
#pragma unroll
                for (int ii = 0; ii < 4; ii++)
#pragma unroll
                    for (int jj = 0; jj < 4; jj++) {
                        acc[ii][jj].x += av[ii].x * bv[jj].x - av[ii].y * bv[jj].y;
                        acc[ii][jj].y += av[ii].x * bv[jj].y + av[ii].y * bv[jj].x;
                    }
            }
            if (ch < 7) {
                int nb = (ch + 1) & 1;
#pragma unroll
                for (int s = 0; s < 4; s++) {
                    int e = tid + s * 256;
                    int r = e >> 4, c = e & 15;
                    sA[nb][c][r] = ra[s];
                    int r2 = e >> 6, c2 = e & 63;
                    sB[nb][r2][c2] = rb[s];
                }
                __syncthreads();
            }
        }
#pragma unroll
        for (int ii = 0; ii < 4; ii++)
#pragma unroll
            for (int jj = 0; jj < 4; jj++)
                T65[((size_t)b * 128 + i0 + ty * 4 + ii) * JW + j0 + tx * 4 + jj] = acc[ii][jj];
    }
}

// ---------------- k_invB: MxX2 (|.|->cat) + irfft_w -----------------------
__global__ void __launch_bounds__(256)
k_invB(const float2* __restrict__ Minv, const float2* __restrict__ T,
       float* __restrict__ cat, const float2* __restrict__ T65) {
    int bid = blockIdx.x;
    int tid = threadIdx.x;
    if (bid >= 256) {
        int r0 = bid - 256;
        int b = r0 >> 4;
        int hb = (r0 & 15) * 8;
        int tx = tid & 127, ty = tid >> 7;
        float acc[4] = {0.f, 0.f, 0.f, 0.f};
        for (int k = 0; k < JW; k++) {
            float2 bw = g_Bw[k * 128 + tx];
#pragma unroll
            for (int s = 0; s < 4; s++) {
                float2 a = T65[((size_t)b * 128 + hb + ty * 4 + s) * JW + k];
                acc[s] += a.x * bw.x - a.y * bw.y;
            }
        }
        int n = b >> 4, c = b & 15;
        float* Yp = cat + (size_t)(n * C1c + 32 + c) * PP;
#pragma unroll
        for (int s = 0; s < 4; s++)
            Yp[(hb + ty * 4 + s) * WW + tx] = acc[s];
        return;
    }
    __shared__ __align__(16) float2 sA[2][16][66];
    __shared__ __align__(16) float2 sB[2][16][66];
    int tx = tid & 15, ty = tid >> 4;
    int b = bid >> 2;
    int i0 = ((bid >> 1) & 1) * 64, j0 = (bid & 1) * 64;
    const float2* X = T + (size_t)b * 128 * 128;
    float2 acc[4][4];
#pragma unroll
    for (int a = 0; a < 4; a++)
#pragma unroll
        for (int c = 0; c < 4; c++) acc[a][c] = make_float2(0.f, 0.f);
    float2 ra[4], rb[4];
#pragma unroll
    for (int s = 0; s < 4; s++) {
        int e = tid + s * 256;
        int r = e >> 4, c = e & 15;
        ra[s] = Minv[(i0 + r) * 128 + c];
        int r2 = e >> 6, c2 = e & 63;
        rb[s] = X[(size_t)r2 * 128 + j0 + c2];
    }
#pragma unroll
    for (int s = 0; s < 4; s++) {
        int e = tid + s * 256;
        int r = e >> 4, c = e & 15;
        sA[0][c][r] = ra[s];
        int r2 = e >> 6, c2 = e & 63;
        sB[0][r2][c2] = rb[s];
    }
    __syncthreads();
    for (int ch = 0; ch < 8; ch++) {
        if (ch < 7) {
            int kt = (ch + 1) * 16;
#pragma unroll
            for (int s = 0; s < 4; s++) {
                int e = tid + s * 256;
                int r = e >> 4, c = e & 15;
                ra[s] = Minv[(i0 + r) * 128 + kt + c];
                int r2 = e >> 6, c2 = e & 63;
                rb[s] = X[(size_t)(kt + r2) * 128 + j0 + c2];
            }
        }
        int pb = ch & 1;
#pragma unroll
        for (int kk = 0; kk < 16; kk++) {
            float4 a0 = *(const float4*)&sA[pb][kk][ty * 4];
            float4 a1 = *(const float4*)&sA[pb][kk][ty * 4 + 2];
            float4 b0 = *(const float4*)&sB[pb][kk][tx * 4];
            float4 b1 = *(const float4*)&sB[pb][kk][tx * 4 + 2];
            float2 av[4] = {{a0.x, a0.y}, {a0.z, a0.w}, {a1.x, a1.y}, {a1.z, a1.w}};
            float2 bv[4] = {{b0.x, b0.y}, {b0.z, b0.w}, {b1.x, b1.y}, {b1.z, b1.w}};
#pragma unroll
            for (int ii = 0; ii < 4; ii++)
#pragma unroll
                for (int jj = 0; jj < 4; jj++) {
                    acc[ii][jj].x += av[ii].x * bv[jj].x - av[ii].y * bv[jj].y;
                    acc[ii][jj].y += av[ii].x * bv[jj].y + av[ii].y * bv[jj].x;
                }
        }
        if (ch < 7) {
            int nb = (ch + 1) & 1;
#pragma unroll
            for (int s = 0; s < 4; s++) {
                int e = tid + s * 256;
                int r = e >> 4, c = e & 15;
                sA[nb][c][r] = ra[s];
                int r2 = e >> 6, c2 = e & 63;
                sB[nb][r2][c2] = rb[s];
            }
            __syncthreads();
        }
    }
    int n = b >> 4, c = b & 15;
    float* O = cat + (size_t)(n * C1c + 16 + c) * PP;
#pragma unroll
    for (int ii = 0; ii < 4; ii++)
#pragma unroll
        for (int jj = 0; jj < 4; jj++) {
            float2 v = acc[ii][jj];
            O[(size_t)(i0 + ty * 4 + ii) * 128 + j0 + tx * 4 + jj] =
                sqrtf(v.x * v.x + v.y * v.y);
        }
}

// ---------------- 3x3 masked conv + magw + pha-mix + makec (inside px) ----
__global__ void __launch_bounds__(256)
k_conv3mF(const float* __restrict__ X, const float* __restrict__ Pha,
          const float* __restrict__ Wt, const float* __restrict__ Bs,
          const float* __restrict__ MagW, const float* __restrict__ MagB,
          const float* __restrict__ PhaW, const float* __restrict__ PhaB,
          float2* __restrict__ F) {
    __shared__ float sW[CMc * CMc * 9];
    __shared__ float sMW[256];
    __shared__ float sPW[256];
    __shared__ float sSB[16];
    __shared__ float sMB[16];
    __shared__ float sPB[16];
    __shared__ float sT[10][34];
    int tid = threadIdx.y * 32 + threadIdx.x;
    for (int e = tid; e < CMc * CMc * 9; e += 256) sW[e] = Wt[e];
    if (tid < 256) { sMW[tid] = MagW[tid]; sPW[tid] = PhaW[tid]; }
    if (tid < 16) { sSB[tid] = Bs[tid]; sMB[tid] = MagB[tid]; sPB[tid] = PhaB[tid]; }
    int n = blockIdx.z;
    int wb = blockIdx.x * 32, hb = 16 + blockIdx.y * 8;
    const float* Xn = X + (size_t)n * CMc * PP;
    float acc[CMc];
#pragma unroll
    for (int o = 0; o < CMc; o++) acc[o] = 0.f;
    for (int c = 0; c < CMc; c++) {
        __syncthreads();
        for (int e = tid; e < 340; e += 256) {
            int ly = e / 34, lx = e % 34;
            int gy = hb - 1 + ly, gx = wb - 1 + lx;
            float v = 0.f;
            if (gy >= 19 && gy < 109 && gx >= 19 && gx < 109)
                v = Xn[(size_t)c * PP + gy * WW + gx];
            sT[ly][lx] = v;
        }
        __syncthreads();
#pragma unroll
        for (int kh = 0; kh < 3; kh++)
#pragma unroll
            for (int kw = 0; kw < 3; kw++) {
                float xv = sT[threadIdx.y + kh][threadIdx.x + kw];
#pragma unroll
                for (int o = 0; o < CMc; o++)
                    acc[o] += sW[(o * CMc + c) * 9 + kh * 3 + kw] * xv;
            }
    }
    int h = hb + threadIdx.y, w = wb + threadIdx.x;
    if (h >= 19 && h < 109 && w >= 19 && w < 109) {
        int p = h * WW + w;
        size_t base = (size_t)n * 16 * PP;
#pragma unroll
        for (int m = 0; m < CMc; m++) acc[m] += sSB[m];
        float ph[16];
#pragma unroll
        for (int c = 0; c < 16; c++) ph[c] = Pha[base + (size_t)c * PP + p];
#pragma unroll
        for (int o = 0; o < CMc; o++) {
            float mo = sMB[o];
#pragma unroll
            for (int m = 0; m < CMc; m++) mo += sMW[o * 16 + m] * acc[m];
            float po = sPB[o];
#pragma unroll
            for (int c = 0; c < 16; c++) po += sPW[o * 16 + c] * ph[c];
            float sn, cs;
            __sincosf(po, &sn, &cs);
            F[base + (size_t)o * PP + p] = make_float2(mo * cs, mo * sn);
        }
    }
}

// ---------------- merged: phaO (blk 0..511) + fmfp (blk 512..771) ---------
__global__ void __launch_bounds__(128)
k_phaOF(const float* __restrict__ Pha, const float* __restrict__ Mag,
        const float* __restrict__ PhaW, const float* __restrict__ PhaB,
        float2* __restrict__ F,
        const float* __restrict__ Fm, const float* __restrict__ Fp,
        const float* __restrict__ W1, const float* __restrict__ B1,
        float2* __restrict__ F65) {
    int bid = blockIdx.x;
    int t = threadIdx.x;
    if (bid < 512) {
        __shared__ float sPW[256];
        __shared__ float sW2[256];
        __shared__ float sPB[16];
        __shared__ float sB2[16];
        sPW[t] = PhaW[t]; sPW[t + 128] = PhaW[t + 128];
        sW2[t] = g_W2[t]; sW2[t + 128] = g_W2[t + 128];
        if (t < 16)  { sPB[t] = PhaB[t]; sB2[t] = g_b2[t]; }
        __syncthreads();
        int n = bid >> 7;
        int p = (bid & 127) * 128 + t;
        int h = p >> 7, w = p & 127;
        if (h >= 19 && h < 109 && w >= 19 && w < 109) return;
        size_t base = (size_t)n * 16 * PP;
        float ph[16], mg[16];
#pragma unroll
        for (int c = 0; c < 16; c++) {
            ph[c] = Pha[base + (size_t)c * PP + p];
            mg[c] = Mag[base + (size_t)c * PP + p];
        }
#pragma unroll
        for (int o = 0; o < 16; o++) {
            float po = sPB[o];
            float m = sB2[o];
#pragma unroll
            for (int c = 0; c < 16; c++) {
                po += sPW[o * 16 + c] * ph[c];
                m  += sW2[o * 16 + c] * mg[c];
            }
            float sn, cs;
            __sincosf(po, &sn, &cs);
            F[base + (size_t)o * PP + p] = make_float2(m * cs, m * sn);
        }
    } else {
        __shared__ float sW[256];
        __shared__ float sB[16];
        sW[t] = W1[t]; sW[t + 128] = W1[t + 128];
        if (t < 16)  sB[t] = B1[t];
        __syncthreads();
        int r = bid - 512;
        int n = r / 65;
        int p = (r % 65) * 128 + t;
        if (p >= P65) return;
        size_t base = (size_t)n * 16 * P65;
        float fm[16], fp[16];
#pragma unroll
        for (int c = 0; c < 16; c++) {
            fm[c] = Fm[base + (size_t)c * P65 + p];
            fp[c] = Fp[base + (size_t)c * P65 + p];
        }
#pragma unroll
        for (int o = 0; o < 16; o++) {
            float mo = sB[o], po = sB[o];
#pragma unroll
            for (int c = 0; c < 16; c++) {
                mo += sW[o * 16 + c] * fm[c];
                po += sW[o * 16 + c] * fp[c];
            }
            float sn, cs;
            __sincosf(po, &sn, &cs);
            F65[base + (size_t)o * P65 + p] = make_float2(mo * cs, mo * sn);
        }
    }
}

// ---------------- launch ----------------
extern "C" void kernel_launch(void* const* d_in, const int* in_sizes, int n_in,
                              void* d_out, int out_size) {
    const float* x        = (const float*)d_in[0];
    const float* conv1_w  = (const float*)d_in[1];
    const float* mag_s_w  = (const float*)d_in[2];
    const float* mag_s_b  = (const float*)d_in[3];
    const float* mag_f_w  = (const float*)d_in[4];
    const float* mag_f_b  = (const float*)d_in[5];
    const float* mag_w    = (const float*)d_in[6];
    const float* mag_b    = (const float*)d_in[7];
    const float* pha_w    = (const float*)d_in[8];
    const float* pha_b    = (const float*)d_in[9];
    const float* conv_0_w = (const float*)d_in[10];
    const float* conv_0_b = (const float*)d_in[11];
    const float* conv_1_w = (const float*)d_in[12];
    const float* conv_1_b = (const float*)d_in[13];
    const float* conv2_w  = (const float*)d_in[14];
    float* out = (float*)d_out;

    float  *px1, *pmag, *ppha, *pfm, *pfp, *pcat;
    float2 *pM, *pMinv, *pFh, *pFhi, *pFw, *pT, *pF, *pT65, *pF65;
    cudaGetSymbolAddress((void**)&px1,    g_x1);
    cudaGetSymbolAddress((void**)&pmag,   g_mag);
    cudaGetSymbolAddress((void**)&ppha,   g_pha);
    cudaGetSymbolAddress((void**)&pfm,    g_fm);
    cudaGetSymbolAddress((void**)&pfp,    g_fp);
    cudaGetSymbolAddress((void**)&pcat,   g_cat);
    cudaGetSymbolAddress((void**)&pM,     g_M);
    cudaGetSymbolAddress((void**)&pMinv,  g_Minv);
    cudaGetSymbolAddress((void**)&pFh,    g_Fh);
    cudaGetSymbolAddress((void**)&pFhi,   g_Fhi);
    cudaGetSymbolAddress((void**)&pFw,    g_Fw);
    cudaGetSymbolAddress((void**)&pT,     g_T);
    cudaGetSymbolAddress((void**)&pF,     g_F);
    cudaGetSymbolAddress((void**)&pT65,   g_T65);
    cudaGetSymbolAddress((void**)&pF65,   g_F65);

    k_init <<<128, 256>>>();
    k_init2<<<141, 512>>>(conv2_w, conv_0_w, conv_0_b, mag_w, mag_f_w, mag_f_b, mag_b);

    k_g1x1<<<dim3(32, 3, NB), 128>>>(x, conv1_w, px1, 192, 192 * PP, 48 * PP);

    k_rxMT64D<<<384, 256>>>(px1, pM, pT, pFw, pT65);
    k_MxXD<<<416, 256>>>(px1, pM, pT, pmag, ppha, pFh, pT65, pfm, pfp);

    k_conv3mF<<<dim3(4, 12, NB), dim3(32, 8)>>>(pmag, ppha, mag_s_w, mag_s_b,
                                                mag_w, mag_b, pha_w, pha_b, pF);
    k_phaOF<<<772, 128>>>(ppha, pmag, pha_w, pha_b, pF,
                          pfm, pfp, conv_1_w, conv_1_b, pF65);

    k_invA<<<416, 256>>>(pF, pMinv, pT, pFhi, pF65, pT65);
    k_invB<<<1280, 256>>>(pMinv, pT, pcat, pT65);

    k_conv2<<<dim3(32, 12, NB), 128>>>(px1, pcat, conv2_w, out);
}

// round 15
// speedup vs baseline: 2.3030x; 1.0572x over previous
#include <cuda_runtime.h>
#include <math.h>

#define NB   4
#define CIN  192
#define HH   128
#define WW   128
#define PP   (HH*WW)       // 16384
#define C1c  48
#define C0c  16
#define CMc  16
#define BATCH 64           // NB * CMc
#define JW   65
#define P65  (128*JW)      // 8320

// ---------------- device scratch ----------------
static __device__ float2  g_M   [128*128];
static __device__ float2  g_Cm  [128*128];
static __device__ float2  g_Minv[128*128];
static __device__ float2  g_Fh  [128*128];
static __device__ float2  g_Fhi [128*128];
static __device__ float2  g_Fw  [JW*128];
static __device__ float2  g_Bw  [JW*128];

static __device__ float   g_W2[256];
static __device__ float   g_b2[16];
static __device__ float   g_Wc[192*16];
static __device__ float   g_bc[192];

static __device__ float   g_x1 [NB*C1c*PP];
static __device__ float2  g_T  [BATCH*128*128];
static __device__ float2  g_F  [BATCH*128*128];
static __device__ float   g_mag[BATCH*PP];
static __device__ float   g_pha[BATCH*PP];
static __device__ float2  g_T65[BATCH*P65];
static __device__ float2  g_F65[BATCH*P65];
static __device__ float   g_fm[BATCH*P65];
static __device__ float   g_fp[BATCH*P65];
static __device__ float   g_cat[NB*C1c*PP];

// ---------------- k_init ----------------
__global__ void __launch_bounds__(256) k_init() {
    int bid = blockIdx.x, t = threadIdx.x;
    const double PI = 3.14159265358979323846;
    if (bid < 64) {
        int idx = bid * 256 + t;
        {
            int u = idx >> 7, v = idx & 127;
            int e1 = ((u + 64) * (v + 64)) & 127;
            double s, c; sincospi(2.0 * e1 / 128.0, &s, &c);
            double inv = 1.0 / sqrt(128.0);
            g_Cm[idx] = make_float2((float)(c * inv), (float)(s * inv));
            int e2 = (u * v) & 127;
            double s2, c2; sincospi(-2.0 * e2 / 128.0, &s2, &c2);
            g_Fh[idx] = make_float2((float)c2, (float)s2);
            double s3, c3; sincospi(2.0 * e2 / 128.0, &s3, &c3);
            g_Fhi[idx] = make_float2((float)(c3 / 128.0), (float)(s3 / 128.0));
        }
        if (idx < JW * 128) {
            int k = idx / 128, w = idx & 127;
            int e = (k * w) & 127;
            double s, c; sincospi(-2.0 * e / 128.0, &s, &c);
            g_Fw[idx] = make_float2((float)c, (float)s);
            float2 bw;
            if (k == 0)       bw = make_float2(1.0f / 128.0f, 0.f);
            else if (k == 64) bw = make_float2(((w & 1) ? -1.0f : 1.0f) / 128.0f, 0.f);
            else {
                double s4, c4; sincospi(2.0 * e / 128.0, &s4, &c4);
                bw = make_float2((float)(c4 * 2.0 / 128.0), (float)(s4 * 2.0 / 128.0));
            }
            g_Bw[idx] = bw;
        }
    } else {
        __shared__ float2 sC1[255];
        __shared__ float2 sE[509];
        __shared__ float  sS[509];
        __shared__ float2 sFac[2];
        int B = bid - 64;
        double tana2 = tan(PI / 8.0);
        double sina  = sin(PI / 4.0);
        double coef  = tana2 / 512.0;
        double ec    = 1.0 / (512.0 * sina);
        for (int j = t; j < 255; j += 256) {
            double n = (double)(j - 127);
            double s, c; sincospi(-coef * n * n, &s, &c);
            sC1[j] = make_float2((float)c, (float)s);
        }
        for (int i = t; i < 509; i += 256) {
            double d = (double)(i - 254);
            double s, c; sincospi(ec * d * d, &s, &c);
            sE[i] = make_float2((float)c, (float)s);
            int m = i - 254;
            double sv;
            if (m == 0) sv = 1.0;
            else if ((m & 1) == 0) sv = 0.0;
            else {
                double x = 0.5 * (double)m;
                sv = sinpi(x) / (PI * x);
            }
            sS[i] = (float)sv;
        }
        if (t < 2) {
            double amp = sqrt(1.0 / (512.0 * sina));
            double ps, pc; sincospi(-0.125, &ps, &pc);
            int r = 2 * B + t;
            double n = 2.0 * r - 127.0;
            double s, c; sincospi(-coef * n * n, &s, &c);
            sFac[t] = make_float2((float)(amp * (pc * c - ps * s)),
                                  (float)(amp * (pc * s + ps * c)));
        }
        __syncthreads();
        int idx = B * 256 + t;
        int r = idx >> 7, k = idx & 127;
        float ax = 0.f, ay = 0.f;
        {
            int j = 2 * k;
            float2 c1 = sC1[j];
            float2 e  = sE[2 * r - j + 254];
            ax += c1.x * e.x - c1.y * e.y;
            ay += c1.x * e.y + c1.y * e.x;
        }
        for (int j = 1; j < 255; j += 2) {
            float s = sS[j - 2 * k + 254];
            float2 c1 = sC1[j];
            float2 e  = sE[2 * r - j + 254];
            ax += (c1.x * e.x - c1.y * e.y) * s;
            ay += (c1.x * e.y + c1.y * e.x) * s;
        }
        float2 f = sFac[r - 2 * B];
        g_M[idx] = make_float2(f.x * ax - f.y * ay, f.x * ay + f.y * ax);
    }
}

// ---------------- k_init2 ----------------
__global__ void __launch_bounds__(512) k_init2(
        const float* __restrict__ conv2w, const float* __restrict__ conv0w,
        const float* __restrict__ conv0b,
        const float* __restrict__ magw, const float* __restrict__ magf,
        const float* __restrict__ magfb, const float* __restrict__ magb) {
    int bid = blockIdx.x, t = threadIdx.x;
    if (bid < 128) {
        __shared__ float2 sM[128];
        __shared__ float2 sP[512];
        int r = bid;
        int v = t & 127, seg = t >> 7;
        if (t < 128) sM[t] = g_M[r * 128 + t];
        __syncthreads();
        float ax = 0.f, ay = 0.f;
        int u0 = seg * 32;
#pragma unroll 8
        for (int u = u0; u < u0 + 32; u++) {
            float2 a = sM[u];
            float2 b = g_Cm[u * 128 + v];
            ax += a.x * b.x - a.y * b.y;
            ay += a.x * b.y + a.y * b.x;
        }
        sP[t] = make_float2(ax, ay);
        __syncthreads();
        if (t < 128) {
            float2 p0 = sP[t], p1 = sP[t + 128], p2 = sP[t + 256], p3 = sP[t + 384];
            g_Minv[r * 128 + v] = make_float2(p0.x + p1.x + p2.x + p3.x,
                                              p0.y + p1.y + p2.y + p3.y);
        }
    } else if (bid < 140) {
        if (t >= 256) return;
        int idx = (bid - 128) * 256 + t;
        if (idx < 192 * 16) {
            int o = idx >> 4, c = idx & 15;
            float a = 0.f;
#pragma unroll
            for (int m = 0; m < 16; m++) a += conv2w[o * 48 + m] * conv0w[m * 16 + c];
            g_Wc[idx] = a;
        }
        if (idx < 192) {
            float b = 0.f;
#pragma unroll
            for (int m = 0; m < 16; m++) b += conv2w[idx * 48 + m] * conv0b[m];
            g_bc[idx] = b;
        }
    } else {
        if (t >= 256) return;
        int o = t >> 4, c = t & 15;
        float a = 0.f;
#pragma unroll
        for (int m = 0; m < 16; m++) a += magw[o * 16 + m] * magf[m * 16 + c];
        g_W2[t] = a;
        if (t < 16) {
            float b = magb[t];
#pragma unroll
            for (int m = 0; m < 16; m++) b += magw[t * 16 + m] * magfb[m];
            g_b2[t] = b;
        }
    }
}

// ---------------- conv1 (float4) ----------------
__global__ void __launch_bounds__(128)
k_g1x1(const float* __restrict__ X, const float* __restrict__ Wt,
       float* __restrict__ Y, int Cc, int xStrideN, int yStrideN) {
    __shared__ float sW[16 * 192];
    int n = blockIdx.z, ob = blockIdx.y * 16;
    int tx = threadIdx.x;
    for (int e = tx; e < 16 * Cc; e += 128) sW[e] = Wt[ob * Cc + e];
    __syncthreads();
    const float* Xn = X + (size_t)n * xStrideN;
    int p4 = blockIdx.x * 512 + tx * 4;
    float acc[16][4];
#pragma unroll
    for (int o = 0; o < 16; o++)
#pragma unroll
        for (int s = 0; s < 4; s++) acc[o][s] = 0.f;
#pragma unroll 4
    for (int c = 0; c < Cc; c++) {
        float4 xv = *(const float4*)&Xn[(size_t)c * PP + p4];
#pragma unroll
        for (int o = 0; o < 16; o++) {
            float w = sW[o * Cc + c];
            acc[o][0] += w * xv.x; acc[o][1] += w * xv.y;
            acc[o][2] += w * xv.z; acc[o][3] += w * xv.w;
        }
    }
#pragma unroll
    for (int o = 0; o < 16; o++) {
        float4 r = make_float4(acc[o][0], acc[o][1], acc[o][2], acc[o][3]);
        *(float4*)&Y[(size_t)n * yStrideN + (size_t)(ob + o) * PP + p4] = r;
    }
}

// ---------------- conv2 (folded conv_0, float4) ----------------
__global__ void __launch_bounds__(128)
k_conv2(const float* __restrict__ X1, const float* __restrict__ Cat,
        const float* __restrict__ conv2w, float* __restrict__ Y) {
    __shared__ float sWa[16 * 16];
    __shared__ float sWb[16 * 32];
    __shared__ float sB[16];
    int n = blockIdx.z, ob = blockIdx.y * 16;
    int tx = threadIdx.x;
    for (int e = tx; e < 256; e += 128)
        sWa[e] = g_Wc[(ob + (e >> 4)) * 16 + (e & 15)];
    for (int e = tx; e < 512; e += 128) {
        int o = e >> 5, c = e & 31;
        sWb[e] = conv2w[(ob + o) * 48 + 16 + c];
    }
    if (tx < 16) sB[tx] = g_bc[ob + tx];
    __syncthreads();
    const float* Xn = X1 + (size_t)n * 48 * PP;
    const float* Cn = Cat + (size_t)n * 48 * PP + (size_t)16 * PP;
    int p4 = blockIdx.x * 512 + tx * 4;
    float acc[16][4];
#pragma unroll
    for (int o = 0; o < 16; o++)
#pragma unroll
        for (int s = 0; s < 4; s++) acc[o][s] = 0.f;
#pragma unroll 4
    for (int c = 0; c < 16; c++) {
        float4 xv = *(const float4*)&Xn[(size_t)c * PP + p4];
#pragma unroll
        for (int o = 0; o < 16; o++) {
            float w = sWa[o * 16 + c];
            acc[o][0] += w * xv.x; acc[o][1] += w * xv.y;
            acc[o][2] += w * xv.z; acc[o][3] += w * xv.w;
        }
    }
#pragma unroll 4
    for (int c = 0; c < 32; c++) {
        float4 xv = *(const float4*)&Cn[(size_t)c * PP + p4];
#pragma unroll
        for (int o = 0; o < 16; o++) {
            float w = sWb[o * 32 + c];
            acc[o][0] += w * xv.x; acc[o][1] += w * xv.y;
            acc[o][2] += w * xv.z; acc[o][3] += w * xv.w;
        }
    }
#pragma unroll
    for (int o = 0; o < 16; o++) {
        float4 r = make_float4(acc[o][0] + sB[o], acc[o][1] + sB[o],
                               acc[o][2] + sB[o], acc[o][3] + sB[o]);
        *(float4*)&Y[(size_t)n * 192 * PP + (size_t)(ob + o) * PP + p4] = r;
    }
}

// ---------------- 8x4 micro-tile compute steps ----------------------------
__device__ __forceinline__ void cstep(const float2 (&A)[16][66], const float2 (&B)[16][66],
                                      int ty, int tx, float2 (&acc)[8][4]) {
#pragma unroll 4
    for (int kk = 0; kk < 16; kk++) {
        float4 t0 = *(const float4*)&A[kk][ty * 8];
        float4 t1 = *(const float4*)&A[kk][ty * 8 + 2];
        float4 t2 = *(const float4*)&A[kk][ty * 8 + 4];
        float4 t3 = *(const float4*)&A[kk][ty * 8 + 6];
        float4 u0 = *(const float4*)&B[kk][tx * 4];
        float4 u1 = *(const float4*)&B[kk][tx * 4 + 2];
        float2 av[8] = {{t0.x,t0.y},{t0.z,t0.w},{t1.x,t1.y},{t1.z,t1.w},
                        {t2.x,t2.y},{t2.z,t2.w},{t3.x,t3.y},{t3.z,t3.w}};
        float2 bv[4] = {{u0.x,u0.y},{u0.z,u0.w},{u1.x,u1.y},{u1.z,u1.w}};
#pragma unroll
        for (int ii = 0; ii < 8; ii++)
#pragma unroll
            for (int jj = 0; jj < 4; jj++) {
                acc[ii][jj].x += av[ii].x * bv[jj].x - av[ii].y * bv[jj].y;
                acc[ii][jj].y += av[ii].x * bv[jj].y + av[ii].y * bv[jj].x;
            }
    }
}

__device__ __forceinline__ void rstep(const float (&A)[16][68], const float2 (&B)[16][66],
                                      int ty, int tx, float2 (&acc)[8][4]) {
#pragma unroll 4
    for (int kk = 0; kk < 16; kk++) {
        float4 t0 = *(const float4*)&A[kk][ty * 8];
        float4 t1 = *(const float4*)&A[kk][ty * 8 + 4];
        float4 u0 = *(const float4*)&B[kk][tx * 4];
        float4 u1 = *(const float4*)&B[kk][tx * 4 + 2];
        float av[8] = {t0.x, t0.y, t0.z, t0.w, t1.x, t1.y, t1.z, t1.w};
        float2 bv[4] = {{u0.x,u0.y},{u0.z,u0.w},{u1.x,u1.y},{u1.z,u1.w}};
#pragma unroll
        for (int ii = 0; ii < 8; ii++)
#pragma unroll
            for (int jj = 0; jj < 4; jj++) {
                acc[ii][jj].x += av[ii] * bv[jj].x;
                acc[ii][jj].y += av[ii] * bv[jj].y;
            }
    }
}

// ---------------- merged rxMT (128 thr, 8x4 micro) ------------------------
__global__ void __launch_bounds__(128)
k_rxMT64D(const float* __restrict__ X1,
          const float2* __restrict__ Ma, float2* __restrict__ Ya,
          const float2* __restrict__ Mb, float2* __restrict__ Yb) {
    int bid = blockIdx.x;
    const float* X; const float2* M; float2* Y; int J, j0, i0;
    if (bid < 256) {
        int b = bid >> 2;
        i0 = ((bid >> 1) & 1) * 64; j0 = (bid & 1) * 64;
        X = X1 + (size_t)((b >> 4) * C1c + 16 + (b & 15)) * PP;
        M = Ma; Y = Ya + (size_t)b * 128 * 128; J = 128;
    } else {
        int r = bid - 256; int b = r >> 1;
        i0 = (r & 1) * 64; j0 = 0;
        X = X1 + (size_t)((b >> 4) * C1c + 32 + (b & 15)) * PP;
        M = Mb; Y = Yb + (size_t)b * 128 * JW; J = JW;
    }
    __shared__ __align__(16) float  sA[2][16][68];
    __shared__ __align__(16) float2 sB[2][16][66];
    int tid = threadIdx.x, tx = tid & 15, ty = tid >> 4;
    float2 acc[8][4];
#pragma unroll
    for (int a = 0; a < 8; a++)
#pragma unroll
        for (int c = 0; c < 4; c++) acc[a][c] = make_float2(0.f, 0.f);
    float ra[8]; float2 rb[8];
#pragma unroll
    for (int s = 0; s < 8; s++) {
        int e = tid + s * 128; int r = e >> 4, c = e & 15;
        ra[s] = X[(i0 + r) * 128 + c];
        rb[s] = M[(j0 + r) * 128 + c];
    }
#pragma unroll
    for (int s = 0; s < 8; s++) {
        int e = tid + s * 128; int r = e >> 4, c = e & 15;
        sA[0][c][r] = ra[s]; sB[0][c][r] = rb[s];
    }
    __syncthreads();
    for (int ch = 0; ch < 8; ch++) {
        if (ch < 7) {
            int kt = (ch + 1) * 16;
#pragma unroll
            for (int s = 0; s < 8; s++) {
                int e = tid + s * 128; int r = e >> 4, c = e & 15;
                ra[s] = X[(i0 + r) * 128 + kt + c];
                rb[s] = M[(j0 + r) * 128 + kt + c];
            }
        }
        rstep(sA[ch & 1], sB[ch & 1], ty, tx, acc);
        if (ch < 7) {
            int nb = (ch + 1) & 1;
#pragma unroll
            for (int s = 0; s < 8; s++) {
                int e = tid + s * 128; int r = e >> 4, c = e & 15;
                sA[nb][c][r] = ra[s]; sB[nb][c][r] = rb[s];
            }
            __syncthreads();
        }
    }
#pragma unroll
    for (int ii = 0; ii < 8; ii++)
#pragma unroll
        for (int jj = 0; jj < 4; jj++)
            Y[(size_t)(i0 + ty * 8 + ii) * J + j0 + tx * 4 + jj] = acc[ii][jj];
}

// ---------------- merged MxX (mag/pha epilogue) + nyqB --------------------
__global__ void __launch_bounds__(128)
k_MxXD(const float* __restrict__ X1,
       const float2* __restrict__ Ma, const float2* __restrict__ Xa,
       float* __restrict__ m1, float* __restrict__ p1,
       const float2* __restrict__ Mb, const float2* __restrict__ Xb,
       float* __restrict__ m2, float* __restrict__ p2) {
    int bid = blockIdx.x;
    int tid = threadIdx.x;
    if (bid >= 384) {
        __shared__ float sTn[128];
        int b = bid - 384;
        const float* X = X1 + (size_t)((b >> 4) * C1c + 32 + (b & 15)) * PP;
        float s = 0.f;
        const float* row = X + tid * 128;
#pragma unroll 16
        for (int w = 0; w < 128; w += 2) s += row[w] - row[w + 1];
        sTn[tid] = s;
        __syncthreads();
        float ax = 0.f, ay = 0.f;
#pragma unroll 8
        for (int k = 0; k < 128; k++) {
            float2 f = Mb[tid * 128 + k];
            float v = sTn[k];
            ax += f.x * v; ay += f.y * v;
        }
        size_t idx = ((size_t)b * 128 + tid) * JW + 64;
        m2[idx] = sqrtf(ax * ax + ay * ay);
        p2[idx] = atan2f(ay, ax);
        return;
    }
    const float2* M; const float2* X; float* o1; float* o2; int J, j0, i0; size_t ob;
    if (bid < 256) {
        int b = bid >> 2;
        i0 = ((bid >> 1) & 1) * 64; j0 = (bid & 1) * 64;
        M = Ma; X = Xa + (size_t)b * 128 * 128; J = 128;
        o1 = m1; o2 = p1; ob = (size_t)b * 128;
    } else {
        int r = bid - 256; int b = r >> 1;
        i0 = (r & 1) * 64; j0 = 0;
        M = Mb; X = Xb + (size_t)b * 128 * JW; J = JW;
        o1 = m2; o2 = p2; ob = (size_t)b * 128;
    }
    __shared__ __align__(16) float2 sA[2][16][66];
    __shared__ __align__(16) float2 sB[2][16][66];
    int tx = tid & 15, ty = tid >> 4;
    float2 acc[8][4];
#pragma unroll
    for (int a = 0; a < 8; a++)
#pragma unroll
        for (int c = 0; c < 4; c++) acc[a][c] = make_float2(0.f, 0.f);
    float2 ra[8], rb[8];
#pragma unroll
    for (int s = 0; s < 8; s++) {
        int e = tid + s * 128;
        int r = e >> 4, c = e & 15;
        ra[s] = M[(i0 + r) * 128 + c];
        int r2 = e >> 6, c2 = e & 63;
        rb[s] = X[(size_t)r2 * J + j0 + c2];
    }
#pragma unroll
    for (int s = 0; s < 8; s++) {
        int e = tid + s * 128;
        int r = e >> 4, c = e & 15;
        sA[0][c][r] = ra[s];
        int r2 = e >> 6, c2 = e & 63;
        sB[0][r2][c2] = rb[s];
    }
    __syncthreads();
    for (int ch = 0; ch < 8; ch++) {
        if (ch < 7) {
            int kt = (ch + 1) * 16;
#pragma unroll
            for (int s = 0; s < 8; s++) {
                int e = tid + s * 128;
                int r = e >> 4, c = e & 15;
                ra[s] = M[(i0 + r) * 128 + kt + c];
                int r2 = e >> 6, c2 = e & 63;
                rb[s] = X[(size_t)(kt + r2) * J + j0 + c2];
            }
        }
        cstep(sA[ch & 1], sB[ch & 1], ty, tx, acc);
        if (ch < 7) {
            int nb = (ch + 1) & 1;
#pragma unroll
            for (int s = 0; s < 8; s++) {
                int e = tid + s * 128;
                int r = e >> 4, c = e & 15;
                sA[nb][c][r] = ra[s];
                int r2 = e >> 6, c2 = e & 63;
                sB[nb][r2][c2] = rb[s];
            }
            __syncthreads();
        }
    }
#pragma unroll
    for (int ii = 0; ii < 8; ii++)
#pragma unroll
        for (int jj = 0; jj < 4; jj++) {
            int i = i0 + ty * 8 + ii;
            int j = j0 + tx * 4 + jj;
            float2 v = acc[ii][jj];
            size_t idx = (ob + i) * J + j;
            float m = sqrtf(v.x * v.x + v.y * v.y);
            o1[idx] = m;
            o2[idx] = atan2f(v.y, v.x);
        }
}

// ---------------- k_invA: cMT(frft) + MxX0(rfft) + nyqC -------------------
__global__ void __launch_bounds__(128)
k_invA(const float2* __restrict__ Fc, const float2* __restrict__ Minv,
       float2* __restrict__ T,
       const float2* __restrict__ Fhi, const float2* __restrict__ F65,
       float2* __restrict__ T65) {
    int bid = blockIdx.x;
    int tid = threadIdx.x;
    if (bid >= 384) {
        __shared__ float2 sC[128];
        int b = bid - 384;
        sC[tid] = F65[((size_t)b * 128 + tid) * JW + 64];
        __syncthreads();
        float ax = 0.f, ay = 0.f;
#pragma unroll 8
        for (int k = 0; k < 128; k++) {
            float2 m = Fhi[tid * 128 + k];
            float2 v = sC[k];
            ax += m.x * v.x - m.y * v.y;
            ay += m.x * v.y + m.y * v.x;
        }
        T65[((size_t)b * 128 + tid) * JW + 64] = make_float2(ax, ay);
        return;
    }
    __shared__ __align__(16) float2 sA[2][16][66];
    __shared__ __align__(16) float2 sB[2][16][66];
    int tx = tid & 15, ty = tid >> 4;
    float2 acc[8][4];
#pragma unroll
    for (int a = 0; a < 8; a++)
#pragma unroll
        for (int c = 0; c < 4; c++) acc[a][c] = make_float2(0.f, 0.f);
    if (bid < 256) {
        // cMT: T[b][i][j] = sum_k Fc[b][i][k] * Minv[j][k]
        int b = bid >> 2;
        int i0 = ((bid >> 1) & 1) * 64, j0 = (bid & 1) * 64;
        const float2* X = Fc + (size_t)b * 128 * 128;
        float2 ra[8], rb[8];
#pragma unroll
        for (int s = 0; s < 8; s++) {
            int e = tid + s * 128; int r = e >> 4, c = e & 15;
            ra[s] = X[(i0 + r) * 128 + c];
            rb[s] = Minv[(j0 + r) * 128 + c];
        }
#pragma unroll
        for (int s = 0; s < 8; s++) {
            int e = tid + s * 128; int r = e >> 4, c = e & 15;
            sA[0][c][r] = ra[s]; sB[0][c][r] = rb[s];
        }
        __syncthreads();
        for (int ch = 0; ch < 8; ch++) {
            if (ch < 7) {
                int kt = (ch + 1) * 16;
#pragma unroll
                for (int s = 0; s < 8; s++) {
                    int e = tid + s * 128; int r = e >> 4, c = e & 15;
                    ra[s] = X[(i0 + r) * 128 + kt + c];
                    rb[s] = Minv[(j0 + r) * 128 + kt + c];
                }
            }
            cstep(sA[ch & 1], sB[ch & 1], ty, tx, acc);
            if (ch < 7) {
                int nb = (ch + 1) & 1;
#pragma unroll
                for (int s = 0; s < 8; s++) {
                    int e = tid + s * 128; int r = e >> 4, c = e & 15;
                    sA[nb][c][r] = ra[s]; sB[nb][c][r] = rb[s];
                }
                __syncthreads();
            }
        }
#pragma unroll
        for (int ii = 0; ii < 8; ii++)
#pragma unroll
            for (int jj = 0; jj < 4; jj++)
                T[((size_t)b * 128 + i0 + ty * 8 + ii) * 128 + j0 + tx * 4 + jj] = acc[ii][jj];
    } else {
        // MxX0: T65[b][i][j] = sum_k Fhi[i][k] * F65[b][k][j], j<64
        int r0 = bid - 256; int b = r0 >> 1;
        int i0 = (r0 & 1) * 64;
        const float2* X = F65 + (size_t)b * 128 * JW;
        float2 ra[8], rb[8];
#pragma unroll
        for (int s = 0; s < 8; s++) {
            int e = tid + s * 128;
            int r = e >> 4, c = e & 15;
            ra[s] = Fhi[(i0 + r) * 128 + c];
            int r2 = e >> 6, c2 = e & 63;
            rb[s] = X[(size_t)r2 * JW + c2];
        }
#pragma unroll
        for (int s = 0; s < 8; s++) {
            int e = tid + s * 128;
            int r = e >> 4, c = e & 15;
            sA[0][c][r] = ra[s];
            int r2 = e >> 6, c2 = e & 63;
            sB[0][r2][c2] = rb[s];
        }
        __syncthreads();
        for (int ch = 0; ch < 8; ch++) {
            if (ch < 7) {
                int kt = (ch + 1) * 16;
#pragma unroll
                for (int s = 0; s < 8; s++) {
                    int e = tid + s * 128;
                    int r = e >> 4, c = e & 15;
                    ra[s] = Fhi[(i0 + r) * 128 + kt + c];
                    int r2 = e >> 6, c2 = e & 63;
                    rb[s] = X[(size_t)(kt + r2) * JW + c2];
                }
            }
            cstep(sA[ch & 1], sB[ch & 1], ty, tx, acc);
            if (ch < 7) {
                int nb = (ch + 1) & 1;
#pragma unroll
                for (int s = 0; s < 8; s++) {
                    int e = tid + s * 128;
                    int r = e >> 4, c = e & 15;
                    sA[nb][c][r] = ra[s];
                    int r2 = e >> 6, c2 = e & 63;
                    sB[nb][r2][c2] = rb[s];
                }
                __syncthreads();
            }
        }
#pragma unroll
        for (int ii = 0; ii < 8; ii++)
#pragma unroll
            for (int jj = 0; jj < 4; jj++)
                T65[((size_t)b * 128 + i0 + ty * 8 + ii) * JW + tx * 4 + jj] = acc[ii][jj];
    }
}

// ---------------- k_invB: MxX2 (|.|->cat) + irfft_w -----------------------
__global__ void __launch_bounds__(128)
k_invB(const float2* __restrict__ Minv, const float2* __restrict__ T,
       float* __restrict__ cat, const float2* __restrict__ T65) {
    int bid = blockIdx.x;
    int tid = threadIdx.x;
    if (bid >= 256) {
        int r0 = bid - 256;
        int b = r0 >> 5;
        int hb = (r0 & 31) * 4;
        float acc[4] = {0.f, 0.f, 0.f, 0.f};
        for (int k = 0; k < JW; k++) {
            float2 bw = g_Bw[k * 128 + tid];
#pragma unroll
            for (int s = 0; s < 4; s++) {
                float2 a = T65[((size_t)b * 128 + hb + s) * JW + k];
                acc[s] += a.x * bw.x - a.y * bw.y;
            }
        }
        int n = b >> 4, c = b & 15;
        float* Yp = cat + (size_t)(n * C1c + 32 + c) * PP;
#pragma unroll
        for (int s = 0; s < 4; s++)
            Yp[(hb + s) * WW + tid] = acc[s];
        return;
    }
    __shared__ __align__(16) float2 sA[2][16][66];
    __shared__ __align__(16) float2 sB[2][16][66];
    int tx = tid & 15, ty = tid >> 4;
    int b = bid >> 2;
    int i0 = ((bid >> 1) & 1) * 64, j0 = (bid & 1) * 64;
    const float2* X = T + (size_t)b * 128 * 128;
    float2 acc[8][4];
#pragma unroll
    for (int a = 0; a < 8; a++)
#pragma unroll
        for (int c = 0; c < 4; c++) acc[a][c] = make_float2(0.f, 0.f);
    float2 ra[8], rb[8];
#pragma unroll
    for (int s = 0; s < 8; s++) {
        int e = tid + s * 128;
        int r = e >> 4, c = e & 15;
        ra[s] = Minv[(i0 + r) * 128 + c];
        int r2 = e >> 6, c2 = e & 63;
        rb[s] = X[(size_t)r2 * 128 + j0 + c2];
    }
#pragma unroll
    for (int s = 0; s < 8; s++) {
        int e = tid + s * 128;
        int r = e >> 4, c = e & 15;
        sA[0][c][r] = ra[s];
        int r2 = e >> 6, c2 = e & 63;
        sB[0][r2][c2] = rb[s];
    }
    __syncthreads();
    for (int ch = 0; ch < 8; ch++) {
        if (ch < 7) {
            int kt = (ch + 1) * 16;
#pragma unroll
            for (int s = 0; s < 8; s++) {
                int e = tid + s * 128;
                int r = e >> 4, c = e & 15;
                ra[s] = Minv[(i0 + r) * 128 + kt + c];
                int r2 = e >> 6, c2 = e & 63;
                rb[s] = X[(size_t)(kt + r2) * 128 + j0 + c2];
            }
        }
        cstep(sA[ch & 1], sB[ch & 1], ty, tx, acc);
        if (ch < 7) {
            int nb = (ch + 1) & 1;
#pragma unroll
            for (int s = 0; s < 8; s++) {
                int e = tid + s * 128;
                int r = e >> 4, c = e & 15;
                sA[nb][c][r] = ra[s];
                int r2 = e >> 6, c2 = e & 63;
                sB[nb][r2][c2] = rb[s];
            }
            __syncthreads();
        }
    }
    int n = b >> 4, c = b & 15;
    float* O = cat + (size_t)(n * C1c + 16 + c) * PP;
#pragma unroll
    for (int ii = 0; ii < 8; ii++)
#pragma unroll
        for (int jj = 0; jj < 4; jj++) {
            float2 v = acc[ii][jj];
            O[(size_t)(i0 + ty * 8 + ii) * 128 + j0 + tx * 4 + jj] =
                sqrtf(v.x * v.x + v.y * v.y);
        }
}

// ---------------- 3x3 masked conv + magw + pha-mix + makec (inside px) ----
__global__ void __launch_bounds__(256)
k_conv3mF(const float* __restrict__ X, const float* __restrict__ Pha,
          const float* __restrict__ Wt, const float* __restrict__ Bs,
          const float* __restrict__ MagW, const float* __restrict__ MagB,
          const float* __restrict__ PhaW, const float* __restrict__ PhaB,
          float2* __restrict__ F) {
    __shared__ float sW[CMc * CMc * 9];
    __shared__ float sMW[256];
    __shared__ float sPW[256];
    __shared__ float sSB[16];
    __shared__ float sMB[16];
    __shared__ float sPB[16];
    __shared__ float sT[10][34];
    int tid = threadIdx.y * 32 + threadIdx.x;
    for (int e = tid; e < CMc * CMc * 9; e += 256) sW[e] = Wt[e];
    if (tid < 256) { sMW[tid] = MagW[tid]; sPW[tid] = PhaW[tid]; }
    if (tid < 16) { sSB[tid] = Bs[tid]; sMB[tid] = MagB[tid]; sPB[tid] = PhaB[tid]; }
    int n = blockIdx.z;
    int wb = blockIdx.x * 32, hb = 16 + blockIdx.y * 8;
    const float* Xn = X + (size_t)n * CMc * PP;
    float acc[CMc];
#pragma unroll
    for (int o = 0; o < CMc; o++) acc[o] = 0.f;
    for (int c = 0; c < CMc; c++) {
        __syncthreads();
        for (int e = tid; e < 340; e += 256) {
            int ly = e / 34, lx = e % 34;
            int gy = hb - 1 + ly, gx = wb - 1 + lx;
            float v = 0.f;
            if (gy >= 19 && gy < 109 && gx >= 19 && gx < 109)
                v = Xn[(size_t)c * PP + gy * WW + gx];
            sT[ly][lx] = v;
        }
        __syncthreads();
#pragma unroll
        for (int kh = 0; kh < 3; kh++)
#pragma unroll
            for (int kw = 0; kw < 3; kw++) {
                float xv = sT[threadIdx.y + kh][threadIdx.x + kw];
#pragma unroll
                for (int o = 0; o < CMc; o++)
                    acc[o] += sW[(o * CMc + c) * 9 + kh * 3 + kw] * xv;
            }
    }
    int h = hb + threadIdx.y, w = wb + threadIdx.x;
    if (h >= 19 && h < 109 && w >= 19 && w < 109) {
        int p = h * WW + w;
        size_t base = (size_t)n * 16 * PP;
#pragma unroll
        for (int m = 0; m < CMc; m++) acc[m] += sSB[m];
        float ph[16];
#pragma unroll
        for (int c = 0; c < 16; c++) ph[c] = Pha[base + (size_t)c * PP + p];
#pragma unroll
        for (int o = 0; o < CMc; o++) {
            float mo = sMB[o];
#pragma unroll
            for (int m = 0; m < CMc; m++) mo += sMW[o * 16 + m] * acc[m];
            float po = sPB[o];
#pragma unroll
            for (int c = 0; c < 16; c++) po += sPW[o * 16 + c] * ph[c];
            float sn, cs;
            __sincosf(po, &sn, &cs);
            F[base + (size_t)o * PP + p] = make_float2(mo * cs, mo * sn);
        }
    }
}

// ---------------- merged: phaO (blk 0..511) + fmfp (blk 512..771) ---------
__global__ void __launch_bounds__(128)
k_phaOF(const float* __restrict__ Pha, const float* __restrict__ Mag,
        const float* __restrict__ PhaW, const float* __restrict__ PhaB,
        float2* __restrict__ F,
        const float* __restrict__ Fm, const float* __restrict__ Fp,
        const float* __restrict__ W1, const float* __restrict__ B1,
        float2* __restrict__ F65) {
    int bid = blockIdx.x;
    int t = threadIdx.x;
    if (bid < 512) {
        __shared__ float sPW[256];
        __shared__ float sW2[256];
        __shared__ float sPB[16];
        __shared__ float sB2[16];
        sPW[t] = PhaW[t]; sPW[t + 128] = PhaW[t + 128];
        sW2[t] = g_W2[t]; sW2[t + 128] = g_W2[t + 128];
        if (t < 16)  { sPB[t] = PhaB[t]; sB2[t] = g_b2[t]; }
        __syncthreads();
        int n = bid >> 7;
        int p = (bid & 127) * 128 + t;
        int h = p >> 7, w = p & 127;
        if (h >= 19 && h < 109 && w >= 19 && w < 109) return;
        size_t base = (size_t)n * 16 * PP;
        float ph[16], mg[16];
#pragma unroll
        for (int c = 0; c < 16; c++) {
            ph[c] = Pha[base + (size_t)c * PP + p];
            mg[c] = Mag[base + (size_t)c * PP + p];
        }
#pragma unroll
        for (int o = 0; o < 16; o++) {
            float po = sPB[o];
            float m = sB2[o];
#pragma unroll
            for (int c = 0; c < 16; c++) {
                po += sPW[o * 16 + c] * ph[c];
                m  += sW2[o * 16 + c] * mg[c];
            }
            float sn, cs;
            __sincosf(po, &sn, &cs);
            F[base + (size_t)o * PP + p] = make_float2(m * cs, m * sn);
        }
    } else {
        __shared__ float sW[256];
        __shared__ float sB[16];
        sW[t] = W1[t]; sW[t + 128] = W1[t + 128];
        if (t < 16)  sB[t] = B1[t];
        __syncthreads();
        int r = bid - 512;
        int n = r / 65;
        int p = (r % 65) * 128 + t;
        if (p >= P65) return;
        size_t base = (size_t)n * 16 * P65;
        float fm[16], fp[16];
#pragma unroll
        for (int c = 0; c < 16; c++) {
            fm[c] = Fm[base + (size_t)c * P65 + p];
            fp[c] = Fp[base + (size_t)c * P65 + p];
        }
#pragma unroll
        for (int o = 0; o < 16; o++) {
            float mo = sB[o], po = sB[o];
#pragma unroll
            for (int c = 0; c < 16; c++) {
                mo += sW[o * 16 + c] * fm[c];
                po += sW[o * 16 + c] * fp[c];
            }
            float sn, cs;
            __sincosf(po, &sn, &cs);
            F65[base + (size_t)o * P65 + p] = make_float2(mo * cs, mo * sn);
        }
    }
}

// ---------------- launch ----------------
extern "C" void kernel_launch(void* const* d_in, const int* in_sizes, int n_in,
                              void* d_out, int out_size) {
    const float* x        = (const float*)d_in[0];
    const float* conv1_w  = (const float*)d_in[1];
    const float* mag_s_w  = (const float*)d_in[2];
    const float* mag_s_b  = (const float*)d_in[3];
    const float* mag_f_w  = (const float*)d_in[4];
    const float* mag_f_b  = (const float*)d_in[5];
    const float* mag_w    = (const float*)d_in[6];
    const float* mag_b    = (const float*)d_in[7];
    const float* pha_w    = (const float*)d_in[8];
    const float* pha_b    = (const float*)d_in[9];
    const float* conv_0_w = (const float*)d_in[10];
    const float* conv_0_b = (const float*)d_in[11];
    const float* conv_1_w = (const float*)d_in[12];
    const float* conv_1_b = (const float*)d_in[13];
    const float* conv2_w  = (const float*)d_in[14];
    float* out = (float*)d_out;

    float  *px1, *pmag, *ppha, *pfm, *pfp, *pcat;
    float2 *pM, *pMinv, *pFh, *pFhi, *pFw, *pT, *pF, *pT65, *pF65;
    cudaGetSymbolAddress((void**)&px1,    g_x1);
    cudaGetSymbolAddress((void**)&pmag,   g_mag);
    cudaGetSymbolAddress((void**)&ppha,   g_pha);
    cudaGetSymbolAddress((void**)&pfm,    g_fm);
    cudaGetSymbolAddress((void**)&pfp,    g_fp);
    cudaGetSymbolAddress((void**)&pcat,   g_cat);
    cudaGetSymbolAddress((void**)&pM,     g_M);
    cudaGetSymbolAddress((void**)&pMinv,  g_Minv);
    cudaGetSymbolAddress((void**)&pFh,    g_Fh);
    cudaGetSymbolAddress((void**)&pFhi,   g_Fhi);
    cudaGetSymbolAddress((void**)&pFw,    g_Fw);
    cudaGetSymbolAddress((void**)&pT,     g_T);
    cudaGetSymbolAddress((void**)&pF,     g_F);
    cudaGetSymbolAddress((void**)&pT65,   g_T65);
    cudaGetSymbolAddress((void**)&pF65,   g_F65);

    k_init <<<128, 256>>>();
    k_init2<<<141, 512>>>(conv2_w, conv_0_w, conv_0_b, mag_w, mag_f_w, mag_f_b, mag_b);

    k_g1x1<<<dim3(32, 3, NB), 128>>>(x, conv1_w, px1, 192, 192 * PP, 48 * PP);

    k_rxMT64D<<<384, 128>>>(px1, pM, pT, pFw, pT65);
    k_MxXD<<<448, 128>>>(px1, pM, pT, pmag, ppha, pFh, pT65, pfm, pfp);

    k_conv3mF<<<dim3(4, 12, NB), dim3(32, 8)>>>(pmag, ppha, mag_s_w, mag_s_b,
                                                mag_w, mag_b, pha_w, pha_b, pF);
    k_phaOF<<<772, 128>>>(ppha, pmag, pha_w, pha_b, pF,
                          pfm, pfp, conv_1_w, conv_1_b, pF65);

    k_invA<<<448, 128>>>(pF, pMinv, pT, pFhi, pF65, pT65);
    k_invB<<<2304, 128>>>(pMinv, pT, pcat, pT65);

    k_conv2<<<dim3(32, 12, NB), 128>>>(px1, pcat, conv2_w, out);
}

// round 17
// speedup vs baseline: 2.7780x; 1.2062x over previous
#include <cuda_runtime.h>
#include <math.h>

#define NB   4
#define CIN  192
#define HH   128
#define WW   128
#define PP   (HH*WW)       // 16384
#define C1c  48
#define C0c  16
#define CMc  16
#define BATCH 64           // NB * CMc
#define JW   65
#define P65  (128*JW)      // 8320

typedef unsigned long long u64t;

__device__ __forceinline__ u64t pk2(float lo, float hi) {
    u64t r; asm("mov.b64 %0, {%1,%2};" : "=l"(r) : "f"(lo), "f"(hi)); return r;
}
__device__ __forceinline__ float2 upk2(u64t v) {
    float2 f; asm("mov.b64 {%0,%1}, %2;" : "=f"(f.x), "=f"(f.y) : "l"(v)); return f;
}
__device__ __forceinline__ u64t ffma2(u64t a, u64t b, u64t c) {
    u64t d; asm("fma.rn.f32x2 %0, %1, %2, %3;" : "=l"(d) : "l"(a), "l"(b), "l"(c)); return d;
}

// ---------------- device scratch ----------------
static __device__ float2  g_M   [128*128];
static __device__ float2  g_Cm  [128*128];
static __device__ float2  g_Minv[128*128];
static __device__ float2  g_Fh  [128*128];
static __device__ float2  g_Fhi [128*128];
static __device__ float2  g_Fw  [JW*128];
static __device__ float2  g_Bw  [JW*128];

static __device__ float   g_W2[256];
static __device__ float   g_b2[16];
static __device__ float   g_Wc[192*16];
static __device__ float   g_bc[192];

static __device__ float   g_x1 [NB*C1c*PP];
static __device__ float2  g_T  [BATCH*128*128];
static __device__ float2  g_F  [BATCH*128*128];
static __device__ float   g_mag[BATCH*PP];
static __device__ float   g_pha[BATCH*PP];
static __device__ float2  g_T65[BATCH*P65];
static __device__ float2  g_F65[BATCH*P65];
static __device__ float   g_fm[BATCH*P65];
static __device__ float   g_fp[BATCH*P65];
static __device__ float   g_cat[NB*C1c*PP];

// ---------------- k_init ----------------
__global__ void __launch_bounds__(256) k_init() {
    int bid = blockIdx.x, t = threadIdx.x;
    const double PI = 3.14159265358979323846;
    if (bid < 64) {
        int idx = bid * 256 + t;
        {
            int u = idx >> 7, v = idx & 127;
            int e1 = ((u + 64) * (v + 64)) & 127;
            double s, c; sincospi(2.0 * e1 / 128.0, &s, &c);
            double inv = 1.0 / sqrt(128.0);
            g_Cm[idx] = make_float2((float)(c * inv), (float)(s * inv));
            int e2 = (u * v) & 127;
            double s2, c2; sincospi(-2.0 * e2 / 128.0, &s2, &c2);
            g_Fh[idx] = make_float2((float)c2, (float)s2);
            double s3, c3; sincospi(2.0 * e2 / 128.0, &s3, &c3);
            g_Fhi[idx] = make_float2((float)(c3 / 128.0), (float)(s3 / 128.0));
        }
        if (idx < JW * 128) {
            int k = idx / 128, w = idx & 127;
            int e = (k * w) & 127;
            double s, c; sincospi(-2.0 * e / 128.0, &s, &c);
            g_Fw[idx] = make_float2((float)c, (float)s);
            float2 bw;
            if (k == 0)       bw = make_float2(1.0f / 128.0f, 0.f);
            else if (k == 64) bw = make_float2(((w & 1) ? -1.0f : 1.0f) / 128.0f, 0.f);
            else {
                double s4, c4; sincospi(2.0 * e / 128.0, &s4, &c4);
                bw = make_float2((float)(c4 * 2.0 / 128.0), (float)(s4 * 2.0 / 128.0));
            }
            g_Bw[idx] = bw;
        }
    } else {
        __shared__ float2 sC1[255];
        __shared__ float2 sE[509];
        __shared__ float  sS[509];
        __shared__ float2 sFac[2];
        int B = bid - 64;
        double tana2 = tan(PI / 8.0);
        double sina  = sin(PI / 4.0);
        double coef  = tana2 / 512.0;
        double ec    = 1.0 / (512.0 * sina);
        for (int j = t; j < 255; j += 256) {
            double n = (double)(j - 127);
            double s, c; sincospi(-coef * n * n, &s, &c);
            sC1[j] = make_float2((float)c, (float)s);
        }
        for (int i = t; i < 509; i += 256) {
            double d = (double)(i - 254);
            double s, c; sincospi(ec * d * d, &s, &c);
            sE[i] = make_float2((float)c, (float)s);
            int m = i - 254;
            double sv;
            if (m == 0) sv = 1.0;
            else if ((m & 1) == 0) sv = 0.0;
            else {
                double x = 0.5 * (double)m;
                sv = sinpi(x) / (PI * x);
            }
            sS[i] = (float)sv;
        }
        if (t < 2) {
            double amp = sqrt(1.0 / (512.0 * sina));
            double ps, pc; sincospi(-0.125, &ps, &pc);
            int r = 2 * B + t;
            double n = 2.0 * r - 127.0;
            double s, c; sincospi(-coef * n * n, &s, &c);
            sFac[t] = make_float2((float)(amp * (pc * c - ps * s)),
                                  (float)(amp * (pc * s + ps * c)));
        }
        __syncthreads();
        int idx = B * 256 + t;
        int r = idx >> 7, k = idx & 127;
        float ax = 0.f, ay = 0.f;
        {
            int j = 2 * k;
            float2 c1 = sC1[j];
            float2 e  = sE[2 * r - j + 254];
            ax += c1.x * e.x - c1.y * e.y;
            ay += c1.x * e.y + c1.y * e.x;
        }
        for (int j = 1; j < 255; j += 2) {
            float s = sS[j - 2 * k + 254];
            float2 c1 = sC1[j];
            float2 e  = sE[2 * r - j + 254];
            ax += (c1.x * e.x - c1.y * e.y) * s;
            ay += (c1.x * e.y + c1.y * e.x) * s;
        }
        float2 f = sFac[r - 2 * B];
        g_M[idx] = make_float2(f.x * ax - f.y * ay, f.x * ay + f.y * ax);
    }
}

// ---------------- k_init2 ----------------
__global__ void __launch_bounds__(512) k_init2(
        const float* __restrict__ conv2w, const float* __restrict__ conv0w,
        const float* __restrict__ conv0b,
        const float* __restrict__ magw, const float* __restrict__ magf,
        const float* __restrict__ magfb, const float* __restrict__ magb) {
    int bid = blockIdx.x, t = threadIdx.x;
    if (bid < 128) {
        __shared__ float2 sM[128];
        __shared__ float2 sP[512];
        int r = bid;
        int v = t & 127, seg = t >> 7;
        if (t < 128) sM[t] = g_M[r * 128 + t];
        __syncthreads();
        float ax = 0.f, ay = 0.f;
        int u0 = seg * 32;
#pragma unroll 8
        for (int u = u0; u < u0 + 32; u++) {
            float2 a = sM[u];
            float2 b = g_Cm[u * 128 + v];
            ax += a.x * b.x - a.y * b.y;
            ay += a.x * b.y + a.y * b.x;
        }
        sP[t] = make_float2(ax, ay);
        __syncthreads();
        if (t < 128) {
            float2 p0 = sP[t], p1 = sP[t + 128], p2 = sP[t + 256], p3 = sP[t + 384];
            g_Minv[r * 128 + v] = make_float2(p0.x + p1.x + p2.x + p3.x,
                                              p0.y + p1.y + p2.y + p3.y);
        }
    } else if (bid < 140) {
        if (t >= 256) return;
        int idx = (bid - 128) * 256 + t;
        if (idx < 192 * 16) {
            int o = idx >> 4, c = idx & 15;
            float a = 0.f;
#pragma unroll
            for (int m = 0; m < 16; m++) a += conv2w[o * 48 + m] * conv0w[m * 16 + c];
            g_Wc[idx] = a;
        }
        if (idx < 192) {
            float b = 0.f;
#pragma unroll
            for (int m = 0; m < 16; m++) b += conv2w[idx * 48 + m] * conv0b[m];
            g_bc[idx] = b;
        }
    } else {
        if (t >= 256) return;
        int o = t >> 4, c = t & 15;
        float a = 0.f;
#pragma unroll
        for (int m = 0; m < 16; m++) a += magw[o * 16 + m] * magf[m * 16 + c];
        g_W2[t] = a;
        if (t < 16) {
            float b = magb[t];
#pragma unroll
            for (int m = 0; m < 16; m++) b += magw[t * 16 + m] * magfb[m];
            g_b2[t] = b;
        }
    }
}

// ---------------- conv1 (float4 loads, FFMA2, dup weights) ----------------
__global__ void __launch_bounds__(128)
k_g1x1(const float* __restrict__ X, const float* __restrict__ Wt,
       float* __restrict__ Y, int Cc, int xStrideN, int yStrideN) {
    __shared__ u64t sW[16 * 192];
    int n = blockIdx.z, ob = blockIdx.y * 16;
    int tx = threadIdx.x;
    for (int e = tx; e < 16 * Cc; e += 128) {
        float w = Wt[ob * Cc + e];
        sW[e] = pk2(w, w);
    }
    __syncthreads();
    const float* Xn = X + (size_t)n * xStrideN;
    int p4 = blockIdx.x * 512 + tx * 4;
    u64t acc[16][2];
#pragma unroll
    for (int o = 0; o < 16; o++) { acc[o][0] = 0ULL; acc[o][1] = 0ULL; }
#pragma unroll 4
    for (int c = 0; c < Cc; c++) {
        ulonglong2 xq = *(const ulonglong2*)&Xn[(size_t)c * PP + p4];
#pragma unroll
        for (int o = 0; o < 16; o++) {
            u64t w2 = sW[o * Cc + c];
            acc[o][0] = ffma2(w2, xq.x, acc[o][0]);
            acc[o][1] = ffma2(w2, xq.y, acc[o][1]);
        }
    }
#pragma unroll
    for (int o = 0; o < 16; o++) {
        float2 a0 = upk2(acc[o][0]), a1 = upk2(acc[o][1]);
        float4 r = make_float4(a0.x, a0.y, a1.x, a1.y);
        *(float4*)&Y[(size_t)n * yStrideN + (size_t)(ob + o) * PP + p4] = r;
    }
}

// ---------------- conv2 (folded conv_0, FFMA2) ----------------
__global__ void __launch_bounds__(128)
k_conv2(const float* __restrict__ X1, const float* __restrict__ Cat,
        const float* __restrict__ conv2w, float* __restrict__ Y) {
    __shared__ u64t sWa[16 * 16];
    __shared__ u64t sWb[16 * 32];
    __shared__ float sB[16];
    int n = blockIdx.z, ob = blockIdx.y * 16;
    int tx = threadIdx.x;
    for (int e = tx; e < 256; e += 128) {
        float w = g_Wc[(ob + (e >> 4)) * 16 + (e & 15)];
        sWa[e] = pk2(w, w);
    }
    for (int e = tx; e < 512; e += 128) {
        int o = e >> 5, c = e & 31;
        float w = conv2w[(ob + o) * 48 + 16 + c];
        sWb[e] = pk2(w, w);
    }
    if (tx < 16) sB[tx] = g_bc[ob + tx];
    __syncthreads();
    const float* Xn = X1 + (size_t)n * 48 * PP;
    const float* Cn = Cat + (size_t)n * 48 * PP + (size_t)16 * PP;
    int p4 = blockIdx.x * 512 + tx * 4;
    u64t acc[16][2];
#pragma unroll
    for (int o = 0; o < 16; o++) { acc[o][0] = 0ULL; acc[o][1] = 0ULL; }
#pragma unroll 4
    for (int c = 0; c < 16; c++) {
        ulonglong2 xq = *(const ulonglong2*)&Xn[(size_t)c * PP + p4];
#pragma unroll
        for (int o = 0; o < 16; o++) {
            u64t w2 = sWa[o * 16 + c];
            acc[o][0] = ffma2(w2, xq.x, acc[o][0]);
            acc[o][1] = ffma2(w2, xq.y, acc[o][1]);
        }
    }
#pragma unroll 4
    for (int c = 0; c < 32; c++) {
        ulonglong2 xq = *(const ulonglong2*)&Cn[(size_t)c * PP + p4];
#pragma unroll
        for (int o = 0; o < 16; o++) {
            u64t w2 = sWb[o * 32 + c];
            acc[o][0] = ffma2(w2, xq.x, acc[o][0]);
            acc[o][1] = ffma2(w2, xq.y, acc[o][1]);
        }
    }
#pragma unroll
    for (int o = 0; o < 16; o++) {
        float2 a0 = upk2(acc[o][0]), a1 = upk2(acc[o][1]);
        float b = sB[o];
        float4 r = make_float4(a0.x + b, a0.y + b, a1.x + b, a1.y + b);
        *(float4*)&Y[(size_t)n * 192 * PP + (size_t)(ob + o) * PP + p4] = r;
    }
}

// ---------------- 8x4 micro-tile compute steps (FFMA2) --------------------
__device__ __forceinline__ void cstep(const float2 (&A)[16][66], const float2 (&B)[16][66],
                                      int ty, int tx, u64t (&acc)[8][4]) {
#pragma unroll 4
    for (int kk = 0; kk < 16; kk++) {
        float4 t0 = *(const float4*)&A[kk][ty * 8];
        float4 t1 = *(const float4*)&A[kk][ty * 8 + 2];
        float4 t2 = *(const float4*)&A[kk][ty * 8 + 4];
        float4 t3 = *(const float4*)&A[kk][ty * 8 + 6];
        float4 u0 = *(const float4*)&B[kk][tx * 4];
        float4 u1 = *(const float4*)&B[kk][tx * 4 + 2];
        float2 av[8] = {{t0.x,t0.y},{t0.z,t0.w},{t1.x,t1.y},{t1.z,t1.w},
                        {t2.x,t2.y},{t2.z,t2.w},{t3.x,t3.y},{t3.z,t3.w}};
        float2 bv[4] = {{u0.x,u0.y},{u0.z,u0.w},{u1.x,u1.y},{u1.z,u1.w}};
        u64t axd[8], ayd[8];
#pragma unroll
        for (int ii = 0; ii < 8; ii++) {
            axd[ii] = pk2(av[ii].x, av[ii].x);
            ayd[ii] = pk2(av[ii].y, av[ii].y);
        }
        u64t bp[4], bs[4];
#pragma unroll
        for (int jj = 0; jj < 4; jj++) {
            bp[jj] = pk2(bv[jj].x, bv[jj].y);
            bs[jj] = pk2(-bv[jj].y, bv[jj].x);
        }
#pragma unroll
        for (int ii = 0; ii < 8; ii++)
#pragma unroll
            for (int jj = 0; jj < 4; jj++) {
                acc[ii][jj] = ffma2(axd[ii], bp[jj], acc[ii][jj]);
                acc[ii][jj] = ffma2(ayd[ii], bs[jj], acc[ii][jj]);
            }
    }
}

__device__ __forceinline__ void rstep(const float (&A)[16][68], const float2 (&B)[16][66],
                                      int ty, int tx, u64t (&acc)[8][4]) {
#pragma unroll 4
    for (int kk = 0; kk < 16; kk++) {
        float4 t0 = *(const float4*)&A[kk][ty * 8];
        float4 t1 = *(const float4*)&A[kk][ty * 8 + 4];
        ulonglong2 q0 = *(const ulonglong2*)&B[kk][tx * 4];
        ulonglong2 q1 = *(const ulonglong2*)&B[kk][tx * 4 + 2];
        float a[8] = {t0.x, t0.y, t0.z, t0.w, t1.x, t1.y, t1.z, t1.w};
        u64t bq[4] = {q0.x, q0.y, q1.x, q1.y};
        u64t ad[8];
#pragma unroll
        for (int ii = 0; ii < 8; ii++) ad[ii] = pk2(a[ii], a[ii]);
#pragma unroll
        for (int ii = 0; ii < 8; ii++)
#pragma unroll
            for (int jj = 0; jj < 4; jj++)
                acc[ii][jj] = ffma2(ad[ii], bq[jj], acc[ii][jj]);
    }
}

// ---------------- merged rxMT (128 thr, 8x4 micro) ------------------------
__global__ void __launch_bounds__(128)
k_rxMT64D(const float* __restrict__ X1,
          const float2* __restrict__ Ma, float2* __restrict__ Ya,
          const float2* __restrict__ Mb, float2* __restrict__ Yb) {
    int bid = blockIdx.x;
    const float* X; const float2* M; float2* Y; int J, j0, i0;
    if (bid < 256) {
        int b = bid >> 2;
        i0 = ((bid >> 1) & 1) * 64; j0 = (bid & 1) * 64;
        X = X1 + (size_t)((b >> 4) * C1c + 16 + (b & 15)) * PP;
        M = Ma; Y = Ya + (size_t)b * 128 * 128; J = 128;
    } else {
        int r = bid - 256; int b = r >> 1;
        i0 = (r & 1) * 64; j0 = 0;
        X = X1 + (size_t)((b >> 4) * C1c + 32 + (b & 15)) * PP;
        M = Mb; Y = Yb + (size_t)b * 128 * JW; J = JW;
    }
    __shared__ __align__(16) float  sA[2][16][68];
    __shared__ __align__(16) float2 sB[2][16][66];
    int tid = threadIdx.x, tx = tid & 15, ty = tid >> 4;
    u64t acc[8][4];
#pragma unroll
    for (int a = 0; a < 8; a++)
#pragma unroll
        for (int c = 0; c < 4; c++) acc[a][c] = 0ULL;
    float ra[8]; float2 rb[8];
#pragma unroll
    for (int s = 0; s < 8; s++) {
        int e = tid + s * 128; int r = e >> 4, c = e & 15;
        ra[s] = X[(i0 + r) * 128 + c];
        rb[s] = M[(j0 + r) * 128 + c];
    }
#pragma unroll
    for (int s = 0; s < 8; s++) {
        int e = tid + s * 128; int r = e >> 4, c = e & 15;
        sA[0][c][r] = ra[s]; sB[0][c][r] = rb[s];
    }
    __syncthreads();
    for (int ch = 0; ch < 8; ch++) {
        if (ch < 7) {
            int kt = (ch + 1) * 16;
#pragma unroll
            for (int s = 0; s < 8; s++) {
                int e = tid + s * 128; int r = e >> 4, c = e & 15;
                ra[s] = X[(i0 + r) * 128 + kt + c];
                rb[s] = M[(j0 + r) * 128 + kt + c];
            }
        }
        rstep(sA[ch & 1], sB[ch & 1], ty, tx, acc);
        if (ch < 7) {
            int nb = (ch + 1) & 1;
#pragma unroll
            for (int s = 0; s < 8; s++) {
                int e = tid + s * 128; int r = e >> 4, c = e & 15;
                sA[nb][c][r] = ra[s]; sB[nb][c][r] = rb[s];
            }
            __syncthreads();
        }
    }
#pragma unroll
    for (int ii = 0; ii < 8; ii++)
#pragma unroll
        for (int jj = 0; jj < 4; jj++)
            Y[(size_t)(i0 + ty * 8 + ii) * J + j0 + tx * 4 + jj] = upk2(acc[ii][jj]);
}

// ---------------- merged MxX (mag/pha epilogue) + nyqB --------------------
__global__ void __launch_bounds__(128)
k_MxXD(const float* __restrict__ X1,
       const float2* __restrict__ Ma, const float2* __restrict__ Xa,
       float* __restrict__ m1, float* __restrict__ p1,
       const float2* __restrict__ Mb, const float2* __restrict__ Xb,
       float* __restrict__ m2, float* __restrict__ p2) {
    int bid = blockIdx.x;
    int tid = threadIdx.x;
    if (bid >= 384) {
        __shared__ float sTn[128];
        int b = bid - 384;
        const float* X = X1 + (size_t)((b >> 4) * C1c + 32 + (b & 15)) * PP;
        float s = 0.f;
        const float* row = X + tid * 128;
#pragma unroll 16
        for (int w = 0; w < 128; w += 2) s += row[w] - row[w + 1];
        sTn[tid] = s;
        __syncthreads();
        float ax = 0.f, ay = 0.f;
#pragma unroll 8
        for (int k = 0; k < 128; k++) {
            float2 f = Mb[tid * 128 + k];
            float v = sTn[k];
            ax += f.x * v; ay += f.y * v;
        }
        size_t idx = ((size_t)b * 128 + tid) * JW + 64;
        m2[idx] = sqrtf(ax * ax + ay * ay);
        p2[idx] = atan2f(ay, ax);
        return;
    }
    const float2* M; const float2* X; float* o1; float* o2; int J, j0, i0; size_t ob;
    if (bid < 256) {
        int b = bid >> 2;
        i0 = ((bid >> 1) & 1) * 64; j0 = (bid & 1) * 64;
        M = Ma; X = Xa + (size_t)b * 128 * 128; J = 128;
        o1 = m1; o2 = p1; ob = (size_t)b * 128;
    } else {
        int r = bid - 256; int b = r >> 1;
        i0 = (r & 1) * 64; j0 = 0;
        M = Mb; X = Xb + (size_t)b * 128 * JW; J = JW;
        o1 = m2; o2 = p2; ob = (size_t)b * 128;
    }
    __shared__ __align__(16) float2 sA[2][16][66];
    __shared__ __align__(16) float2 sB[2][16][66];
    int tx = tid & 15, ty = tid >> 4;
    u64t acc[8][4];
#pragma unroll
    for (int a = 0; a < 8; a++)
#pragma unroll
        for (int c = 0; c < 4; c++) acc[a][c] = 0ULL;
    float2 ra[8], rb[8];
#pragma unroll
    for (int s = 0; s < 8; s++) {
        int e = tid + s * 128;
        int r = e >> 4, c = e & 15;
        ra[s] = M[(i0 + r) * 128 + c];
        int r2 = e >> 6, c2 = e & 63;
        rb[s] = X[(size_t)r2 * J + j0 + c2];
    }
#pragma unroll
    for (int s = 0; s < 8; s++) {
        int e = tid + s * 128;
        int r = e >> 4, c = e & 15;
        sA[0][c][r] = ra[s];
        int r2 = e >> 6, c2 = e & 63;
        sB[0][r2][c2] = rb[s];
    }
    __syncthreads();
    for (int ch = 0; ch < 8; ch++) {
        if (ch < 7) {
            int kt = (ch + 1) * 16;
#pragma unroll
            for (int s = 0; s < 8; s++) {
                int e = tid + s * 128;
                int r = e >> 4, c = e & 15;
                ra[s] = M[(i0 + r) * 128 + kt + c];
                int r2 = e >> 6, c2 = e & 63;
                rb[s] = X[(size_t)(kt + r2) * J + j0 + c2];
            }
        }
        cstep(sA[ch & 1], sB[ch & 1], ty, tx, acc);
        if (ch < 7) {
            int nb = (ch + 1) & 1;
#pragma unroll
            for (int s = 0; s < 8; s++) {
                int e = tid + s * 128;
                int r = e >> 4, c = e & 15;
                sA[nb][c][r] = ra[s];
                int r2 = e >> 6, c2 = e & 63;
                sB[nb][r2][c2] = rb[s];
            }
            __syncthreads();
        }
    }
#pragma unroll
    for (int ii = 0; ii < 8; ii++)
#pragma unroll
        for (int jj = 0; jj < 4; jj++) {
            int i = i0 + ty * 8 + ii;
            int j = j0 + tx * 4 + jj;
            float2 v = upk2(acc[ii][jj]);
            size_t idx = (ob + i) * J + j;
            float m = sqrtf(v.x * v.x + v.y * v.y);
            o1[idx] = m;
            o2[idx] = atan2f(v.y, v.x);
        }
}

// ---------------- k_invA: cMT(frft) + MxX0(rfft) + nyqC -------------------
__global__ void __launch_bounds__(128)
k_invA(const float2* __restrict__ Fc, const float2* __restrict__ Minv,
       float2* __restrict__ T,
       const float2* __restrict__ Fhi, const float2* __restrict__ F65,
       float2* __restrict__ T65) {
    int bid = blockIdx.x;
    int tid = threadIdx.x;
    if (bid >= 384) {
        __shared__ float2 sC[128];
        int b = bid - 384;
        sC[tid] = F65[((size_t)b * 128 + tid) * JW + 64];
        __syncthreads();
        float ax = 0.f, ay = 0.f;
#pragma unroll 8
        for (int k = 0; k < 128; k++) {
            float2 m = Fhi[tid * 128 + k];
            float2 v = sC[k];
            ax += m.x * v.x - m.y * v.y;
            ay += m.x * v.y + m.y * v.x;
        }
        T65[((size_t)b * 128 + tid) * JW + 64] = make_float2(ax, ay);
        return;
    }
    __shared__ __align__(16) float2 sA[2][16][66];
    __shared__ __align__(16) float2 sB[2][16][66];
    int tx = tid & 15, ty = tid >> 4;
    u64t acc[8][4];
#pragma unroll
    for (int a = 0; a < 8; a++)
#pragma unroll
        for (int c = 0; c < 4; c++) acc[a][c] = 0ULL;
    if (bid < 256) {
        int b = bid >> 2;
        int i0 = ((bid >> 1) & 1) * 64, j0 = (bid & 1) * 64;
        const float2* X = Fc + (size_t)b * 128 * 128;
        float2 ra[8], rb[8];
#pragma unroll
        for (int s = 0; s < 8; s++) {
            int e = tid + s * 128; int r = e >> 4, c = e & 15;
            ra[s] = X[(i0 + r) * 128 + c];
            rb[s] = Minv[(j0 + r) * 128 + c];
        }
#pragma unroll
        for (int s = 0; s < 8; s++) {
            int e = tid + s * 128; int r = e >> 4, c = e & 15;
            sA[0][c][r] = ra[s]; sB[0][c][r] = rb[s];
        }
        __syncthreads();
        for (int ch = 0; ch < 8; ch++) {
            if (ch < 7) {
                int kt = (ch + 1) * 16;
#pragma unroll
                for (int s = 0; s < 8; s++) {
                    int e = tid + s * 128; int r = e >> 4, c = e & 15;
                    ra[s] = X[(i0 + r) * 128 + kt + c];
                    rb[s] = Minv[(j0 + r) * 128 + kt + c];
                }
            }
            cstep(sA[ch & 1], sB[ch & 1], ty, tx, acc);
            if (ch < 7) {
                int nb = (ch + 1) & 1;
#pragma unroll
                for (int s = 0; s < 8; s++) {
                    int e = tid + s * 128; int r = e >> 4, c = e & 15;
                    sA[nb][c][r] = ra[s]; sB[nb][c][r] = rb[s];
                }
                __syncthreads();
            }
        }
#pragma unroll
        for (int ii = 0; ii < 8; ii++)
#pragma unroll
            for (int jj = 0; jj < 4; jj++)
                T[((size_t)b * 128 + i0 + ty * 8 + ii) * 128 + j0 + tx * 4 + jj] = upk2(acc[ii][jj]);
    } else {
        int r0 = bid - 256; int b = r0 >> 1;
        int i0 = (r0 & 1) * 64;
        const float2* X = F65 + (size_t)b * 128 * JW;
        float2 ra[8], rb[8];
#pragma unroll
        for (int s = 0; s < 8; s++) {
            int e = tid + s * 128;
            int r = e >> 4, c = e & 15;
            ra[s] = Fhi[(i0 + r) * 128 + c];
            int r2 = e >> 6, c2 = e & 63;
            rb[s] = X[(size_t)r2 * JW + c2];
        }
#pragma unroll
        for (int s = 0; s < 8; s++) {
            int e = tid + s * 128;
            int r = e >> 4, c = e & 15;
            sA[0][c][r] = ra[s];
            int r2 = e >> 6, c2 = e & 63;
            sB[0][r2][c2] = rb[s];
        }
        __syncthreads();
        for (int ch = 0; ch < 8; ch++) {
            if (ch < 7) {
                int kt = (ch + 1) * 16;
#pragma unroll
                for (int s = 0; s < 8; s++) {
                    int e = tid + s * 128;
                    int r = e >> 4, c = e & 15;
                    ra[s] = Fhi[(i0 + r) * 128 + kt + c];
                    int r2 = e >> 6, c2 = e & 63;
                    rb[s] = X[(size_t)(kt + r2) * JW + c2];
                }
            }
            cstep(sA[ch & 1], sB[ch & 1], ty, tx, acc);
            if (ch < 7) {
                int nb = (ch + 1) & 1;
#pragma unroll
                for (int s = 0; s < 8; s++) {
                    int e = tid + s * 128;
                    int r = e >> 4, c = e & 15;
                    sA[nb][c][r] = ra[s];
                    int r2 = e >> 6, c2 = e & 63;
                    sB[nb][r2][c2] = rb[s];
                }
                __syncthreads();
            }
        }
#pragma unroll
        for (int ii = 0; ii < 8; ii++)
#pragma unroll
            for (int jj = 0; jj < 4; jj++)
                T65[((size_t)b * 128 + i0 + ty * 8 + ii) * JW + tx * 4 + jj] = upk2(acc[ii][jj]);
    }
}

// ---------------- k_invB: MxX2 (|.|->cat) + irfft_w -----------------------
__global__ void __launch_bounds__(128)
k_invB(const float2* __restrict__ Minv, const float2* __restrict__ T,
       float* __restrict__ cat, const float2* __restrict__ T65) {
    int bid = blockIdx.x;
    int tid = threadIdx.x;
    if (bid >= 256) {
        int r0 = bid - 256;
        int b = r0 >> 5;
        int hb = (r0 & 31) * 4;
        float acc[4] = {0.f, 0.f, 0.f, 0.f};
        for (int k = 0; k < JW; k++) {
            float2 bw = g_Bw[k * 128 + tid];
#pragma unroll
            for (int s = 0; s < 4; s++) {
                float2 a = T65[((size_t)b * 128 + hb + s) * JW + k];
                acc[s] += a.x * bw.x - a.y * bw.y;
            }
        }
        int n = b >> 4, c = b & 15;
        float* Yp = cat + (size_t)(n * C1c + 32 + c) * PP;
#pragma unroll
        for (int s = 0; s < 4; s++)
            Yp[(hb + s) * WW + tid] = acc[s];
        return;
    }
    __shared__ __align__(16) float2 sA[2][16][66];
    __shared__ __align__(16) float2 sB[2][16][66];
    int tx = tid & 15, ty = tid >> 4;
    int b = bid >> 2;
    int i0 = ((bid >> 1) & 1) * 64, j0 = (bid & 1) * 64;
    const float2* X = T + (size_t)b * 128 * 128;
    u64t acc[8][4];
#pragma unroll
    for (int a = 0; a < 8; a++)
#pragma unroll
        for (int c = 0; c < 4; c++) acc[a][c] = 0ULL;
    float2 ra[8], rb[8];
#pragma unroll
    for (int s = 0; s < 8; s++) {
        int e = tid + s * 128;
        int r = e >> 4, c = e & 15;
        ra[s] = Minv[(i0 + r) * 128 + c];
        int r2 = e >> 6, c2 = e & 63;
        rb[s] = X[(size_t)r2 * 128 + j0 + c2];
    }
#pragma unroll
    for (int s = 0; s < 8; s++) {
        int e = tid + s * 128;
        int r = e >> 4, c = e & 15;
        sA[0][c][r] = ra[s];
        int r2 = e >> 6, c2 = e & 63;
        sB[0][r2][c2] = rb[s];
    }
    __syncthreads();
    for (int ch = 0; ch < 8; ch++) {
        if (ch < 7) {
            int kt = (ch + 1) * 16;
#pragma unroll
            for (int s = 0; s < 8; s++) {
                int e = tid + s * 128;
                int r = e >> 4, c = e & 15;
                ra[s] = Minv[(i0 + r) * 128 + kt + c];
                int r2 = e >> 6, c2 = e & 63;
                rb[s] = X[(size_t)(kt + r2) * 128 + j0 + c2];
            }
        }
        cstep(sA[ch & 1], sB[ch & 1], ty, tx, acc);
        if (ch < 7) {
            int nb = (ch + 1) & 1;
#pragma unroll
            for (int s = 0; s < 8; s++) {
                int e = tid + s * 128;
                int r = e >> 4, c = e & 15;
                sA[nb][c][r] = ra[s];
                int r2 = e >> 6, c2 = e & 63;
                sB[nb][r2][c2] = rb[s];
            }
            __syncthreads();
        }
    }
    int n = b >> 4, c = b & 15;
    float* O = cat + (size_t)(n * C1c + 16 + c) * PP;
#pragma unroll
    for (int ii = 0; ii < 8; ii++)
#pragma unroll
        for (int jj = 0; jj < 4; jj++) {
            float2 v = upk2(acc[ii][jj]);
            O[(size_t)(i0 + ty * 8 + ii) * 128 + j0 + tx * 4 + jj] =
                sqrtf(v.x * v.x + v.y * v.y);
        }
}

// ---------------- 3x3 masked conv + magw + pha-mix + makec (inside px) ----
__global__ void __launch_bounds__(256)
k_conv3mF(const float* __restrict__ X, const float* __restrict__ Pha,
          const float* __restrict__ Wt, const float* __restrict__ Bs,
          const float* __restrict__ MagW, const float* __restrict__ MagB,
          const float* __restrict__ PhaW, const float* __restrict__ PhaB,
          float2* __restrict__ F) {
    __shared__ float sW[CMc * CMc * 9];
    __shared__ float sMW[256];
    __shared__ float sPW[256];
    __shared__ float sSB[16];
    __shared__ float sMB[16];
    __shared__ float sPB[16];
    __shared__ float sT[10][34];
    int tid = threadIdx.y * 32 + threadIdx.x;
    for (int e = tid; e < CMc * CMc * 9; e += 256) sW[e] = Wt[e];
    if (tid < 256) { sMW[tid] = MagW[tid]; sPW[tid] = PhaW[tid]; }
    if (tid < 16) { sSB[tid] = Bs[tid]; sMB[tid] = MagB[tid]; sPB[tid] = PhaB[tid]; }
    int n = blockIdx.z;
    int wb = blockIdx.x * 32, hb = 16 + blockIdx.y * 8;
    const float* Xn = X + (size_t)n * CMc * PP;
    float acc[CMc];
#pragma unroll
    for (int o = 0; o < CMc; o++) acc[o] = 0.f;
    for (int c = 0; c < CMc; c++) {
        __syncthreads();
        for (int e = tid; e < 340; e += 256) {
            int ly = e / 34, lx = e % 34;
            int gy = hb - 1 + ly, gx = wb - 1 + lx;
            float v = 0.f;
            if (gy >= 19 && gy < 109 && gx >= 19 && gx < 109)
                v = Xn[(size_t)c * PP + gy * WW + gx];
            sT[ly][lx] = v;
        }
        __syncthreads();
#pragma unroll
        for (int kh = 0; kh < 3; kh++)
#pragma unroll
            for (int kw = 0; kw < 3; kw++) {
                float xv = sT[threadIdx.y + kh][threadIdx.x + kw];
#pragma unroll
                for (int o = 0; o < CMc; o++)
                    acc[o] += sW[(o * CMc + c) * 9 + kh * 3 + kw] * xv;
            }
    }
    int h = hb + threadIdx.y, w = wb + threadIdx.x;
    if (h >= 19 && h < 109 && w >= 19 && w < 109) {
        int p = h * WW + w;
        size_t base = (size_t)n * 16 * PP;
#pragma unroll
        for (int m = 0; m < CMc; m++) acc[m] += sSB[m];
        float ph[16];
#pragma unroll
        for (int c = 0; c < 16; c++) ph[c] = Pha[base + (size_t)c * PP + p];
#pragma unroll
        for (int o = 0; o < CMc; o++) {
            float mo = sMB[o];
#pragma unroll
            for (int m = 0; m < CMc; m++) mo += sMW[o * 16 + m] * acc[m];
            float po = sPB[o];
#pragma unroll
            for (int c = 0; c < 16; c++) po += sPW[o * 16 + c] * ph[c];
            float sn, cs;
            __sincosf(po, &sn, &cs);
            F[base + (size_t)o * PP + p] = make_float2(mo * cs, mo * sn);
        }
    }
}

// ---------------- merged: phaO (blk 0..511) + fmfp (blk 512..771) ---------
__global__ void __launch_bounds__(128)
k_phaOF(const float* __restrict__ Pha, const float* __restrict__ Mag,
        const float* __restrict__ PhaW, const float* __restrict__ PhaB,
        float2* __restrict__ F,
        const float* __restrict__ Fm, const float* __restrict__ Fp,
        const float* __restrict__ W1, const float* __restrict__ B1,
        float2* __restrict__ F65) {
    int bid = blockIdx.x;
    int t = threadIdx.x;
    if (bid < 512) {
        __shared__ float sPW[256];
        __shared__ float sW2[256];
        __shared__ float sPB[16];
        __shared__ float sB2[16];
        sPW[t] = PhaW[t]; sPW[t + 128] = PhaW[t + 128];
        sW2[t] = g_W2[t]; sW2[t + 128] = g_W2[t + 128];
        if (t < 16)  { sPB[t] = PhaB[t]; sB2[t] = g_b2[t]; }
        __syncthreads();
        int n = bid >> 7;
        int p = (bid & 127) * 128 + t;
        int h = p >> 7, w = p & 127;
        if (h >= 19 && h < 109 && w >= 19 && w < 109) return;
        size_t base = (size_t)n * 16 * PP;
        float ph[16], mg[16];
#pragma unroll
        for (int c = 0; c < 16; c++) {
            ph[c] = Pha[base + (size_t)c * PP + p];
            mg[c] = Mag[base + (size_t)c * PP + p];
        }
#pragma unroll
        for (int o = 0; o < 16; o++) {
            float po = sPB[o];
            float m = sB2[o];
#pragma unroll
            for (int c = 0; c < 16; c++) {
                po += sPW[o * 16 + c] * ph[c];
                m  += sW2[o * 16 + c] * mg[c];
            }
            float sn, cs;
            __sincosf(po, &sn, &cs);
            F[base + (size_t)o * PP + p] = make_float2(m * cs, m * sn);
        }
    } else {
        __shared__ float sW[256];
        __shared__ float sB[16];
        sW[t] = W1[t]; sW[t + 128] = W1[t + 128];
        if (t < 16)  sB[t] = B1[t];
        __syncthreads();
        int r = bid - 512;
        int n = r / 65;
        int p = (r % 65) * 128 + t;
        if (p >= P65) return;
        size_t base = (size_t)n * 16 * P65;
        float fm[16], fp[16];
#pragma unroll
        for (int c = 0; c < 16; c++) {
            fm[c] = Fm[base + (size_t)c * P65 + p];
            fp[c] = Fp[base + (size_t)c * P65 + p];
        }
#pragma unroll
        for (int o = 0; o < 16; o++) {
            float mo = sB[o], po = sB[o];
#pragma unroll
            for (int c = 0; c < 16; c++) {
                mo += sW[o * 16 + c] * fm[c];
                po += sW[o * 16 + c] * fp[c];
            }
            float sn, cs;
            __sincosf(po, &sn, &cs);
            F65[base + (size_t)o * P65 + p] = make_float2(mo * cs, mo * sn);
        }
    }
}

// ---------------- launch ----------------
extern "C" void kernel_launch(void* const* d_in, const int* in_sizes, int n_in,
                              void* d_out, int out_size) {
    const float* x        = (const float*)d_in[0];
    const float* conv1_w  = (const float*)d_in[1];
    const float* mag_s_w  = (const float*)d_in[2];
    const float* mag_s_b  = (const float*)d_in[3];
    const float* mag_f_w  = (const float*)d_in[4];
    const float* mag_f_b  = (const float*)d_in[5];
    const float* mag_w    = (const float*)d_in[6];
    const float* mag_b    = (const float*)d_in[7];
    const float* pha_w    = (const float*)d_in[8];
    const float* pha_b    = (const float*)d_in[9];
    const float* conv_0_w = (const float*)d_in[10];
    const float* conv_0_b = (const float*)d_in[11];
    const float* conv_1_w = (const float*)d_in[12];
    const float* conv_1_b = (const float*)d_in[13];
    const float* conv2_w  = (const float*)d_in[14];
    float* out = (float*)d_out;

    float  *px1, *pmag, *ppha, *pfm, *pfp, *pcat;
    float2 *pM, *pMinv, *pFh, *pFhi, *pFw, *pT, *pF, *pT65, *pF65;
    cudaGetSymbolAddress((void**)&px1,    g_x1);
    cudaGetSymbolAddress((void**)&pmag,   g_mag);
    cudaGetSymbolAddress((void**)&ppha,   g_pha);
    cudaGetSymbolAddress((void**)&pfm,    g_fm);
    cudaGetSymbolAddress((void**)&pfp,    g_fp);
    cudaGetSymbolAddress((void**)&pcat,   g_cat);
    cudaGetSymbolAddress((void**)&pM,     g_M);
    cudaGetSymbolAddress((void**)&pMinv,  g_Minv);
    cudaGetSymbolAddress((void**)&pFh,    g_Fh);
    cudaGetSymbolAddress((void**)&pFhi,   g_Fhi);
    cudaGetSymbolAddress((void**)&pFw,    g_Fw);
    cudaGetSymbolAddress((void**)&pT,     g_T);
    cudaGetSymbolAddress((void**)&pF,     g_F);
    cudaGetSymbolAddress((void**)&pT65,   g_T65);
    cudaGetSymbolAddress((void**)&pF65,   g_F65);

    k_init <<<128, 256>>>();
    k_init2<<<141, 512>>>(conv2_w, conv_0_w, conv_0_b, mag_w, mag_f_w, mag_f_b, mag_b);

    k_g1x1<<<dim3(32, 3, NB), 128>>>(x, conv1_w, px1, 192, 192 * PP, 48 * PP);

    k_rxMT64D<<<384, 128>>>(px1, pM, pT, pFw, pT65);
    k_MxXD<<<448, 128>>>(px1, pM, pT, pmag, ppha, pFh, pT65, pfm, pfp);

    k_conv3mF<<<dim3(4, 12, NB), dim3(32, 8)>>>(pmag, ppha, mag_s_w, mag_s_b,
                                                mag_w, mag_b, pha_w, pha_b, pF);
    k_phaOF<<<772, 128>>>(ppha, pmag, pha_w, pha_b, pF,
                          pfm, pfp, conv_1_w, conv_1_b, pF65);

    k_invA<<<448, 128>>>(pF, pMinv, pT, pFhi, pF65, pT65);
    k_invB<<<2304, 128>>>(pMinv, pT, pcat, pT65);

    k_conv2<<<dim3(32, 12, NB), 128>>>(px1, pcat, conv2_w, out);
}